// round 3
// baseline (speedup 1.0000x reference)
#include <cuda_runtime.h>
#include <math.h>

// ---------------------------------------------------------------------------
// Swin block: B=4, C=96, H=W=256, WS=8, NH=4, HD=24, SHIFT=4, N=64, MLP_H=384
// Kernel A: per-window fused LN1 + QKV + attn(bias+mask) + softmax + AV + proj
//           + residual -> g_h (NHWC scratch)
// Kernel B: per-64-pixel fused LN2 + MLP(GELU) + residual -> out (NCHW)
// ---------------------------------------------------------------------------

#define CC    96
#define NTOK  64
#define SHIFTV 4

// NHWC scratch for h = x + attn_out   (4*256*256*96 floats = 100.7 MB)
__device__ float g_h[4 * 256 * 256 * 96];

// ---------------- Kernel A smem layout (floats) ----------------
#define OFF_XLN  0        // 96*64 = 6144   (reused as attn-out "ao")
#define OFF_Q    6144     // 96*64
#define OFF_K    12288    // 96*64
#define OFF_V    18432    // 64*97 = 6208   (reused as hout)
#define OFF_S    24640    // 4*64*65 = 16640 (also weight staging buffer)
#define OFF_MU   41280    // 64
#define OFF_RS   41344    // 64
#define OFF_RED  41408    // 256
#define OFF_RED2 41664    // 256
#define OFF_POS  41920    // 64 (int)
#define OFF_CLS  41984    // 64 (int)
#define K2_SMEM_FLOATS 42048   // 168,192 bytes

__global__ void __launch_bounds__(256, 1) swin_attn_kernel(
    const float* __restrict__ x,
    const float* __restrict__ norm_w, const float* __restrict__ norm_b,
    const float* __restrict__ qkv_w,  const float* __restrict__ qkv_b,
    const float* __restrict__ proj_w, const float* __restrict__ proj_b,
    const float* __restrict__ rpb)
{
    extern __shared__ float sm[];
    float* xln  = sm + OFF_XLN;
    float* qs   = sm + OFF_Q;
    float* ks   = sm + OFF_K;
    float* vs   = sm + OFF_V;
    float* S    = sm + OFF_S;
    float* mu_s = sm + OFF_MU;
    float* rs_s = sm + OFF_RS;
    float* red  = sm + OFF_RED;
    float* red2 = sm + OFF_RED2;
    int*   pos  = (int*)(sm + OFF_POS);
    int*   cls  = (int*)(sm + OFF_CLS);

    const int tid  = threadIdx.x;
    const int lane = tid & 31;
    const int wrp  = tid >> 5;
    const int blk  = blockIdx.x;
    const int b    = blk >> 10;
    const int wh   = (blk >> 5) & 31;
    const int ww   = blk & 31;

    // token geometry: shifted coords (hs,ws) -> original pixel pos, region class
    if (tid < 64) {
        int i  = tid >> 3, j = tid & 7;
        int hs = wh * 8 + i;
        int wsp = ww * 8 + j;
        int r = (hs + SHIFTV) & 255;
        int c = (wsp + SHIFTV) & 255;
        pos[tid] = r * 256 + c;
        int rr = (hs  < 248) ? 0 : ((hs  < 252) ? 1 : 2);
        int cr = (wsp < 248) ? 0 : ((wsp < 252) ? 1 : 2);
        cls[tid] = rr * 3 + cr;
    }
    __syncthreads();

    const int xbase = b * CC * 65536;

    // Load window tokens into xln[c][n]   (raw values first)
    for (int it = 0; it < 24; it++) {
        int e = tid + it * 256;
        int c = e >> 6, n = e & 63;
        xln[e] = __ldg(&x[xbase + (c << 16) + pos[n]]);
    }
    __syncthreads();

    // LayerNorm over C: 4 partial groups of 24 channels per token
    {
        int n = tid & 63, part = tid >> 6;
        float s = 0.f, s2 = 0.f;
        #pragma unroll
        for (int cc = 0; cc < 24; cc++) {
            float v = xln[(part * 24 + cc) * 64 + n];
            s += v; s2 += v * v;
        }
        red[part * 64 + n] = s;
        red2[part * 64 + n] = s2;
    }
    __syncthreads();
    if (tid < 64) {
        float s  = red[tid] + red[64 + tid] + red[128 + tid] + red[192 + tid];
        float s2 = red2[tid] + red2[64 + tid] + red2[128 + tid] + red2[192 + tid];
        float mu = s * (1.f / 96.f);
        float var = s2 * (1.f / 96.f) - mu * mu;
        mu_s[tid] = mu;
        rs_s[tid] = rsqrtf(var + 1e-6f);
    }
    __syncthreads();
    for (int it = 0; it < 24; it++) {
        int e = tid + it * 256;
        int c = e >> 6, n = e & 63;
        xln[e] = (xln[e] - mu_s[n]) * rs_s[n] * __ldg(norm_w + c) + __ldg(norm_b + c);
    }
    __syncthreads();

    // ---------------- QKV GEMM: 288x96 weights staged in S (2 halves of 144 rows)
    const float scale = 0.2041241452319315f;   // 24^-0.5
    for (int half = 0; half < 2; half++) {
        for (int it = 0; it < 54; it++) {
            int e = tid + it * 256;
            S[e] = __ldg(&qkv_w[half * 13824 + e]);
        }
        __syncthreads();
        for (int t = 0; t < 18; t++) {
            int ol = wrp + 8 * t;
            int o  = half * 144 + ol;
            float a0 = __ldg(qkv_b + o), a1 = a0;
            const float* wrow = S + ol * 96;
            #pragma unroll
            for (int k = 0; k < 96; k++) {
                float w = wrow[k];
                a0 += w * xln[k * 64 + lane];
                a1 += w * xln[k * 64 + lane + 32];
            }
            if (o < 96) {
                qs[o * 64 + lane]      = a0 * scale;
                qs[o * 64 + lane + 32] = a1 * scale;
            } else if (o < 192) {
                ks[(o - 96) * 64 + lane]      = a0;
                ks[(o - 96) * 64 + lane + 32] = a1;
            } else {
                vs[lane * 97 + (o - 192)]        = a0;
                vs[(lane + 32) * 97 + (o - 192)] = a1;
            }
        }
        __syncthreads();
    }

    // ---------------- Scores: S[h*64+n][m] = q.k + bias + mask (rows padded to 65)
    for (int t = 0; t < 32; t++) {
        int task = wrp + 8 * t;           // task = h*64 + n
        int h = task >> 6, n = task & 63;
        int i1 = n >> 3, j1 = n & 7;
        const float* qcol = qs + (h * 24) * 64 + n;
        float a0 = 0.f, a1 = 0.f;
        #pragma unroll
        for (int d = 0; d < 24; d++) {
            float qv = qcol[d * 64];
            a0 += qv * ks[(h * 24 + d) * 64 + lane];
            a1 += qv * ks[(h * 24 + d) * 64 + lane + 32];
        }
        int cn = cls[n];
        {
            int m = lane;
            int ridx = (i1 - (m >> 3) + 7) * 15 + (j1 - (m & 7) + 7);
            a0 += __ldg(rpb + ridx * 4 + h);
            if (cls[m] != cn) a0 -= 100.f;
        }
        {
            int m = lane + 32;
            int ridx = (i1 - (m >> 3) + 7) * 15 + (j1 - (m & 7) + 7);
            a1 += __ldg(rpb + ridx * 4 + h);
            if (cls[m] != cn) a1 -= 100.f;
        }
        S[task * 65 + lane]      = a0;
        S[task * 65 + lane + 32] = a1;
    }
    __syncthreads();

    // ---------------- Softmax (warp per row)
    for (int t = 0; t < 32; t++) {
        int row = wrp + 8 * t;
        float x0 = S[row * 65 + lane], x1 = S[row * 65 + lane + 32];
        float mx = fmaxf(x0, x1);
        #pragma unroll
        for (int o = 16; o > 0; o >>= 1) mx = fmaxf(mx, __shfl_xor_sync(0xffffffffu, mx, o));
        float e0 = __expf(x0 - mx), e1 = __expf(x1 - mx);
        float sum = e0 + e1;
        #pragma unroll
        for (int o = 16; o > 0; o >>= 1) sum += __shfl_xor_sync(0xffffffffu, sum, o);
        float inv = __fdividef(1.f, sum);
        S[row * 65 + lane]      = e0 * inv;
        S[row * 65 + lane + 32] = e1 * inv;
    }
    __syncthreads();

    // ---------------- AV: ao[c][n] (reuse xln region),  c = h*24+d = task
    float* ao = xln;
    for (int t = 0; t < 12; t++) {
        int task = wrp + 8 * t;           // 0..95
        int h = task / 24, d = task - h * 24;
        float a0 = 0.f, a1 = 0.f;
        #pragma unroll
        for (int m = 0; m < 64; m++) {
            float vv = vs[m * 97 + h * 24 + d];
            a0 += S[(h * 64 + lane) * 65 + m] * vv;
            a1 += S[(h * 64 + lane + 32) * 65 + m] * vv;
        }
        ao[task * 64 + lane]      = a0;
        ao[task * 64 + lane + 32] = a1;
    }
    __syncthreads();

    // ---------------- Proj (weights staged in S) + residual; hout in vs region
    for (int it = 0; it < 36; it++) {
        int e = tid + it * 256;
        S[e] = __ldg(&proj_w[e]);
    }
    __syncthreads();
    float* hout = vs;
    for (int t = 0; t < 12; t++) {
        int co = wrp + 8 * t;
        float a0 = __ldg(proj_b + co), a1 = a0;
        const float* wrow = S + co * 96;
        #pragma unroll
        for (int c = 0; c < 96; c++) {
            float w = wrow[c];
            a0 += w * ao[c * 64 + lane];
            a1 += w * ao[c * 64 + lane + 32];
        }
        a0 += __ldg(&x[xbase + (co << 16) + pos[lane]]);
        a1 += __ldg(&x[xbase + (co << 16) + pos[lane + 32]]);
        hout[lane * 97 + co]        = a0;
        hout[(lane + 32) * 97 + co] = a1;
    }
    __syncthreads();

    // Write h (NHWC), coalesced 384B runs per token
    for (int it = 0; it < 24; it++) {
        int e = tid + it * 256;
        int n = e / 96, c = e - n * 96;
        g_h[(b * 65536 + pos[n]) * 96 + c] = hout[n * 97 + c];
    }
}

// ---------------- Kernel B smem layout (floats) ----------------
#define O3_X   0        // 96*65 = 6240  (raw h, padded rows)
#define O3_Y   6240     // 96*64 = 6144  (LN2 output)
#define O3_W1  12384    // 64*96 = 6144
#define O3_W2  18528    // 96*64 = 6144
#define O3_HC  24672    // 64*64 = 4096
#define O3_MU  28768
#define O3_RS  28832
#define O3_RED 28896    // 256
#define O3_RED2 29152   // 256
#define K3_SMEM_FLOATS 29408   // 117,632 bytes

__global__ void __launch_bounds__(256, 1) swin_mlp_kernel(
    const float* __restrict__ n2w, const float* __restrict__ n2b,
    const float* __restrict__ w1g, const float* __restrict__ b1g,
    const float* __restrict__ w2g, const float* __restrict__ b2g,
    float* __restrict__ out)
{
    extern __shared__ float sm[];
    float* xs   = sm + O3_X;
    float* ys   = sm + O3_Y;
    float* w1   = sm + O3_W1;
    float* w2   = sm + O3_W2;
    float* hc   = sm + O3_HC;
    float* mu_s = sm + O3_MU;
    float* rs_s = sm + O3_RS;
    float* red  = sm + O3_RED;
    float* red2 = sm + O3_RED2;

    const int tid  = threadIdx.x;
    const int lane = tid & 31;
    const int wrp  = tid >> 5;
    const int P0   = blockIdx.x * 64;   // 64 pixels per block
    const int b    = P0 >> 16;
    const int pix0 = P0 & 65535;

    // Load h tile (contiguous 24 KB) into xs[c][p] (row pad 65)
    for (int it = 0; it < 24; it++) {
        int e = tid + it * 256;
        int p = e / 96, c = e - p * 96;
        xs[c * 65 + p] = g_h[P0 * 96 + e];
    }
    __syncthreads();

    // LN2
    {
        int p = tid & 63, part = tid >> 6;
        float s = 0.f, s2 = 0.f;
        #pragma unroll
        for (int cc = 0; cc < 24; cc++) {
            float v = xs[(part * 24 + cc) * 65 + p];
            s += v; s2 += v * v;
        }
        red[part * 64 + p] = s;
        red2[part * 64 + p] = s2;
    }
    __syncthreads();
    if (tid < 64) {
        float s  = red[tid] + red[64 + tid] + red[128 + tid] + red[192 + tid];
        float s2 = red2[tid] + red2[64 + tid] + red2[128 + tid] + red2[192 + tid];
        float mu = s * (1.f / 96.f);
        float var = s2 * (1.f / 96.f) - mu * mu;
        mu_s[tid] = mu;
        rs_s[tid] = rsqrtf(var + 1e-6f);
    }
    __syncthreads();
    {
        int p = tid & 63, part = tid >> 6;
        float mu = mu_s[p], rs = rs_s[p];
        #pragma unroll
        for (int cc = 0; cc < 24; cc++) {
            int c = part * 24 + cc;
            ys[c * 64 + p] = (xs[c * 65 + p] - mu) * rs * __ldg(n2w + c) + __ldg(n2b + c);
        }
    }
    __syncthreads();

    // MLP: 6 chunks of 64 hidden units; fc2 accumulators live in registers
    float acc[12][2];
    #pragma unroll
    for (int u = 0; u < 12; u++) { acc[u][0] = 0.f; acc[u][1] = 0.f; }

    for (int ch = 0; ch < 6; ch++) {
        for (int it = 0; it < 24; it++) {
            int e = tid + it * 256;
            w1[e] = __ldg(&w1g[ch * 6144 + e]);
        }
        for (int it = 0; it < 24; it++) {
            int e = tid + it * 256;
            int c = e >> 6, jj = e & 63;
            w2[e] = __ldg(&w2g[c * 384 + ch * 64 + jj]);
        }
        __syncthreads();

        // fc1 + exact GELU
        #pragma unroll
        for (int t = 0; t < 8; t++) {
            int jj = wrp + 8 * t;
            float a0 = __ldg(b1g + ch * 64 + jj), a1 = a0;
            const float* wr = w1 + jj * 96;
            #pragma unroll
            for (int k = 0; k < 96; k++) {
                float w = wr[k];
                a0 += w * ys[k * 64 + lane];
                a1 += w * ys[k * 64 + lane + 32];
            }
            a0 = 0.5f * a0 * (1.f + erff(a0 * 0.7071067811865475f));
            a1 = 0.5f * a1 * (1.f + erff(a1 * 0.7071067811865475f));
            hc[jj * 64 + lane]      = a0;
            hc[jj * 64 + lane + 32] = a1;
        }
        __syncthreads();

        // fc2 partial accumulation
        for (int jj = 0; jj < 64; jj++) {
            float h0 = hc[jj * 64 + lane];
            float h1 = hc[jj * 64 + lane + 32];
            #pragma unroll
            for (int u = 0; u < 12; u++) {
                float w = w2[(wrp + 8 * u) * 64 + jj];
                acc[u][0] += w * h0;
                acc[u][1] += w * h1;
            }
        }
        __syncthreads();
    }

    // Epilogue: bias + residual, coalesced NCHW store
    #pragma unroll
    for (int u = 0; u < 12; u++) {
        int c = wrp + 8 * u;
        float bb = __ldg(b2g + c);
        float o0 = acc[u][0] + bb + xs[c * 65 + lane];
        float o1 = acc[u][1] + bb + xs[c * 65 + lane + 32];
        size_t base = ((size_t)(b * 96 + c) << 16) + (size_t)pix0;
        out[base + lane]      = o0;
        out[base + lane + 32] = o1;
    }
}

extern "C" void kernel_launch(void* const* d_in, const int* in_sizes, int n_in,
                              void* d_out, int out_size)
{
    const float* x      = (const float*)d_in[0];
    const float* norm_w = (const float*)d_in[1];
    const float* norm_b = (const float*)d_in[2];
    const float* qkv_w  = (const float*)d_in[3];
    const float* qkv_b  = (const float*)d_in[4];
    const float* proj_w = (const float*)d_in[5];
    const float* proj_b = (const float*)d_in[6];
    const float* rpb    = (const float*)d_in[7];
    const float* n2w    = (const float*)d_in[8];
    const float* n2b    = (const float*)d_in[9];
    const float* fc1_w  = (const float*)d_in[10];
    const float* fc1_b  = (const float*)d_in[11];
    const float* fc2_w  = (const float*)d_in[12];
    const float* fc2_b  = (const float*)d_in[13];
    float* out = (float*)d_out;

    cudaFuncSetAttribute(swin_attn_kernel, cudaFuncAttributeMaxDynamicSharedMemorySize,
                         K2_SMEM_FLOATS * 4);
    cudaFuncSetAttribute(swin_mlp_kernel, cudaFuncAttributeMaxDynamicSharedMemorySize,
                         K3_SMEM_FLOATS * 4);

    swin_attn_kernel<<<4096, 256, K2_SMEM_FLOATS * 4>>>(
        x, norm_w, norm_b, qkv_w, qkv_b, proj_w, proj_b, rpb);
    swin_mlp_kernel<<<4096, 256, K3_SMEM_FLOATS * 4>>>(
        n2w, n2b, fc1_w, fc1_b, fc2_w, fc2_b, out);
}

// round 4
// speedup vs baseline: 1.3421x; 1.3421x over previous
#include <cuda_runtime.h>
#include <math.h>

// ---------------------------------------------------------------------------
// Swin block, B=4 C=96 H=W=256 WS=8 NH=4 HD=24 SHIFT=4 N=64 MLP_H=384
// Register-tiled fp32 with packed fma.rn.f32x2 (FFMA2, sm_103a).
// Kernel A: per-window  LN1 + QKV + scores(bias+mask) + softmax + AV + proj
//           + residual -> g_h (NHWC scratch)
// Kernel B: per-64-pixel LN2 + fc1 + GELU + fc2 + residual -> out (NCHW)
// ---------------------------------------------------------------------------

typedef unsigned long long ull;

__device__ __forceinline__ void fma2(ull &acc, ull a, ull b) {
    asm("fma.rn.f32x2 %0, %1, %2, %0;" : "+l"(acc) : "l"(a), "l"(b));
}
__device__ __forceinline__ ull bcast2(float v) {
    ull r; asm("mov.b64 %0, {%1, %1};" : "=l"(r) : "f"(v)); return r;
}
__device__ __forceinline__ float f2lo(ull v) { return __uint_as_float((unsigned)v); }
__device__ __forceinline__ float f2hi(ull v) { return __uint_as_float((unsigned)(v >> 32)); }
__device__ __forceinline__ float hadd2(ull v) { return f2lo(v) + f2hi(v); }
__device__ __forceinline__ ull lds64(const float* p) { return *(const ull*)p; }

// NHWC scratch for h = x + attn_out (100.7 MB)
__device__ float g_h[4 * 256 * 256 * 96];

// ---------------- Kernel A smem layout (floats) ----------------
#define A_XT   0        // x_t[n*98+c]   64*98 = 6272  (token-major, LN'd in place)
#define A_QS   6272     // qs[o*64+n]    96*64 (later: proj weights 96*96 spanning QS+KS)
#define A_KS   12416    // ks[o*64+m]    96*64
#define A_VT   18560    // v_t[c*64+m]   96*64
#define A_S    24704    // S[r*66+m]     256*66 = 16896 (first: QKV weight stage 13824)
#define A_AOT  41600    // ao_t[n*98+c]  64*98
#define A_HOUT 47872    // hout[n*98+c]  64*98
#define A_RPB  54144    // 912 (225*4 used)
#define A_MU   55056    // 64
#define A_RS   55120    // 64
#define A_RED  55184    // 256
#define A_RED2 55440    // 256
#define A_POS  55696    // 64 (int)
#define A_CLS  55760    // 64 (int)
#define A_TOT  55824    // 223,296 bytes

__global__ void __launch_bounds__(256, 1) swin_attn_kernel(
    const float* __restrict__ x,
    const float* __restrict__ norm_w, const float* __restrict__ norm_b,
    const float* __restrict__ qkv_w,  const float* __restrict__ qkv_b,
    const float* __restrict__ proj_w, const float* __restrict__ proj_b,
    const float* __restrict__ rpb)
{
    extern __shared__ float sm[];
    float* xt    = sm + A_XT;
    float* qs    = sm + A_QS;
    float* ks    = sm + A_KS;
    float* vt    = sm + A_VT;
    float* S     = sm + A_S;
    float* aot   = sm + A_AOT;
    float* hout  = sm + A_HOUT;
    float* rpb_s = sm + A_RPB;
    float* mu_s  = sm + A_MU;
    float* rs_s  = sm + A_RS;
    float* red   = sm + A_RED;
    float* red2  = sm + A_RED2;
    int*   pos   = (int*)(sm + A_POS);
    int*   cls   = (int*)(sm + A_CLS);

    const int tid  = threadIdx.x;
    const int lane = tid & 31;
    const int wrp  = tid >> 5;
    const int rg   = tid >> 4;        // 0..15
    const int cg   = tid & 15;        // 0..15
    const int n0   = cg * 4;
    const int blk  = blockIdx.x;
    const int b    = blk >> 10;
    const int wh   = (blk >> 5) & 31;
    const int ww   = blk & 31;

    // geometry + rpb staging
    if (tid < 64) {
        int i = tid >> 3, j = tid & 7;
        int hs = wh * 8 + i;
        int wsp = ww * 8 + j;
        int r = (hs + 4) & 255;
        int c = (wsp + 4) & 255;
        pos[tid] = r * 256 + c;
        int rr = (hs  < 248) ? 0 : ((hs  < 252) ? 1 : 2);
        int cr = (wsp < 248) ? 0 : ((wsp < 252) ? 1 : 2);
        cls[tid] = rr * 3 + cr;
    }
    for (int idx = tid; idx < 900; idx += 256) rpb_s[idx] = __ldg(rpb + idx);
    __syncthreads();

    const int xbase = b * 96 * 65536;

    // load window tokens, token-major x_t[n*98+c]
    for (int it = 0; it < 24; it++) {
        int e = tid + it * 256;
        int c = e >> 6, n = e & 63;
        xt[n * 98 + c] = __ldg(&x[xbase + (c << 16) + pos[n]]);
    }
    __syncthreads();

    // LayerNorm over C (4 partial groups of 24 per token)
    {
        int n = tid & 63, part = tid >> 6;
        float s = 0.f, s2 = 0.f;
        #pragma unroll
        for (int cc = 0; cc < 24; cc++) {
            float v = xt[n * 98 + part * 24 + cc];
            s += v; s2 += v * v;
        }
        red[part * 64 + n] = s;
        red2[part * 64 + n] = s2;
    }
    __syncthreads();
    if (tid < 64) {
        float s  = red[tid] + red[64 + tid] + red[128 + tid] + red[192 + tid];
        float s2 = red2[tid] + red2[64 + tid] + red2[128 + tid] + red2[192 + tid];
        float mu = s * (1.f / 96.f);
        float var = s2 * (1.f / 96.f) - mu * mu;
        mu_s[tid] = mu;
        rs_s[tid] = rsqrtf(var + 1e-6f);
    }
    __syncthreads();
    for (int it = 0; it < 24; it++) {
        int e = tid + it * 256;
        int c = e >> 6, n = e & 63;
        xt[n * 98 + c] = (xt[n * 98 + c] - mu_s[n]) * rs_s[n] * __ldg(norm_w + c)
                         + __ldg(norm_b + c);
    }
    __syncthreads();

    // ---------------- QKV: k-pair FFMA2, weights staged j-major (direct copy)
    const float scale = 0.2041241452319315f;  // 24^-0.5
    for (int half = 0; half < 2; half++) {
        for (int idx = tid; idx < 13824; idx += 256)
            S[idx] = __ldg(&qkv_w[half * 13824 + idx]);
        __syncthreads();

        ull acc[9][4];
        #pragma unroll
        for (int jj = 0; jj < 9; jj++)
            #pragma unroll
            for (int i = 0; i < 4; i++) acc[jj][i] = 0ULL;

        #pragma unroll 2
        for (int kp = 0; kp < 48; kp++) {
            ull xp[4];
            #pragma unroll
            for (int i = 0; i < 4; i++) xp[i] = lds64(xt + (n0 + i) * 98 + 2 * kp);
            #pragma unroll
            for (int jj = 0; jj < 9; jj++) {
                ull wp = lds64(S + (rg * 9 + jj) * 96 + 2 * kp);
                #pragma unroll
                for (int i = 0; i < 4; i++) fma2(acc[jj][i], wp, xp[i]);
            }
        }
        __syncthreads();   // done reading staged weights

        #pragma unroll
        for (int jj = 0; jj < 9; jj++) {
            int o = half * 144 + rg * 9 + jj;
            float bb = __ldg(qkv_b + o);
            #pragma unroll
            for (int i = 0; i < 4; i++) {
                float v = hadd2(acc[jj][i]) + bb;
                int n = n0 + i;
                if (o < 96)       qs[o * 64 + n] = v * scale;
                else if (o < 192) ks[(o - 96) * 64 + n] = v;
                else              vt[(o - 192) * 64 + n] = v;
            }
        }
        __syncthreads();
    }

    // ---------------- Scores: m-pair FFMA2 (broadcast q), + bias + mask -> S
    {
        const int sg = tid >> 3;          // 0..31
        const int sc = tid & 7;           // 0..7
        const int h  = sg >> 3;
        const int nb = (sg & 7) * 8;
        const int m0 = sc * 8;

        ull acc[8][4];
        #pragma unroll
        for (int i = 0; i < 8; i++)
            #pragma unroll
            for (int mp = 0; mp < 4; mp++) acc[i][mp] = 0ULL;

        #pragma unroll 2
        for (int d = 0; d < 24; d++) {
            const float* base = qs + (h * 24 + d) * 64;
            const float* kb   = ks + (h * 24 + d) * 64 + m0;
            ull kpv[4];
            #pragma unroll
            for (int mp = 0; mp < 4; mp++) kpv[mp] = lds64(kb + 2 * mp);
            #pragma unroll
            for (int i = 0; i < 8; i++) {
                ull qq = bcast2(base[nb + i]);
                #pragma unroll
                for (int mp = 0; mp < 4; mp++) fma2(acc[i][mp], qq, kpv[mp]);
            }
        }

        #pragma unroll
        for (int i = 0; i < 8; i++) {
            int n = nb + i;
            int r = sg * 8 + i;
            int i1 = n >> 3, jA = n & 7;
            int cn = cls[n];
            #pragma unroll
            for (int mp = 0; mp < 4; mp++) {
                #pragma unroll
                for (int half = 0; half < 2; half++) {
                    int m = m0 + 2 * mp + half;
                    float v = half ? f2hi(acc[i][mp]) : f2lo(acc[i][mp]);
                    int ridx = (i1 - (m >> 3) + 7) * 15 + (jA - (m & 7) + 7);
                    v += rpb_s[ridx * 4 + h];
                    if (cls[m] != cn) v -= 100.f;
                    S[r * 66 + m] = v;
                }
            }
        }
    }
    __syncthreads();

    // ---------------- Softmax (warp per row)
    for (int t = 0; t < 32; t++) {
        int row = wrp + 8 * t;
        float x0 = S[row * 66 + lane], x1 = S[row * 66 + lane + 32];
        float mx = fmaxf(x0, x1);
        #pragma unroll
        for (int o = 16; o > 0; o >>= 1) mx = fmaxf(mx, __shfl_xor_sync(0xffffffffu, mx, o));
        float e0 = __expf(x0 - mx), e1 = __expf(x1 - mx);
        float sum = e0 + e1;
        #pragma unroll
        for (int o = 16; o > 0; o >>= 1) sum += __shfl_xor_sync(0xffffffffu, sum, o);
        float inv = __fdividef(1.f, sum);
        S[row * 66 + lane]      = e0 * inv;
        S[row * 66 + lane + 32] = e1 * inv;
    }
    __syncthreads();

    // ---------------- AV (m-pair reduction) + stage proj weights into qs/ks
    float* wpj = qs;   // 96*96 = 9216 floats, spans qs..ks (both dead now)
    for (int idx = tid; idx < 9216; idx += 256) wpj[idx] = __ldg(&proj_w[idx]);
    {
        const int c0 = rg * 6;
        const int h  = rg >> 2;
        ull acc[6][4];
        #pragma unroll
        for (int jj = 0; jj < 6; jj++)
            #pragma unroll
            for (int i = 0; i < 4; i++) acc[jj][i] = 0ULL;

        #pragma unroll 2
        for (int mp = 0; mp < 32; mp++) {
            ull pp[4];
            #pragma unroll
            for (int i = 0; i < 4; i++)
                pp[i] = lds64(S + (h * 64 + n0 + i) * 66 + 2 * mp);
            #pragma unroll
            for (int jj = 0; jj < 6; jj++) {
                ull vp = lds64(vt + (c0 + jj) * 64 + 2 * mp);
                #pragma unroll
                for (int i = 0; i < 4; i++) fma2(acc[jj][i], vp, pp[i]);
            }
        }
        #pragma unroll
        for (int jj = 0; jj < 6; jj++)
            #pragma unroll
            for (int i = 0; i < 4; i++)
                aot[(n0 + i) * 98 + c0 + jj] = hadd2(acc[jj][i]);
    }
    __syncthreads();

    // ---------------- Proj (c-pair reduction) + residual -> hout
    {
        const int j0 = rg * 6;
        ull acc[6][4];
        #pragma unroll
        for (int jj = 0; jj < 6; jj++)
            #pragma unroll
            for (int i = 0; i < 4; i++) acc[jj][i] = 0ULL;

        #pragma unroll 2
        for (int cp = 0; cp < 48; cp++) {
            ull ap[4];
            #pragma unroll
            for (int i = 0; i < 4; i++) ap[i] = lds64(aot + (n0 + i) * 98 + 2 * cp);
            #pragma unroll
            for (int jj = 0; jj < 6; jj++) {
                ull wp = lds64(wpj + (j0 + jj) * 96 + 2 * cp);
                #pragma unroll
                for (int i = 0; i < 4; i++) fma2(acc[jj][i], wp, ap[i]);
            }
        }
        #pragma unroll
        for (int jj = 0; jj < 6; jj++) {
            int j = j0 + jj;
            float bb = __ldg(proj_b + j);
            #pragma unroll
            for (int i = 0; i < 4; i++) {
                int n = n0 + i;
                float v = hadd2(acc[jj][i]) + bb
                        + __ldg(&x[xbase + (j << 16) + pos[n]]);
                hout[n * 98 + j] = v;
            }
        }
    }
    __syncthreads();

    // write h (NHWC)
    for (int it = 0; it < 24; it++) {
        int e = tid + it * 256;
        int n = e / 96, c = e - n * 96;
        g_h[(b * 65536 + pos[n]) * 96 + c] = hout[n * 98 + c];
    }
}

// ---------------- Kernel B smem layout (floats) ----------------
#define B_XS   0        // xs[p*98+c]    64*98 = 6272 (raw h, residual)
#define B_YS   6272     // ys[p*98+c]    6272 (LN2)
#define B_WST  12544    // weight stage  18432 (w1 half [192][96] / w2 half [96][192])
#define B_HCT  30976    // hc_t[p*194+k] 64*194 = 12416 (gelu'd fc1 half)
#define B_MU   43392    // 64
#define B_RS   43456    // 64
#define B_RED  43520    // 256
#define B_RED2 43776    // 256
#define B_TOT  44032    // 176,128 bytes

__global__ void __launch_bounds__(256, 1) swin_mlp_kernel(
    const float* __restrict__ n2w, const float* __restrict__ n2b,
    const float* __restrict__ w1g, const float* __restrict__ b1g,
    const float* __restrict__ w2g, const float* __restrict__ b2g,
    float* __restrict__ out)
{
    extern __shared__ float sm[];
    float* xs   = sm + B_XS;
    float* ys   = sm + B_YS;
    float* wst  = sm + B_WST;
    float* hct  = sm + B_HCT;
    float* mu_s = sm + B_MU;
    float* rs_s = sm + B_RS;
    float* red  = sm + B_RED;
    float* red2 = sm + B_RED2;

    const int tid = threadIdx.x;
    const int rg  = tid >> 4;       // 0..15
    const int cg  = tid & 15;       // 0..15
    const int p0  = cg * 4;
    const int P0  = blockIdx.x * 64;
    const int b   = P0 >> 16;
    const int pix0 = P0 & 65535;

    // load h tile (contiguous), token-major xs[p*98+c]
    for (int it = 0; it < 24; it++) {
        int e = tid + it * 256;
        int p = e / 96, c = e - p * 96;
        xs[p * 98 + c] = g_h[P0 * 96 + e];
    }
    __syncthreads();

    // LN2
    {
        int p = tid & 63, part = tid >> 6;
        float s = 0.f, s2 = 0.f;
        #pragma unroll
        for (int cc = 0; cc < 24; cc++) {
            float v = xs[p * 98 + part * 24 + cc];
            s += v; s2 += v * v;
        }
        red[part * 64 + p] = s;
        red2[part * 64 + p] = s2;
    }
    __syncthreads();
    if (tid < 64) {
        float s  = red[tid] + red[64 + tid] + red[128 + tid] + red[192 + tid];
        float s2 = red2[tid] + red2[64 + tid] + red2[128 + tid] + red2[192 + tid];
        float mu = s * (1.f / 96.f);
        float var = s2 * (1.f / 96.f) - mu * mu;
        mu_s[tid] = mu;
        rs_s[tid] = rsqrtf(var + 1e-6f);
    }
    __syncthreads();
    {
        int p = tid & 63, part = tid >> 6;
        float mu = mu_s[p], rs = rs_s[p];
        #pragma unroll
        for (int cc = 0; cc < 24; cc++) {
            int c = part * 24 + cc;
            ys[p * 98 + c] = (xs[p * 98 + c] - mu) * rs * __ldg(n2w + c) + __ldg(n2b + c);
        }
    }
    __syncthreads();

    // fc2 accumulators persist across both k-halves
    ull acc2[6][4];
    #pragma unroll
    for (int jj = 0; jj < 6; jj++)
        #pragma unroll
        for (int i = 0; i < 4; i++) acc2[jj][i] = 0ULL;

    for (int half = 0; half < 2; half++) {
        // stage fc1 weights half [192][96] (direct copy)
        for (int idx = tid; idx < 18432; idx += 256)
            wst[idx] = __ldg(&w1g[half * 18432 + idx]);
        __syncthreads();

        // fc1 in two quarter-passes of 96 rows (keeps regs bounded)
        for (int q4 = 0; q4 < 2; q4++) {
            ull acc1[6][4];
            #pragma unroll
            for (int jj = 0; jj < 6; jj++)
                #pragma unroll
                for (int i = 0; i < 4; i++) acc1[jj][i] = 0ULL;

            #pragma unroll 2
            for (int kp = 0; kp < 48; kp++) {
                ull xp[4];
                #pragma unroll
                for (int i = 0; i < 4; i++) xp[i] = lds64(ys + (p0 + i) * 98 + 2 * kp);
                #pragma unroll
                for (int jj = 0; jj < 6; jj++) {
                    ull wp = lds64(wst + (q4 * 96 + rg * 6 + jj) * 96 + 2 * kp);
                    #pragma unroll
                    for (int i = 0; i < 4; i++) fma2(acc1[jj][i], wp, xp[i]);
                }
            }
            #pragma unroll
            for (int jj = 0; jj < 6; jj++) {
                int jloc = q4 * 96 + rg * 6 + jj;
                float bb = __ldg(b1g + half * 192 + jloc);
                #pragma unroll
                for (int i = 0; i < 4; i++) {
                    float v = hadd2(acc1[jj][i]) + bb;
                    v = 0.5f * v * (1.f + erff(v * 0.7071067811865475f));
                    hct[(p0 + i) * 194 + jloc] = v;
                }
            }
        }
        __syncthreads();

        // stage fc2 weights half: wst[c*192+kk] = w2g[c*384 + half*192 + kk]
        for (int idx = tid; idx < 18432; idx += 256) {
            int c = idx / 192, kk = idx - c * 192;
            wst[idx] = __ldg(&w2g[c * 384 + half * 192 + kk]);
        }
        __syncthreads();

        // fc2 partial over this k-half
        #pragma unroll 2
        for (int kp = 0; kp < 96; kp++) {
            ull hp[4];
            #pragma unroll
            for (int i = 0; i < 4; i++) hp[i] = lds64(hct + (p0 + i) * 194 + 2 * kp);
            #pragma unroll
            for (int jj = 0; jj < 6; jj++) {
                ull wp = lds64(wst + (rg * 6 + jj) * 192 + 2 * kp);
                #pragma unroll
                for (int i = 0; i < 4; i++) fma2(acc2[jj][i], wp, hp[i]);
            }
        }
        __syncthreads();
    }

    // epilogue: bias + residual -> NCHW
    #pragma unroll
    for (int jj = 0; jj < 6; jj++) {
        int c = rg * 6 + jj;
        float bb = __ldg(b2g + c);
        #pragma unroll
        for (int i = 0; i < 4; i++) {
            int p = p0 + i;
            float v = hadd2(acc2[jj][i]) + bb + xs[p * 98 + c];
            out[((size_t)(b * 96 + c) << 16) + (size_t)pix0 + p] = v;
        }
    }
}

extern "C" void kernel_launch(void* const* d_in, const int* in_sizes, int n_in,
                              void* d_out, int out_size)
{
    const float* x      = (const float*)d_in[0];
    const float* norm_w = (const float*)d_in[1];
    const float* norm_b = (const float*)d_in[2];
    const float* qkv_w  = (const float*)d_in[3];
    const float* qkv_b  = (const float*)d_in[4];
    const float* proj_w = (const float*)d_in[5];
    const float* proj_b = (const float*)d_in[6];
    const float* rpb    = (const float*)d_in[7];
    const float* n2w    = (const float*)d_in[8];
    const float* n2b    = (const float*)d_in[9];
    const float* fc1_w  = (const float*)d_in[10];
    const float* fc1_b  = (const float*)d_in[11];
    const float* fc2_w  = (const float*)d_in[12];
    const float* fc2_b  = (const float*)d_in[13];
    float* out = (float*)d_out;

    cudaFuncSetAttribute(swin_attn_kernel, cudaFuncAttributeMaxDynamicSharedMemorySize,
                         A_TOT * 4);
    cudaFuncSetAttribute(swin_mlp_kernel, cudaFuncAttributeMaxDynamicSharedMemorySize,
                         B_TOT * 4);

    swin_attn_kernel<<<4096, 256, A_TOT * 4>>>(
        x, norm_w, norm_b, qkv_w, qkv_b, proj_w, proj_b, rpb);
    swin_mlp_kernel<<<4096, 256, B_TOT * 4>>>(
        n2w, n2b, fc1_w, fc1_b, fc2_w, fc2_b, out);
}

// round 5
// speedup vs baseline: 2.0441x; 1.5230x over previous
#include <cuda_runtime.h>
#include <math.h>

// ---------------------------------------------------------------------------
// Swin block, B=4 C=96 H=W=256 WS=8 NH=4 HD=24 SHIFT=4 N=64 MLP_H=384
// All GEMMs on tensor cores: mma.sync m16n8k8 tf32 (fp32 accum).
// fp32 everywhere else (LN, softmax, residuals). Operand smem strides are
// chosen ≡ 4 (mod 32) so fragment loads (l/4)*stride + l%4 are conflict-free.
// Kernel A: per-window  LN1 + QKV + scores(bias+mask) + softmax + AV + proj
//           + residual -> g_h (NHWC scratch)
// Kernel B: per-64-pixel LN2 + fc1 + GELU + fc2 + residual -> out (NCHW)
// ---------------------------------------------------------------------------

typedef unsigned uu;

__device__ __forceinline__ uu tf32c(float f) {
    uu u; asm("cvt.rna.tf32.f32 %0, %1;" : "=r"(u) : "f"(f)); return u;
}
__device__ __forceinline__ void mma8(float* d, const uu* a, uu b0, uu b1) {
    asm("mma.sync.aligned.m16n8k8.row.col.f32.tf32.tf32.f32 "
        "{%0,%1,%2,%3},{%4,%5,%6,%7},{%8,%9},{%0,%1,%2,%3};"
        : "+f"(d[0]), "+f"(d[1]), "+f"(d[2]), "+f"(d[3])
        : "r"(a[0]), "r"(a[1]), "r"(a[2]), "r"(a[3]), "r"(b0), "r"(b1));
}
// A fragment, row-major m16k8: a0=(q,r) a1=(q+8,r) a2=(q,r+4) a3=(q+8,r+4)
__device__ __forceinline__ void lda(uu* a, const uu* base, int stride, int lq, int lr) {
    a[0] = base[lq * stride + lr];
    a[1] = base[(lq + 8) * stride + lr];
    a[2] = base[lq * stride + lr + 4];
    a[3] = base[(lq + 8) * stride + lr + 4];
}

// Abramowitz-Stegun 7.1.26 erf (|abs err| < 1.5e-7)
__device__ __forceinline__ float erf_as(float x) {
    float ax = fabsf(x);
    float t  = __frcp_rn(1.f + 0.3275911f * ax);
    float y  = t * (0.254829592f + t * (-0.284496736f + t * (1.421413741f
             + t * (-1.453152027f + t * 1.061405429f))));
    float r  = 1.f - y * __expf(-ax * ax);
    return copysignf(r, x);
}

// NHWC scratch for h = x + attn_out (100.7 MB)
__device__ float g_h[4 * 256 * 256 * 96];

// ---------------- Kernel A smem layout (float indices) ----------------
#define A_XT   0        // X_ln  [64][100] tf32
#define A_Q    6400     // Q     [64][100] tf32  (later AO)
#define A_K    12800    // K     [64][100] tf32  (later hout, fp32)
#define A_VT   19200    // V^T   [96][68]  tf32
#define A_WB   25728    // Wqkv stage [288][100] tf32 (28800)
#define A_S    A_WB     // S     [256][68] fp32->tf32 (17408), overlays Wqkv
#define A_WP   (A_WB + 17408)  // Wproj [96][100] tf32 (9600)
#define A_RPB  54528    // 900
#define A_POS  55428    // 64 int
#define A_CLS  55492    // 64 int
#define A_MU   55556
#define A_RS   55620
#define A_RED  55684    // 256
#define A_RED2 55940    // 256
#define A_TOT  56196    // 224,784 bytes

__global__ void __launch_bounds__(256, 1) swin_attn_kernel(
    const float* __restrict__ x,
    const float* __restrict__ norm_w, const float* __restrict__ norm_b,
    const float* __restrict__ qkv_w,  const float* __restrict__ qkv_b,
    const float* __restrict__ proj_w, const float* __restrict__ proj_b,
    const float* __restrict__ rpb)
{
    extern __shared__ float sm[];
    float* xt    = sm + A_XT;
    float* rpb_s = sm + A_RPB;
    float* mu_s  = sm + A_MU;
    float* rs_s  = sm + A_RS;
    float* red   = sm + A_RED;
    float* red2  = sm + A_RED2;
    int*   pos   = (int*)(sm + A_POS);
    int*   cls_s = (int*)(sm + A_CLS);

    uu* Xu  = (uu*)(sm + A_XT);
    uu* Qu  = (uu*)(sm + A_Q);
    uu* Ku  = (uu*)(sm + A_K);
    uu* Vtu = (uu*)(sm + A_VT);
    uu* Wu  = (uu*)(sm + A_WB);
    uu* Wpu = (uu*)(sm + A_WP);
    float* S   = sm + A_S;
    float* AOf = sm + A_Q;     // AO overlays Q
    uu*    AOu = (uu*)AOf;
    float* hout = sm + A_K;    // hout overlays K

    const int tid  = threadIdx.x;
    const int lane = tid & 31;
    const int wid  = tid >> 5;
    const int lq   = lane >> 2;   // 0..7
    const int lr   = lane & 3;    // 0..3
    const int mh   = wid >> 2;    // 0..1
    const int nq   = wid & 3;     // 0..3
    const int blk  = blockIdx.x;
    const int b    = blk >> 10;
    const int wh   = (blk >> 5) & 31;
    const int ww   = blk & 31;

    // geometry + rpb staging
    if (tid < 64) {
        int i = tid >> 3, j = tid & 7;
        int hs = wh * 8 + i;
        int wsp = ww * 8 + j;
        int r = (hs + 4) & 255;
        int c = (wsp + 4) & 255;
        pos[tid] = r * 256 + c;
        int rr = (hs  < 248) ? 0 : ((hs  < 252) ? 1 : 2);
        int cr = (wsp < 248) ? 0 : ((wsp < 252) ? 1 : 2);
        cls_s[tid] = rr * 3 + cr;
    }
    for (int idx = tid; idx < 900; idx += 256) rpb_s[idx] = __ldg(rpb + idx);
    __syncthreads();

    const int xbase = b * 96 * 65536;

    // load window tokens -> xt[n][100] (raw fp32)
    for (int it = 0; it < 24; it++) {
        int e = tid + it * 256;
        int c = e >> 6, n = e & 63;
        xt[n * 100 + c] = __ldg(&x[xbase + (c << 16) + pos[n]]);
    }
    __syncthreads();

    // LN1 (stats in fp32, final write converted to tf32)
    {
        int n = tid & 63, part = tid >> 6;
        float s = 0.f, s2 = 0.f;
        #pragma unroll
        for (int cc = 0; cc < 24; cc++) {
            float v = xt[n * 100 + part * 24 + cc];
            s += v; s2 += v * v;
        }
        red[part * 64 + n] = s;
        red2[part * 64 + n] = s2;
    }
    __syncthreads();
    if (tid < 64) {
        float s  = red[tid] + red[64 + tid] + red[128 + tid] + red[192 + tid];
        float s2 = red2[tid] + red2[64 + tid] + red2[128 + tid] + red2[192 + tid];
        float mu = s * (1.f / 96.f);
        float var = s2 * (1.f / 96.f) - mu * mu;
        mu_s[tid] = mu;
        rs_s[tid] = rsqrtf(var + 1e-6f);
    }
    // stage Wqkv [288][100] (tf32) while LN stats settle
    __syncthreads();
    for (int it = 0; it < 24; it++) {
        int e = tid + it * 256;
        int c = e >> 6, n = e & 63;
        float v = (xt[n * 100 + c] - mu_s[n]) * rs_s[n] * __ldg(norm_w + c)
                  + __ldg(norm_b + c);
        Xu[n * 100 + c] = tf32c(v);
    }
    for (int idx = tid; idx < 27648; idx += 256) {
        int rrow = idx / 96, cc = idx - rrow * 96;
        Wu[rrow * 100 + cc] = tf32c(__ldg(qkv_w + idx));
    }
    __syncthreads();

    // ---------------- QKV: D[64][288] = X[64][96] * Wqkv^T ----------------
    // warp tile: m32 x n72 (2 A-frags x 9 B-frags), 12 k-steps
    {
        float acc[9][2][4];
        #pragma unroll
        for (int nt = 0; nt < 9; nt++)
            #pragma unroll
            for (int mt = 0; mt < 2; mt++)
                #pragma unroll
                for (int e = 0; e < 4; e++) acc[nt][mt][e] = 0.f;

        #pragma unroll 2
        for (int ks = 0; ks < 12; ks++) {
            int k0 = ks * 8;
            uu af[2][4];
            #pragma unroll
            for (int mt = 0; mt < 2; mt++)
                lda(af[mt], Xu + (mh * 32 + mt * 16) * 100 + k0, 100, lq, lr);
            #pragma unroll
            for (int nt = 0; nt < 9; nt++) {
                const uu* bb = Wu + (nq * 72 + nt * 8) * 100 + k0;
                uu b0 = bb[lq * 100 + lr], b1 = bb[lq * 100 + lr + 4];
                mma8(acc[nt][0], af[0], b0, b1);
                mma8(acc[nt][1], af[1], b0, b1);
            }
        }
        const float scale = 0.2041241452319315f;  // 24^-0.5
        #pragma unroll
        for (int nt = 0; nt < 9; nt++) {
            int j0 = nq * 72 + nt * 8;
            float bl = __ldg(qkv_b + j0 + 2 * lr);
            float bh = __ldg(qkv_b + j0 + 2 * lr + 1);
            #pragma unroll
            for (int mt = 0; mt < 2; mt++) {
                #pragma unroll
                for (int e = 0; e < 4; e++) {
                    int row = mh * 32 + mt * 16 + lq + ((e >> 1) << 3);
                    int col = j0 + 2 * lr + (e & 1);
                    float v = acc[nt][mt][e] + ((e & 1) ? bh : bl);
                    if (col < 96)       Qu[row * 100 + col] = tf32c(v * scale);
                    else if (col < 192) Ku[row * 100 + col - 96] = tf32c(v);
                    else                Vtu[(col - 192) * 68 + row] = tf32c(v);
                }
            }
        }
    }
    __syncthreads();

    // stage Wproj [96][100] into region past S (former Wqkv tail)
    for (int idx = tid; idx < 9216; idx += 256) {
        int rrow = idx / 96, cc = idx - rrow * 96;
        Wpu[rrow * 100 + cc] = tf32c(__ldg(proj_w + idx));
    }

    // ---------------- Scores: per-head S = Q Kt + bias + mask ----------------
    // warp: head hh = wid&3, m-half smh = wid>>2; tile m32 x n64, 3 k-steps
    {
        const int hh  = wid & 3;
        const int smh = wid >> 2;
        float acc[8][2][4];
        #pragma unroll
        for (int nt = 0; nt < 8; nt++)
            #pragma unroll
            for (int mt = 0; mt < 2; mt++)
                #pragma unroll
                for (int e = 0; e < 4; e++) acc[nt][mt][e] = 0.f;

        #pragma unroll
        for (int ks = 0; ks < 3; ks++) {
            int k0 = hh * 24 + ks * 8;
            uu af[2][4];
            #pragma unroll
            for (int mt = 0; mt < 2; mt++)
                lda(af[mt], Qu + (smh * 32 + mt * 16) * 100 + k0, 100, lq, lr);
            #pragma unroll
            for (int nt = 0; nt < 8; nt++) {
                const uu* bb = Ku + (nt * 8) * 100 + k0;
                uu b0 = bb[lq * 100 + lr], b1 = bb[lq * 100 + lr + 4];
                mma8(acc[nt][0], af[0], b0, b1);
                mma8(acc[nt][1], af[1], b0, b1);
            }
        }
        #pragma unroll
        for (int nt = 0; nt < 8; nt++) {
            #pragma unroll
            for (int mt = 0; mt < 2; mt++) {
                #pragma unroll
                for (int e = 0; e < 4; e++) {
                    int n = smh * 32 + mt * 16 + lq + ((e >> 1) << 3);
                    int m = nt * 8 + 2 * lr + (e & 1);
                    int i1 = n >> 3, j1 = n & 7;
                    int ridx = (i1 - (m >> 3) + 7) * 15 + (j1 - (m & 7) + 7);
                    float v = acc[nt][mt][e] + rpb_s[ridx * 4 + hh];
                    if (cls_s[m] != cls_s[n]) v -= 100.f;
                    S[(hh * 64 + n) * 68 + m] = v;
                }
            }
        }
    }
    __syncthreads();

    // ---------------- Softmax (warp per row); store as tf32 ----------------
    for (int t = 0; t < 32; t++) {
        int row = wid + 8 * t;
        float x0 = S[row * 68 + lane], x1 = S[row * 68 + lane + 32];
        float mx = fmaxf(x0, x1);
        #pragma unroll
        for (int o = 16; o > 0; o >>= 1) mx = fmaxf(mx, __shfl_xor_sync(0xffffffffu, mx, o));
        float e0 = __expf(x0 - mx), e1 = __expf(x1 - mx);
        float sum = e0 + e1;
        #pragma unroll
        for (int o = 16; o > 0; o >>= 1) sum += __shfl_xor_sync(0xffffffffu, sum, o);
        float inv = __fdividef(1.f, sum);
        ((uu*)S)[row * 68 + lane]      = tf32c(e0 * inv);
        ((uu*)S)[row * 68 + lane + 32] = tf32c(e1 * inv);
    }
    __syncthreads();

    // ---------------- AV: AO[n][hd] = P[h] V[h]; tile m32 x n24, 8 k ----------------
    {
        const int hh  = wid & 3;
        const int smh = wid >> 2;
        const uu* Su = (const uu*)S;
        float acc[3][2][4];
        #pragma unroll
        for (int nt = 0; nt < 3; nt++)
            #pragma unroll
            for (int mt = 0; mt < 2; mt++)
                #pragma unroll
                for (int e = 0; e < 4; e++) acc[nt][mt][e] = 0.f;

        #pragma unroll 2
        for (int ks = 0; ks < 8; ks++) {
            int k0 = ks * 8;
            uu af[2][4];
            #pragma unroll
            for (int mt = 0; mt < 2; mt++)
                lda(af[mt], Su + (hh * 64 + smh * 32 + mt * 16) * 68 + k0, 68, lq, lr);
            #pragma unroll
            for (int nt = 0; nt < 3; nt++) {
                const uu* bb = Vtu + (hh * 24 + nt * 8) * 68 + k0;
                uu b0 = bb[lq * 68 + lr], b1 = bb[lq * 68 + lr + 4];
                mma8(acc[nt][0], af[0], b0, b1);
                mma8(acc[nt][1], af[1], b0, b1);
            }
        }
        #pragma unroll
        for (int nt = 0; nt < 3; nt++)
            #pragma unroll
            for (int mt = 0; mt < 2; mt++)
                #pragma unroll
                for (int e = 0; e < 4; e++) {
                    int n = smh * 32 + mt * 16 + lq + ((e >> 1) << 3);
                    int c = hh * 24 + nt * 8 + 2 * lr + (e & 1);
                    AOu[n * 100 + c] = tf32c(acc[nt][mt][e]);
                }
    }
    __syncthreads();

    // ---------------- Proj + residual -> hout ----------------
    {
        float acc[3][2][4];
        #pragma unroll
        for (int nt = 0; nt < 3; nt++)
            #pragma unroll
            for (int mt = 0; mt < 2; mt++)
                #pragma unroll
                for (int e = 0; e < 4; e++) acc[nt][mt][e] = 0.f;

        #pragma unroll 2
        for (int ks = 0; ks < 12; ks++) {
            int k0 = ks * 8;
            uu af[2][4];
            #pragma unroll
            for (int mt = 0; mt < 2; mt++)
                lda(af[mt], AOu + (mh * 32 + mt * 16) * 100 + k0, 100, lq, lr);
            #pragma unroll
            for (int nt = 0; nt < 3; nt++) {
                const uu* bb = Wpu + (nq * 24 + nt * 8) * 100 + k0;
                uu b0 = bb[lq * 100 + lr], b1 = bb[lq * 100 + lr + 4];
                mma8(acc[nt][0], af[0], b0, b1);
                mma8(acc[nt][1], af[1], b0, b1);
            }
        }
        #pragma unroll
        for (int nt = 0; nt < 3; nt++) {
            int j0 = nq * 24 + nt * 8;
            float bl = __ldg(proj_b + j0 + 2 * lr);
            float bh = __ldg(proj_b + j0 + 2 * lr + 1);
            #pragma unroll
            for (int mt = 0; mt < 2; mt++)
                #pragma unroll
                for (int e = 0; e < 4; e++) {
                    int n = mh * 32 + mt * 16 + lq + ((e >> 1) << 3);
                    int j = j0 + 2 * lr + (e & 1);
                    float v = acc[nt][mt][e] + ((e & 1) ? bh : bl)
                            + __ldg(&x[xbase + (j << 16) + pos[n]]);
                    hout[n * 100 + j] = v;
                }
        }
    }
    __syncthreads();

    // write h (NHWC), coalesced
    for (int it = 0; it < 24; it++) {
        int e = tid + it * 256;
        int n = e / 96, c = e - n * 96;
        g_h[(b * 65536 + pos[n]) * 96 + c] = hout[n * 100 + c];
    }
}

// ---------------- Kernel B smem layout (float indices) ----------------
#define B_YS   0        // ys [64][100] tf32 (later: output bounce, fp32)
#define B_XR   6400     // raw h [64][100] fp32 (residual + LN2 input)
#define B_WST  12800    // weight stage: w1-half [192][100] / w2-khalf [96][196]
#define B_HCT  32000    // hct [64][388] tf32
#define B_MU   56832
#define B_RS   56896
#define B_RED  56960    // 256
#define B_RED2 57216    // 256
#define B_TOT  57472    // 229,888 bytes

__global__ void __launch_bounds__(256, 1) swin_mlp_kernel(
    const float* __restrict__ n2w, const float* __restrict__ n2b,
    const float* __restrict__ w1g, const float* __restrict__ b1g,
    const float* __restrict__ w2g, const float* __restrict__ b2g,
    float* __restrict__ out)
{
    extern __shared__ float sm[];
    float* xr   = sm + B_XR;
    float* yb   = sm + B_YS;   // output bounce (after fc1 ys is dead)
    float* mu_s = sm + B_MU;
    float* rs_s = sm + B_RS;
    float* red  = sm + B_RED;
    float* red2 = sm + B_RED2;
    uu* Ysu = (uu*)(sm + B_YS);
    uu* Wsu = (uu*)(sm + B_WST);
    uu* Hcu = (uu*)(sm + B_HCT);

    const int tid  = threadIdx.x;
    const int lane = tid & 31;
    const int wid  = tid >> 5;
    const int lq   = lane >> 2;
    const int lr   = lane & 3;
    const int mh   = wid >> 2;
    const int nq   = wid & 3;
    const int P0   = blockIdx.x * 64;
    const int b    = P0 >> 16;
    const int pix0 = P0 & 65535;

    // load raw h tile -> xr[p][100]
    for (int it = 0; it < 24; it++) {
        int e = tid + it * 256;
        int p = e / 96, c = e - p * 96;
        xr[p * 100 + c] = g_h[P0 * 96 + e];
    }
    __syncthreads();

    // LN2
    {
        int p = tid & 63, part = tid >> 6;
        float s = 0.f, s2 = 0.f;
        #pragma unroll
        for (int cc = 0; cc < 24; cc++) {
            float v = xr[p * 100 + part * 24 + cc];
            s += v; s2 += v * v;
        }
        red[part * 64 + p] = s;
        red2[part * 64 + p] = s2;
    }
    __syncthreads();
    if (tid < 64) {
        float s  = red[tid] + red[64 + tid] + red[128 + tid] + red[192 + tid];
        float s2 = red2[tid] + red2[64 + tid] + red2[128 + tid] + red2[192 + tid];
        float mu = s * (1.f / 96.f);
        float var = s2 * (1.f / 96.f) - mu * mu;
        mu_s[tid] = mu;
        rs_s[tid] = rsqrtf(var + 1e-6f);
    }
    __syncthreads();
    {
        int p = tid & 63, part = tid >> 6;
        float mu = mu_s[p], rs = rs_s[p];
        #pragma unroll
        for (int cc = 0; cc < 24; cc++) {
            int c = part * 24 + cc;
            Ysu[p * 100 + c] = tf32c((xr[p * 100 + c] - mu) * rs * __ldg(n2w + c)
                                     + __ldg(n2b + c));
        }
    }

    // ---------------- fc1 + GELU, two 192-row halves ----------------
    for (int half = 0; half < 2; half++) {
        __syncthreads();
        for (int idx = tid; idx < 18432; idx += 256) {
            int rrow = idx / 96, cc = idx - rrow * 96;
            Wsu[rrow * 100 + cc] = tf32c(__ldg(&w1g[half * 18432 + idx]));
        }
        __syncthreads();

        float acc[6][2][4];
        #pragma unroll
        for (int nt = 0; nt < 6; nt++)
            #pragma unroll
            for (int mt = 0; mt < 2; mt++)
                #pragma unroll
                for (int e = 0; e < 4; e++) acc[nt][mt][e] = 0.f;

        #pragma unroll 2
        for (int ks = 0; ks < 12; ks++) {
            int k0 = ks * 8;
            uu af[2][4];
            #pragma unroll
            for (int mt = 0; mt < 2; mt++)
                lda(af[mt], Ysu + (mh * 32 + mt * 16) * 100 + k0, 100, lq, lr);
            #pragma unroll
            for (int nt = 0; nt < 6; nt++) {
                const uu* bb = Wsu + (nq * 48 + nt * 8) * 100 + k0;
                uu b0 = bb[lq * 100 + lr], b1 = bb[lq * 100 + lr + 4];
                mma8(acc[nt][0], af[0], b0, b1);
                mma8(acc[nt][1], af[1], b0, b1);
            }
        }
        #pragma unroll
        for (int nt = 0; nt < 6; nt++) {
            int jl = nq * 48 + nt * 8;
            float bl = __ldg(b1g + half * 192 + jl + 2 * lr);
            float bh = __ldg(b1g + half * 192 + jl + 2 * lr + 1);
            #pragma unroll
            for (int mt = 0; mt < 2; mt++)
                #pragma unroll
                for (int e = 0; e < 4; e++) {
                    int p = mh * 32 + mt * 16 + lq + ((e >> 1) << 3);
                    int jg = half * 192 + jl + 2 * lr + (e & 1);
                    float v = acc[nt][mt][e] + ((e & 1) ? bh : bl);
                    v = 0.5f * v * (1.f + erf_as(v * 0.7071067811865475f));
                    Hcu[p * 388 + jg] = tf32c(v);
                }
        }
    }

    // ---------------- fc2 over two k-halves (acc persists) ----------------
    float acc2[3][2][4];
    #pragma unroll
    for (int nt = 0; nt < 3; nt++)
        #pragma unroll
        for (int mt = 0; mt < 2; mt++)
            #pragma unroll
            for (int e = 0; e < 4; e++) acc2[nt][mt][e] = 0.f;

    for (int kh = 0; kh < 2; kh++) {
        __syncthreads();
        for (int idx = tid; idx < 18432; idx += 256) {
            int cch = idx / 192, kk = idx - cch * 192;
            Wsu[cch * 196 + kk] = tf32c(__ldg(&w2g[cch * 384 + kh * 192 + kk]));
        }
        __syncthreads();

        #pragma unroll 2
        for (int ks = 0; ks < 24; ks++) {
            int k0 = ks * 8;
            uu af[2][4];
            #pragma unroll
            for (int mt = 0; mt < 2; mt++)
                lda(af[mt], Hcu + (mh * 32 + mt * 16) * 388 + kh * 192 + k0, 388, lq, lr);
            #pragma unroll
            for (int nt = 0; nt < 3; nt++) {
                const uu* bb = Wsu + (nq * 24 + nt * 8) * 196 + k0;
                uu b0 = bb[lq * 196 + lr], b1 = bb[lq * 196 + lr + 4];
                mma8(acc2[nt][0], af[0], b0, b1);
                mma8(acc2[nt][1], af[1], b0, b1);
            }
        }
    }
    __syncthreads();   // ys dead; yb reuse safe

    // epilogue: bias + residual -> yb bounce
    #pragma unroll
    for (int nt = 0; nt < 3; nt++) {
        int c0 = nq * 24 + nt * 8;
        float bl = __ldg(b2g + c0 + 2 * lr);
        float bh = __ldg(b2g + c0 + 2 * lr + 1);
        #pragma unroll
        for (int mt = 0; mt < 2; mt++)
            #pragma unroll
            for (int e = 0; e < 4; e++) {
                int p = mh * 32 + mt * 16 + lq + ((e >> 1) << 3);
                int c = c0 + 2 * lr + (e & 1);
                yb[p * 100 + c] = acc2[nt][mt][e] + ((e & 1) ? bh : bl)
                                + xr[p * 100 + c];
            }
    }
    __syncthreads();

    // coalesced NCHW store
    for (int it = 0; it < 24; it++) {
        int e = tid + it * 256;
        int c = e >> 6, p = e & 63;
        out[((size_t)(b * 96 + c) << 16) + (size_t)pix0 + p] = yb[p * 100 + c];
    }
}

extern "C" void kernel_launch(void* const* d_in, const int* in_sizes, int n_in,
                              void* d_out, int out_size)
{
    const float* x      = (const float*)d_in[0];
    const float* norm_w = (const float*)d_in[1];
    const float* norm_b = (const float*)d_in[2];
    const float* qkv_w  = (const float*)d_in[3];
    const float* qkv_b  = (const float*)d_in[4];
    const float* proj_w = (const float*)d_in[5];
    const float* proj_b = (const float*)d_in[6];
    const float* rpb    = (const float*)d_in[7];
    const float* n2w    = (const float*)d_in[8];
    const float* n2b    = (const float*)d_in[9];
    const float* fc1_w  = (const float*)d_in[10];
    const float* fc1_b  = (const float*)d_in[11];
    const float* fc2_w  = (const float*)d_in[12];
    const float* fc2_b  = (const float*)d_in[13];
    float* out = (float*)d_out;

    cudaFuncSetAttribute(swin_attn_kernel, cudaFuncAttributeMaxDynamicSharedMemorySize,
                         A_TOT * 4);
    cudaFuncSetAttribute(swin_mlp_kernel, cudaFuncAttributeMaxDynamicSharedMemorySize,
                         B_TOT * 4);

    swin_attn_kernel<<<4096, 256, A_TOT * 4>>>(
        x, norm_w, norm_b, qkv_w, qkv_b, proj_w, proj_b, rpb);
    swin_mlp_kernel<<<4096, 256, B_TOT * 4>>>(
        n2w, n2b, fc1_w, fc1_b, fc2_w, fc2_b, out);
}

// round 6
// speedup vs baseline: 3.4086x; 1.6675x over previous
#include <cuda_runtime.h>
#include <math.h>

// ---------------------------------------------------------------------------
// Swin block, B=4 C=96 H=W=256 WS=8 NH=4 HD=24 SHIFT=4 N=64 MLP_H=384
// tf32 mma.sync m16n8k8 tensor cores, 512-thread CTAs (16 warps/SM).
// Kernel A (4096 CTAs, 1 window): LN1 + QKV + scores(bias+mask) + in-register
//   softmax + in-register P->AV + proj + residual -> g_h (NHWC scratch)
// Kernel B (2048 CTAs, 128 pixels): LN2 + fc1 + GELU + fc2 + residual -> NCHW
// Smem operand strides all ≡ 4 (mod 32) => conflict-free fragment loads.
// ---------------------------------------------------------------------------

typedef unsigned uu;

__device__ __forceinline__ uu tf32c(float f) {
    uu u; asm("cvt.rna.tf32.f32 %0, %1;" : "=r"(u) : "f"(f)); return u;
}
__device__ __forceinline__ void mma8(float* d, const uu* a, uu b0, uu b1) {
    asm("mma.sync.aligned.m16n8k8.row.col.f32.tf32.tf32.f32 "
        "{%0,%1,%2,%3},{%4,%5,%6,%7},{%8,%9},{%0,%1,%2,%3};"
        : "+f"(d[0]), "+f"(d[1]), "+f"(d[2]), "+f"(d[3])
        : "r"(a[0]), "r"(a[1]), "r"(a[2]), "r"(a[3]), "r"(b0), "r"(b1));
}
// A fragment, row-major m16k8 from smem tile base (16 rows x 8 cols)
__device__ __forceinline__ void lda(uu* a, const uu* base, int stride, int lq, int lr) {
    a[0] = base[lq * stride + lr];
    a[1] = base[(lq + 8) * stride + lr];
    a[2] = base[lq * stride + lr + 4];
    a[3] = base[(lq + 8) * stride + lr + 4];
}

// Abramowitz-Stegun 7.1.26 erf (|abs err| < 1.5e-7)
__device__ __forceinline__ float erf_as(float x) {
    float ax = fabsf(x);
    float t  = __frcp_rn(1.f + 0.3275911f * ax);
    float y  = t * (0.254829592f + t * (-0.284496736f + t * (1.421413741f
             + t * (-1.453152027f + t * 1.061405429f))));
    float r  = 1.f - y * __expf(-ax * ax);
    return copysignf(r, x);
}

// NHWC scratch for h = x + attn_out (100.7 MB)
__device__ float g_h[4 * 256 * 256 * 96];

// ---------------- Kernel A smem (float indices) ----------------
#define A_XT   0        // X_ln [64][100] tf32  (later AO, tf32)
#define A_Q    6400     // Q    [64][100] tf32  (later hout, fp32)
#define A_K    12800    // K    [64][100] tf32
#define A_VT   19200    // V^T  [96][68]  tf32
#define A_WU   25728    // Wqkv stage [288][100] tf32 / later Wproj [96][100]
#define A_RPB  54528    // 900
#define A_POS  55428    // 64 int
#define A_CLS  55492    // 64 int
#define A_MU   55556    // 64
#define A_RS   55620    // 64
#define A_TOT  55684    // 222,736 bytes

__global__ void __launch_bounds__(512, 1) swin_attn_kernel(
    const float* __restrict__ x,
    const float* __restrict__ norm_w, const float* __restrict__ norm_b,
    const float* __restrict__ qkv_w,  const float* __restrict__ qkv_b,
    const float* __restrict__ proj_w, const float* __restrict__ proj_b,
    const float* __restrict__ rpb)
{
    extern __shared__ float sm[];
    float* xt    = sm + A_XT;
    float* rpb_s = sm + A_RPB;
    float* mu_s  = sm + A_MU;
    float* rs_s  = sm + A_RS;
    int*   pos   = (int*)(sm + A_POS);
    int*   cls_s = (int*)(sm + A_CLS);

    uu* Xu  = (uu*)(sm + A_XT);
    uu* Qu  = (uu*)(sm + A_Q);
    uu* Ku  = (uu*)(sm + A_K);
    uu* Vtu = (uu*)(sm + A_VT);
    uu* Wu  = (uu*)(sm + A_WU);
    uu* AOu = (uu*)(sm + A_XT);   // AO overlays xt (dead after QKV)
    float* hout = sm + A_Q;       // hout overlays Q (dead after scores)

    const int tid  = threadIdx.x;
    const int lane = tid & 31;
    const int wid  = tid >> 5;            // 0..15
    const int lq   = lane >> 2;           // 0..7
    const int lr   = lane & 3;            // 0..3
    const int mh   = wid >> 2;            // QKV/proj: m16 group 0..3
    const int nq   = wid & 3;             // QKV/proj: n group 0..3
    const int hh   = wid & 3;             // scores/AV: head
    const int mq   = wid >> 2;            // scores/AV: 16-row slice
    const int blk  = blockIdx.x;
    const int b    = blk >> 10;
    const int wh   = (blk >> 5) & 31;
    const int ww   = blk & 31;

    if (tid < 64) {
        int i = tid >> 3, j = tid & 7;
        int hs = wh * 8 + i;
        int wsp = ww * 8 + j;
        int r = (hs + 4) & 255;
        int c = (wsp + 4) & 255;
        pos[tid] = r * 256 + c;
        int rr = (hs  < 248) ? 0 : ((hs  < 252) ? 1 : 2);
        int cr = (wsp < 248) ? 0 : ((wsp < 252) ? 1 : 2);
        cls_s[tid] = rr * 3 + cr;
    }
    for (int idx = tid; idx < 900; idx += 512) rpb_s[idx] = __ldg(rpb + idx);
    __syncthreads();                                   // (1)

    const int xbase = b * 96 * 65536;

    // load tokens -> xt[n][100] fp32
    #pragma unroll
    for (int it = 0; it < 12; it++) {
        int e = tid + it * 512;
        int c = e >> 6, n = e & 63;
        xt[n * 100 + c] = __ldg(&x[xbase + (c << 16) + pos[n]]);
    }
    __syncthreads();                                   // (2)

    // LN1 stats: 8 lanes per token, 12 channels each, shfl reduce
    {
        int p = tid >> 3, part = tid & 7;
        float s = 0.f, s2 = 0.f;
        #pragma unroll
        for (int i = 0; i < 12; i++) {
            float v = xt[p * 100 + part * 12 + i];
            s += v; s2 += v * v;
        }
        #pragma unroll
        for (int o = 1; o < 8; o <<= 1) {
            s  += __shfl_xor_sync(0xffffffffu, s,  o);
            s2 += __shfl_xor_sync(0xffffffffu, s2, o);
        }
        if (part == 0) {
            float mu = s * (1.f / 96.f);
            float var = s2 * (1.f / 96.f) - mu * mu;
            mu_s[p] = mu;
            rs_s[p] = rsqrtf(var + 1e-6f);
        }
    }
    __syncthreads();                                   // (3)

    // normalize -> tf32 in place; stage Wqkv [288][100]
    #pragma unroll
    for (int it = 0; it < 12; it++) {
        int e = tid + it * 512;
        int c = e >> 6, n = e & 63;
        float v = (xt[n * 100 + c] - mu_s[n]) * rs_s[n] * __ldg(norm_w + c)
                  + __ldg(norm_b + c);
        Xu[n * 100 + c] = tf32c(v);
    }
    for (int idx = tid; idx < 27648; idx += 512) {
        int r = idx / 96, c = idx - (idx / 96) * 96;
        Wu[r * 100 + c] = tf32c(__ldg(qkv_w + idx));
    }
    __syncthreads();                                   // (4)

    // ---------------- QKV: warp tile m16 x n72, 12 k-steps ----------------
    {
        float acc[9][4];
        #pragma unroll
        for (int nt = 0; nt < 9; nt++)
            #pragma unroll
            for (int e = 0; e < 4; e++) acc[nt][e] = 0.f;

        #pragma unroll 2
        for (int ks = 0; ks < 12; ks++) {
            int k0 = ks * 8;
            uu af[4];
            lda(af, Xu + (mh * 16) * 100 + k0, 100, lq, lr);
            #pragma unroll
            for (int nt = 0; nt < 9; nt++) {
                const uu* bb = Wu + (nq * 72 + nt * 8) * 100 + k0;
                uu b0 = bb[lq * 100 + lr], b1 = bb[lq * 100 + lr + 4];
                mma8(acc[nt], af, b0, b1);
            }
        }
        const float scale = 0.2041241452319315f;  // 24^-0.5
        #pragma unroll
        for (int nt = 0; nt < 9; nt++) {
            int j0 = nq * 72 + nt * 8;
            float bl = __ldg(qkv_b + j0 + 2 * lr);
            float bh = __ldg(qkv_b + j0 + 2 * lr + 1);
            #pragma unroll
            for (int e = 0; e < 4; e++) {
                int row = mh * 16 + lq + ((e >> 1) << 3);
                int col = j0 + 2 * lr + (e & 1);
                float v = acc[nt][e] + ((e & 1) ? bh : bl);
                if (col < 96)       Qu[row * 100 + col] = tf32c(v * scale);
                else if (col < 192) Ku[row * 100 + col - 96] = tf32c(v);
                else                Vtu[(col - 192) * 68 + row] = tf32c(v);
            }
        }
    }
    __syncthreads();                                   // (5)

    // stage Wproj [96][100] into Wu (Wqkv dead); visible by sync (6)
    for (int idx = tid; idx < 9216; idx += 512) {
        int r = idx / 96, c = idx - (idx / 96) * 96;
        Wu[r * 100 + c] = tf32c(__ldg(proj_w + idx));
    }

    // ---- Scores (m16 rows x 64 cols) + bias + mask + softmax + AV, in-reg ----
    {
        float acc[8][4];
        #pragma unroll
        for (int nt = 0; nt < 8; nt++)
            #pragma unroll
            for (int e = 0; e < 4; e++) acc[nt][e] = 0.f;

        #pragma unroll
        for (int ks = 0; ks < 3; ks++) {
            int k0 = hh * 24 + ks * 8;
            uu af[4];
            lda(af, Qu + (mq * 16) * 100 + k0, 100, lq, lr);
            #pragma unroll
            for (int nt = 0; nt < 8; nt++) {
                const uu* bb = Ku + (nt * 8) * 100 + k0;
                uu b0 = bb[lq * 100 + lr], b1 = bb[lq * 100 + lr + 4];
                mma8(acc[nt], af, b0, b1);
            }
        }
        // bias + mask
        int nlo = mq * 16 + lq, nhi = nlo + 8;
        int ilo = nlo >> 3, jlo = nlo & 7, clo = cls_s[nlo];
        int ihi = nhi >> 3, jhi = nhi & 7, chi = cls_s[nhi];
        #pragma unroll
        for (int nt = 0; nt < 8; nt++) {
            #pragma unroll
            for (int e = 0; e < 4; e++) {
                int m = nt * 8 + 2 * lr + (e & 1);
                int mi = m >> 3, mj = m & 7;
                int cm = cls_s[m];
                if (e < 2) {
                    int ridx = (ilo - mi + 7) * 15 + (jlo - mj + 7);
                    acc[nt][e] += rpb_s[ridx * 4 + hh];
                    if (cm != clo) acc[nt][e] -= 100.f;
                } else {
                    int ridx = (ihi - mi + 7) * 15 + (jhi - mj + 7);
                    acc[nt][e] += rpb_s[ridx * 4 + hh];
                    if (cm != chi) acc[nt][e] -= 100.f;
                }
            }
        }
        // softmax per row (reduce over lr lanes: xor 1,2)
        float mx0 = -1e30f, mx1 = -1e30f;
        #pragma unroll
        for (int nt = 0; nt < 8; nt++) {
            mx0 = fmaxf(mx0, fmaxf(acc[nt][0], acc[nt][1]));
            mx1 = fmaxf(mx1, fmaxf(acc[nt][2], acc[nt][3]));
        }
        #pragma unroll
        for (int o = 1; o < 4; o <<= 1) {
            mx0 = fmaxf(mx0, __shfl_xor_sync(0xffffffffu, mx0, o));
            mx1 = fmaxf(mx1, __shfl_xor_sync(0xffffffffu, mx1, o));
        }
        float sm0 = 0.f, sm1 = 0.f;
        #pragma unroll
        for (int nt = 0; nt < 8; nt++) {
            acc[nt][0] = __expf(acc[nt][0] - mx0);
            acc[nt][1] = __expf(acc[nt][1] - mx0);
            acc[nt][2] = __expf(acc[nt][2] - mx1);
            acc[nt][3] = __expf(acc[nt][3] - mx1);
            sm0 += acc[nt][0] + acc[nt][1];
            sm1 += acc[nt][2] + acc[nt][3];
        }
        #pragma unroll
        for (int o = 1; o < 4; o <<= 1) {
            sm0 += __shfl_xor_sync(0xffffffffu, sm0, o);
            sm1 += __shfl_xor_sync(0xffffffffu, sm1, o);
        }
        float inv0 = __fdividef(1.f, sm0);
        float inv1 = __fdividef(1.f, sm1);
        #pragma unroll
        for (int nt = 0; nt < 8; nt++) {
            acc[nt][0] *= inv0; acc[nt][1] *= inv0;
            acc[nt][2] *= inv1; acc[nt][3] *= inv1;
        }

        // AV: A-frags of P built via quad shuffles; B = V^T [96][68]
        float fav[3][4];
        #pragma unroll
        for (int nt = 0; nt < 3; nt++)
            #pragma unroll
            for (int e = 0; e < 4; e++) fav[nt][e] = 0.f;

        #pragma unroll
        for (int ks = 0; ks < 8; ks++) {
            int srcA = (lane & ~3) | (lr >> 1);   // same lq, lr/2
            int srcB = srcA + 2;
            float sA0 = __shfl_sync(0xffffffffu, acc[ks][0], srcA);
            float sA1 = __shfl_sync(0xffffffffu, acc[ks][1], srcA);
            float sA2 = __shfl_sync(0xffffffffu, acc[ks][2], srcA);
            float sA3 = __shfl_sync(0xffffffffu, acc[ks][3], srcA);
            float sB0 = __shfl_sync(0xffffffffu, acc[ks][0], srcB);
            float sB1 = __shfl_sync(0xffffffffu, acc[ks][1], srcB);
            float sB2 = __shfl_sync(0xffffffffu, acc[ks][2], srcB);
            float sB3 = __shfl_sync(0xffffffffu, acc[ks][3], srcB);
            bool oddc = (lr & 1);
            uu a[4];
            a[0] = tf32c(oddc ? sA1 : sA0);
            a[1] = tf32c(oddc ? sA3 : sA2);
            a[2] = tf32c(oddc ? sB1 : sB0);
            a[3] = tf32c(oddc ? sB3 : sB2);
            #pragma unroll
            for (int nt = 0; nt < 3; nt++) {
                const uu* bb = Vtu + (hh * 24 + nt * 8) * 68 + ks * 8;
                uu b0 = bb[lq * 68 + lr], b1 = bb[lq * 68 + lr + 4];
                mma8(fav[nt], a, b0, b1);
            }
        }
        // AO -> smem (overlay xt)
        #pragma unroll
        for (int nt = 0; nt < 3; nt++)
            #pragma unroll
            for (int e = 0; e < 4; e++) {
                int n = mq * 16 + lq + ((e >> 1) << 3);
                int c = hh * 24 + nt * 8 + 2 * lr + (e & 1);
                AOu[n * 100 + c] = tf32c(fav[nt][e]);
            }
    }
    __syncthreads();                                   // (6)

    // ---------------- Proj (m16 x n24) + residual -> hout ----------------
    {
        float acc[3][4];
        #pragma unroll
        for (int nt = 0; nt < 3; nt++)
            #pragma unroll
            for (int e = 0; e < 4; e++) acc[nt][e] = 0.f;

        #pragma unroll 2
        for (int ks = 0; ks < 12; ks++) {
            int k0 = ks * 8;
            uu af[4];
            lda(af, AOu + (mh * 16) * 100 + k0, 100, lq, lr);
            #pragma unroll
            for (int nt = 0; nt < 3; nt++) {
                const uu* bb = Wu + (nq * 24 + nt * 8) * 100 + k0;
                uu b0 = bb[lq * 100 + lr], b1 = bb[lq * 100 + lr + 4];
                mma8(acc[nt], af, b0, b1);
            }
        }
        #pragma unroll
        for (int nt = 0; nt < 3; nt++) {
            int j0 = nq * 24 + nt * 8;
            float bl = __ldg(proj_b + j0 + 2 * lr);
            float bh = __ldg(proj_b + j0 + 2 * lr + 1);
            #pragma unroll
            for (int e = 0; e < 4; e++) {
                int n = mh * 16 + lq + ((e >> 1) << 3);
                int j = j0 + 2 * lr + (e & 1);
                float v = acc[nt][e] + ((e & 1) ? bh : bl)
                        + __ldg(&x[xbase + (j << 16) + pos[n]]);
                hout[n * 100 + j] = v;
            }
        }
    }
    __syncthreads();                                   // (7)

    // write h (NHWC), coalesced
    #pragma unroll
    for (int it = 0; it < 12; it++) {
        int e = tid + it * 512;
        int n = e / 96, c = e - (e / 96) * 96;
        g_h[(b * 65536 + pos[n]) * 96 + c] = hout[n * 100 + c];
    }
}

// ---------------- Kernel B smem (float indices) ----------------
#define B_YS   0        // ys [128][100] tf32 (later yb [128][97] fp32)
#define B_WST  12800    // w1 half [192][100] / w2 half [96][196]
#define B_HCT  32000    // hct [128][196] tf32 (one k-half)
#define B_MU   57088    // 128
#define B_RS   57216    // 128
#define B_TOT  57344    // 229,376 bytes

__global__ void __launch_bounds__(512, 1) swin_mlp_kernel(
    const float* __restrict__ n2w, const float* __restrict__ n2b,
    const float* __restrict__ w1g, const float* __restrict__ b1g,
    const float* __restrict__ w2g, const float* __restrict__ b2g,
    float* __restrict__ out)
{
    extern __shared__ float sm[];
    float* yb   = sm + B_YS;    // epilogue bounce [128][97]
    float* mu_s = sm + B_MU;
    float* rs_s = sm + B_RS;
    uu* Ysu = (uu*)(sm + B_YS);
    uu* Wsu = (uu*)(sm + B_WST);
    uu* Hcu = (uu*)(sm + B_HCT);

    const int tid  = threadIdx.x;
    const int lane = tid & 31;
    const int wid  = tid >> 5;
    const int lq   = lane >> 2;
    const int lr   = lane & 3;
    const int mh   = wid >> 2;          // m32 group 0..3 (128 rows)
    const int nq   = wid & 3;
    const int P0   = blockIdx.x * 128;
    const int b    = P0 >> 16;
    const int pix0 = P0 & 65535;

    // LN2 stats straight from g_h: 4 lanes per token, 24 ch each (6 float4)
    {
        int p = tid >> 2, part = tid & 3;
        const float4* g4 = (const float4*)(g_h + (size_t)(P0 + p) * 96 + part * 24);
        float s = 0.f, s2 = 0.f;
        #pragma unroll
        for (int i = 0; i < 6; i++) {
            float4 v = g4[i];
            s  += v.x + v.y + v.z + v.w;
            s2 += v.x * v.x + v.y * v.y + v.z * v.z + v.w * v.w;
        }
        #pragma unroll
        for (int o = 1; o < 4; o <<= 1) {
            s  += __shfl_xor_sync(0xffffffffu, s,  o);
            s2 += __shfl_xor_sync(0xffffffffu, s2, o);
        }
        if (part == 0) {
            float mu = s * (1.f / 96.f);
            float var = s2 * (1.f / 96.f) - mu * mu;
            mu_s[p] = mu;
            rs_s[p] = rsqrtf(var + 1e-6f);
        }
    }
    __syncthreads();                                   // (1)

    // normalize -> ys tf32; stage w1 half0 [192][100]
    #pragma unroll
    for (int it = 0; it < 6; it++) {
        int v4 = tid + it * 512;                       // 3072 float4s
        int p = v4 / 24, c4 = v4 - (v4 / 24) * 24;
        float4 g = *(const float4*)(g_h + (size_t)(P0 + p) * 96 + c4 * 4);
        float mu = mu_s[p], rs = rs_s[p];
        int c = c4 * 4;
        uu* dst = Ysu + p * 100 + c;
        dst[0] = tf32c((g.x - mu) * rs * __ldg(n2w + c)     + __ldg(n2b + c));
        dst[1] = tf32c((g.y - mu) * rs * __ldg(n2w + c + 1) + __ldg(n2b + c + 1));
        dst[2] = tf32c((g.z - mu) * rs * __ldg(n2w + c + 2) + __ldg(n2b + c + 2));
        dst[3] = tf32c((g.w - mu) * rs * __ldg(n2w + c + 3) + __ldg(n2b + c + 3));
    }
    for (int idx = tid; idx < 18432; idx += 512) {
        int r = idx / 96, c = idx - (idx / 96) * 96;
        Wsu[r * 100 + c] = tf32c(__ldg(&w1g[idx]));
    }
    __syncthreads();                                   // (2)

    float acc2[3][2][4];
    #pragma unroll
    for (int nt = 0; nt < 3; nt++)
        #pragma unroll
        for (int mt = 0; mt < 2; mt++)
            #pragma unroll
            for (int e = 0; e < 4; e++) acc2[nt][mt][e] = 0.f;

    for (int half = 0; half < 2; half++) {
        // ---- fc1 half: m32 x n48, 12 ksteps ----
        {
            float acc[6][2][4];
            #pragma unroll
            for (int nt = 0; nt < 6; nt++)
                #pragma unroll
                for (int mt = 0; mt < 2; mt++)
                    #pragma unroll
                    for (int e = 0; e < 4; e++) acc[nt][mt][e] = 0.f;

            #pragma unroll 2
            for (int ks = 0; ks < 12; ks++) {
                int k0 = ks * 8;
                uu af[2][4];
                #pragma unroll
                for (int mt = 0; mt < 2; mt++)
                    lda(af[mt], Ysu + (mh * 32 + mt * 16) * 100 + k0, 100, lq, lr);
                #pragma unroll
                for (int nt = 0; nt < 6; nt++) {
                    const uu* bb = Wsu + (nq * 48 + nt * 8) * 100 + k0;
                    uu b0 = bb[lq * 100 + lr], b1 = bb[lq * 100 + lr + 4];
                    mma8(acc[nt][0], af[0], b0, b1);
                    mma8(acc[nt][1], af[1], b0, b1);
                }
            }
            #pragma unroll
            for (int nt = 0; nt < 6; nt++) {
                int jl = nq * 48 + nt * 8;
                float bl = __ldg(b1g + half * 192 + jl + 2 * lr);
                float bh = __ldg(b1g + half * 192 + jl + 2 * lr + 1);
                #pragma unroll
                for (int mt = 0; mt < 2; mt++)
                    #pragma unroll
                    for (int e = 0; e < 4; e++) {
                        int p = mh * 32 + mt * 16 + lq + ((e >> 1) << 3);
                        int j = jl + 2 * lr + (e & 1);
                        float v = acc[nt][mt][e] + ((e & 1) ? bh : bl);
                        v = 0.5f * v * (1.f + erf_as(v * 0.7071067811865475f));
                        Hcu[p * 196 + j] = tf32c(v);
                    }
            }
        }
        __syncthreads();                               // hct ready, wst free

        // stage w2 half [96][196]
        for (int idx = tid; idx < 18432; idx += 512) {
            int c = idx / 192, kk = idx - (idx / 192) * 192;
            Wsu[c * 196 + kk] = tf32c(__ldg(&w2g[c * 384 + half * 192 + kk]));
        }
        __syncthreads();

        // ---- fc2 partial: m32 x n24, 24 ksteps ----
        #pragma unroll 2
        for (int ks = 0; ks < 24; ks++) {
            int k0 = ks * 8;
            uu af[2][4];
            #pragma unroll
            for (int mt = 0; mt < 2; mt++)
                lda(af[mt], Hcu + (mh * 32 + mt * 16) * 196 + k0, 196, lq, lr);
            #pragma unroll
            for (int nt = 0; nt < 3; nt++) {
                const uu* bb = Wsu + (nq * 24 + nt * 8) * 196 + k0;
                uu b0 = bb[lq * 196 + lr], b1 = bb[lq * 196 + lr + 4];
                mma8(acc2[nt][0], af[0], b0, b1);
                mma8(acc2[nt][1], af[1], b0, b1);
            }
        }
        __syncthreads();                               // hct/wst free

        if (half == 0) {
            // stage w1 half1
            for (int idx = tid; idx < 18432; idx += 512) {
                int r = idx / 96, c = idx - (idx / 96) * 96;
                Wsu[r * 100 + c] = tf32c(__ldg(&w1g[18432 + idx]));
            }
            __syncthreads();
        }
    }

    // epilogue: bias + residual -> yb [128][97]   (ys dead after fc1 half1)
    #pragma unroll
    for (int nt = 0; nt < 3; nt++) {
        int c0 = nq * 24 + nt * 8;
        float bl = __ldg(b2g + c0 + 2 * lr);
        float bh = __ldg(b2g + c0 + 2 * lr + 1);
        #pragma unroll
        for (int mt = 0; mt < 2; mt++)
            #pragma unroll
            for (int e = 0; e < 4; e++) {
                int p = mh * 32 + mt * 16 + lq + ((e >> 1) << 3);
                int c = c0 + 2 * lr + (e & 1);
                float v = acc2[nt][mt][e] + ((e & 1) ? bh : bl)
                        + g_h[(size_t)(P0 + p) * 96 + c];
                yb[p * 97 + c] = v;
            }
    }
    __syncthreads();

    // coalesced NCHW store (stride-97 LDS: conflict-free)
    #pragma unroll
    for (int it = 0; it < 24; it++) {
        int e = tid + it * 512;
        int c = e >> 7, p = e & 127;
        out[((size_t)(b * 96 + c) << 16) + (size_t)pix0 + p] = yb[p * 97 + c];
    }
}

extern "C" void kernel_launch(void* const* d_in, const int* in_sizes, int n_in,
                              void* d_out, int out_size)
{
    const float* x      = (const float*)d_in[0];
    const float* norm_w = (const float*)d_in[1];
    const float* norm_b = (const float*)d_in[2];
    const float* qkv_w  = (const float*)d_in[3];
    const float* qkv_b  = (const float*)d_in[4];
    const float* proj_w = (const float*)d_in[5];
    const float* proj_b = (const float*)d_in[6];
    const float* rpb    = (const float*)d_in[7];
    const float* n2w    = (const float*)d_in[8];
    const float* n2b    = (const float*)d_in[9];
    const float* fc1_w  = (const float*)d_in[10];
    const float* fc1_b  = (const float*)d_in[11];
    const float* fc2_w  = (const float*)d_in[12];
    const float* fc2_b  = (const float*)d_in[13];
    float* out = (float*)d_out;

    cudaFuncSetAttribute(swin_attn_kernel, cudaFuncAttributeMaxDynamicSharedMemorySize,
                         A_TOT * 4);
    cudaFuncSetAttribute(swin_mlp_kernel, cudaFuncAttributeMaxDynamicSharedMemorySize,
                         B_TOT * 4);

    swin_attn_kernel<<<4096, 512, A_TOT * 4>>>(
        x, norm_w, norm_b, qkv_w, qkv_b, proj_w, proj_b, rpb);
    swin_mlp_kernel<<<2048, 512, B_TOT * 4>>>(
        n2w, n2b, fc1_w, fc1_b, fc2_w, fc2_b, out);
}

// round 7
// speedup vs baseline: 3.7702x; 1.1061x over previous
#include <cuda_runtime.h>
#include <math.h>

// ---------------------------------------------------------------------------
// Swin block, B=4 C=96 H=W=256 WS=8 NH=4 HD=24 SHIFT=4 N=64 MLP_H=384
// tf32 mma.sync m16n8k8, 512-thread CTAs. Weights pre-converted/padded/
// k-permuted into __device__ images by a prep kernel; staging = uint4 memcpy.
// k-permuted smem layouts (slot ((k&3)<<1)|(k>>2) within 8-groups, strides
// ≡ 8 mod 32) make fragment loads LDS.64 and conflict-free.
// ---------------------------------------------------------------------------

typedef unsigned uu;

__device__ __forceinline__ uu tf32c(float f) {
    uu u; asm("cvt.rna.tf32.f32 %0, %1;" : "=r"(u) : "f"(f)); return u;
}
__device__ __forceinline__ void mma8(float* d, const uu* a, uu b0, uu b1) {
    asm("mma.sync.aligned.m16n8k8.row.col.f32.tf32.tf32.f32 "
        "{%0,%1,%2,%3},{%4,%5,%6,%7},{%8,%9},{%0,%1,%2,%3};"
        : "+f"(d[0]), "+f"(d[1]), "+f"(d[2]), "+f"(d[3])
        : "r"(a[0]), "r"(a[1]), "r"(a[2]), "r"(a[3]), "r"(b0), "r"(b1));
}
__device__ __forceinline__ int kperm(int k) {
    return (k & ~7) | ((k & 3) << 1) | ((k >> 2) & 1);
}
// A fragment (m16k8) from k-permuted tile: 2x LDS.64
__device__ __forceinline__ void lda64(uu* a, const uu* base, int stride, int lq, int lr) {
    uint2 v0 = *(const uint2*)(base + lq * stride + 2 * lr);
    uint2 v1 = *(const uint2*)(base + (lq + 8) * stride + 2 * lr);
    a[0] = v0.x; a[2] = v0.y; a[1] = v1.x; a[3] = v1.y;
}
// B fragment (n8k8) from k-permuted tile: 1x LDS.64
__device__ __forceinline__ void ldb64(uu& b0, uu& b1, const uu* p) {
    uint2 v = *(const uint2*)p; b0 = v.x; b1 = v.y;
}
// A fragment from natural-layout tile: 4x LDS.32
__device__ __forceinline__ void lda(uu* a, const uu* base, int stride, int lq, int lr) {
    a[0] = base[lq * stride + lr];
    a[1] = base[(lq + 8) * stride + lr];
    a[2] = base[lq * stride + lr + 4];
    a[3] = base[(lq + 8) * stride + lr + 4];
}

// Abramowitz-Stegun 7.1.26 erf (|abs err| < 1.5e-7)
__device__ __forceinline__ float erf_as(float x) {
    float ax = fabsf(x);
    float t  = __frcp_rn(1.f + 0.3275911f * ax);
    float y  = t * (0.254829592f + t * (-0.284496736f + t * (1.421413741f
             + t * (-1.453152027f + t * 1.061405429f))));
    float r  = 1.f - y * __expf(-ax * ax);
    return copysignf(r, x);
}

// NHWC scratch for h = x + attn_out (100.7 MB)
__device__ float g_h[4 * 256 * 256 * 96];

// Pre-converted tf32 weight images (match smem staging layouts exactly)
__device__ uu g_wqkv[288 * 104];   // k-permuted, stride 104
__device__ uu g_wproj[96 * 104];   // k-permuted, stride 104
__device__ uu g_w1[2 * 192 * 100]; // natural, stride 100, per-half
__device__ uu g_w2[2 * 96 * 196];  // natural, stride 196, per-k-half

__global__ void swin_prep_kernel(const float* __restrict__ qkv_w,
                                 const float* __restrict__ proj_w,
                                 const float* __restrict__ fc1_w,
                                 const float* __restrict__ fc2_w)
{
    int t = blockIdx.x * blockDim.x + threadIdx.x;
    int T = gridDim.x * blockDim.x;
    for (int i = t; i < 27648; i += T) {
        int r = i / 96, k = i - r * 96;
        g_wqkv[r * 104 + kperm(k)] = tf32c(__ldg(qkv_w + i));
    }
    for (int i = t; i < 9216; i += T) {
        int r = i / 96, k = i - r * 96;
        g_wproj[r * 104 + kperm(k)] = tf32c(__ldg(proj_w + i));
    }
    for (int i = t; i < 36864; i += T) {
        int r = i / 96, k = i - r * 96;
        int half = (r >= 192) ? 1 : 0;
        g_w1[half * 19200 + (r - half * 192) * 100 + k] = tf32c(__ldg(fc1_w + i));
    }
    for (int i = t; i < 36864; i += T) {
        int c = i / 384, kk = i - c * 384;
        int half = (kk >= 192) ? 1 : 0;
        g_w2[half * 18816 + c * 196 + (kk - half * 192)] = tf32c(__ldg(fc2_w + i));
    }
}

// ---------------- Kernel A smem (float/word indices) ----------------
#define A_XT   0        // X_ln [64][104] tf32, k-perm (later AO)
#define A_Q    6656     // Q    [64][104] tf32, k-perm (later hout fp32)
#define A_K    13312    // K    [64][104] tf32, k-perm
#define A_VT   19968    // V^T  [96][72]  tf32, token-perm cols
#define A_WU   26880    // Wqkv [288][104] (29952) / later Wproj [96][104]
#define A_RPB  56832    // 900
#define A_POS  57732    // 64 int
#define A_CLS  57796    // 64 int
#define A_MU   57860    // 64
#define A_RS   57924    // 64
#define A_TOT  57988    // 231,952 bytes

__global__ void __launch_bounds__(512, 1) swin_attn_kernel(
    const float* __restrict__ x,
    const float* __restrict__ norm_w, const float* __restrict__ norm_b,
    const float* __restrict__ qkv_b,
    const float* __restrict__ proj_b,
    const float* __restrict__ rpb)
{
    extern __shared__ float sm[];
    float* xt    = sm + A_XT;
    float* rpb_s = sm + A_RPB;
    float* mu_s  = sm + A_MU;
    float* rs_s  = sm + A_RS;
    int*   pos   = (int*)(sm + A_POS);
    int*   cls_s = (int*)(sm + A_CLS);

    uu* Xu  = (uu*)(sm + A_XT);
    uu* Qu  = (uu*)(sm + A_Q);
    uu* Ku  = (uu*)(sm + A_K);
    uu* Vtu = (uu*)(sm + A_VT);
    uu* Wu  = (uu*)(sm + A_WU);
    uu* AOu = (uu*)(sm + A_XT);   // AO overlays xt
    float* hout = sm + A_Q;       // hout overlays Q

    const int tid  = threadIdx.x;
    const int lane = tid & 31;
    const int wid  = tid >> 5;
    const int lq   = lane >> 2;
    const int lr   = lane & 3;
    const int mh   = wid >> 2;
    const int nq   = wid & 3;
    const int hh   = wid & 3;
    const int mq   = wid >> 2;
    const int blk  = blockIdx.x;
    const int b    = blk >> 10;
    const int wh   = (blk >> 5) & 31;
    const int ww   = blk & 31;

    if (tid < 64) {
        int i = tid >> 3, j = tid & 7;
        int hs = wh * 8 + i;
        int wsp = ww * 8 + j;
        int r = (hs + 4) & 255;
        int c = (wsp + 4) & 255;
        pos[tid] = r * 256 + c;
        int rr = (hs  < 248) ? 0 : ((hs  < 252) ? 1 : 2);
        int cr = (wsp < 248) ? 0 : ((wsp < 252) ? 1 : 2);
        cls_s[tid] = rr * 3 + cr;
    }
    for (int idx = tid; idx < 900; idx += 512) rpb_s[idx] = __ldg(rpb + idx);
    __syncthreads();                                   // (1)

    const int xbase = b * 96 * 65536;

    // load tokens -> xt[n][perm(c)] fp32
    #pragma unroll
    for (int it = 0; it < 12; it++) {
        int e = tid + it * 512;
        int c = e >> 6, n = e & 63;
        xt[n * 104 + kperm(c)] = __ldg(&x[xbase + (c << 16) + pos[n]]);
    }
    __syncthreads();                                   // (2)

    // LN1 stats (sum over slots == sum over channels)
    {
        int p = tid >> 3, part = tid & 7;
        float s = 0.f, s2 = 0.f;
        #pragma unroll
        for (int i = 0; i < 12; i++) {
            float v = xt[p * 104 + part * 12 + i];
            s += v; s2 += v * v;
        }
        #pragma unroll
        for (int o = 1; o < 8; o <<= 1) {
            s  += __shfl_xor_sync(0xffffffffu, s,  o);
            s2 += __shfl_xor_sync(0xffffffffu, s2, o);
        }
        if (part == 0) {
            float mu = s * (1.f / 96.f);
            float var = s2 * (1.f / 96.f) - mu * mu;
            mu_s[p] = mu;
            rs_s[p] = rsqrtf(var + 1e-6f);
        }
    }
    __syncthreads();                                   // (3)

    // normalize in place -> tf32; stage Wqkv image (pure uint4 copy)
    #pragma unroll
    for (int it = 0; it < 12; it++) {
        int e = tid + it * 512;
        int s = e >> 6, n = e & 63;
        int sl = s & 7;
        int chan = (s & ~7) | ((sl & 1) << 2) | (sl >> 1);   // inverse perm
        float v = (xt[n * 104 + s] - mu_s[n]) * rs_s[n] * __ldg(norm_w + chan)
                  + __ldg(norm_b + chan);
        Xu[n * 104 + s] = tf32c(v);
    }
    {
        uint4* dst = (uint4*)Wu;
        const uint4* src = (const uint4*)g_wqkv;
        for (int i = tid; i < 7488; i += 512) dst[i] = src[i];
    }
    __syncthreads();                                   // (4)

    // ---------------- QKV: warp tile m16 x n72, 12 k-steps ----------------
    {
        float acc[9][4];
        #pragma unroll
        for (int nt = 0; nt < 9; nt++)
            #pragma unroll
            for (int e = 0; e < 4; e++) acc[nt][e] = 0.f;

        #pragma unroll 2
        for (int ks = 0; ks < 12; ks++) {
            int k0 = ks * 8;
            uu af[4];
            lda64(af, Xu + (mh * 16) * 104 + k0, 104, lq, lr);
            #pragma unroll
            for (int nt = 0; nt < 9; nt++) {
                uu b0, b1;
                ldb64(b0, b1, Wu + (nq * 72 + nt * 8 + lq) * 104 + k0 + 2 * lr);
                mma8(acc[nt], af, b0, b1);
            }
        }
        const float scale = 0.2041241452319315f;  // 24^-0.5
        #pragma unroll
        for (int nt = 0; nt < 9; nt++) {
            int j0 = nq * 72 + nt * 8;
            float bl = __ldg(qkv_b + j0 + 2 * lr);
            float bh = __ldg(qkv_b + j0 + 2 * lr + 1);
            #pragma unroll
            for (int e = 0; e < 4; e++) {
                int row = mh * 16 + lq + ((e >> 1) << 3);
                int col = j0 + 2 * lr + (e & 1);
                float v = acc[nt][e] + ((e & 1) ? bh : bl);
                if (col < 96)       Qu[row * 104 + kperm(col)] = tf32c(v * scale);
                else if (col < 192) Ku[row * 104 + kperm(col - 96)] = tf32c(v);
                else                Vtu[(col - 192) * 72 + kperm(row)] = tf32c(v);
            }
        }
    }
    __syncthreads();                                   // (5)

    // stage Wproj image into Wu (visible at barrier (6))
    {
        uint4* dst = (uint4*)Wu;
        const uint4* src = (const uint4*)g_wproj;
        for (int i = tid; i < 2496; i += 512) dst[i] = src[i];
    }

    // ---- Scores (m16 x 64) + bias + mask + softmax + AV, in registers ----
    {
        float acc[8][4];
        #pragma unroll
        for (int nt = 0; nt < 8; nt++)
            #pragma unroll
            for (int e = 0; e < 4; e++) acc[nt][e] = 0.f;

        #pragma unroll
        for (int ks = 0; ks < 3; ks++) {
            int k0 = hh * 24 + ks * 8;
            uu af[4];
            lda64(af, Qu + (mq * 16) * 104 + k0, 104, lq, lr);
            #pragma unroll
            for (int nt = 0; nt < 8; nt++) {
                uu b0, b1;
                ldb64(b0, b1, Ku + (nt * 8 + lq) * 104 + k0 + 2 * lr);
                mma8(acc[nt], af, b0, b1);
            }
        }
        // bias + mask
        int nlo = mq * 16 + lq, nhi = nlo + 8;
        int ilo = nlo >> 3, jlo = nlo & 7, clo = cls_s[nlo];
        int ihi = nhi >> 3, jhi = nhi & 7, chi = cls_s[nhi];
        #pragma unroll
        for (int nt = 0; nt < 8; nt++) {
            #pragma unroll
            for (int e = 0; e < 4; e++) {
                int m = nt * 8 + 2 * lr + (e & 1);
                int mi = m >> 3, mj = m & 7;
                int cm = cls_s[m];
                if (e < 2) {
                    int ridx = (ilo - mi + 7) * 15 + (jlo - mj + 7);
                    acc[nt][e] += rpb_s[ridx * 4 + hh];
                    if (cm != clo) acc[nt][e] -= 100.f;
                } else {
                    int ridx = (ihi - mi + 7) * 15 + (jhi - mj + 7);
                    acc[nt][e] += rpb_s[ridx * 4 + hh];
                    if (cm != chi) acc[nt][e] -= 100.f;
                }
            }
        }
        // softmax per row (reduce over lr lanes: xor 1,2)
        float mx0 = -1e30f, mx1 = -1e30f;
        #pragma unroll
        for (int nt = 0; nt < 8; nt++) {
            mx0 = fmaxf(mx0, fmaxf(acc[nt][0], acc[nt][1]));
            mx1 = fmaxf(mx1, fmaxf(acc[nt][2], acc[nt][3]));
        }
        #pragma unroll
        for (int o = 1; o < 4; o <<= 1) {
            mx0 = fmaxf(mx0, __shfl_xor_sync(0xffffffffu, mx0, o));
            mx1 = fmaxf(mx1, __shfl_xor_sync(0xffffffffu, mx1, o));
        }
        float sm0 = 0.f, sm1 = 0.f;
        #pragma unroll
        for (int nt = 0; nt < 8; nt++) {
            acc[nt][0] = __expf(acc[nt][0] - mx0);
            acc[nt][1] = __expf(acc[nt][1] - mx0);
            acc[nt][2] = __expf(acc[nt][2] - mx1);
            acc[nt][3] = __expf(acc[nt][3] - mx1);
            sm0 += acc[nt][0] + acc[nt][1];
            sm1 += acc[nt][2] + acc[nt][3];
        }
        #pragma unroll
        for (int o = 1; o < 4; o <<= 1) {
            sm0 += __shfl_xor_sync(0xffffffffu, sm0, o);
            sm1 += __shfl_xor_sync(0xffffffffu, sm1, o);
        }
        float inv0 = __fdividef(1.f, sm0);
        float inv1 = __fdividef(1.f, sm1);
        #pragma unroll
        for (int nt = 0; nt < 8; nt++) {
            acc[nt][0] *= inv0; acc[nt][1] *= inv0;
            acc[nt][2] *= inv1; acc[nt][3] *= inv1;
        }

        // AV: P A-frags via quad shuffles; B = Vtu (token-permuted cols)
        float fav[3][4];
        #pragma unroll
        for (int nt = 0; nt < 3; nt++)
            #pragma unroll
            for (int e = 0; e < 4; e++) fav[nt][e] = 0.f;

        #pragma unroll
        for (int ks = 0; ks < 8; ks++) {
            int srcA = (lane & ~3) | (lr >> 1);
            int srcB = srcA + 2;
            float sA0 = __shfl_sync(0xffffffffu, acc[ks][0], srcA);
            float sA1 = __shfl_sync(0xffffffffu, acc[ks][1], srcA);
            float sA2 = __shfl_sync(0xffffffffu, acc[ks][2], srcA);
            float sA3 = __shfl_sync(0xffffffffu, acc[ks][3], srcA);
            float sB0 = __shfl_sync(0xffffffffu, acc[ks][0], srcB);
            float sB1 = __shfl_sync(0xffffffffu, acc[ks][1], srcB);
            float sB2 = __shfl_sync(0xffffffffu, acc[ks][2], srcB);
            float sB3 = __shfl_sync(0xffffffffu, acc[ks][3], srcB);
            bool oddc = (lr & 1);
            uu a[4];
            a[0] = tf32c(oddc ? sA1 : sA0);
            a[1] = tf32c(oddc ? sA3 : sA2);
            a[2] = tf32c(oddc ? sB1 : sB0);
            a[3] = tf32c(oddc ? sB3 : sB2);
            #pragma unroll
            for (int nt = 0; nt < 3; nt++) {
                uu b0, b1;
                ldb64(b0, b1, Vtu + (hh * 24 + nt * 8 + lq) * 72 + ks * 8 + 2 * lr);
                mma8(fav[nt], a, b0, b1);
            }
        }
        // AO -> smem (k-permuted, overlays xt)
        #pragma unroll
        for (int nt = 0; nt < 3; nt++)
            #pragma unroll
            for (int e = 0; e < 4; e++) {
                int n = mq * 16 + lq + ((e >> 1) << 3);
                int c = hh * 24 + nt * 8 + 2 * lr + (e & 1);
                AOu[n * 104 + kperm(c)] = tf32c(fav[nt][e]);
            }
    }
    __syncthreads();                                   // (6)

    // ---------------- Proj (m16 x n24) + residual -> hout ----------------
    {
        float acc[3][4];
        #pragma unroll
        for (int nt = 0; nt < 3; nt++)
            #pragma unroll
            for (int e = 0; e < 4; e++) acc[nt][e] = 0.f;

        #pragma unroll 2
        for (int ks = 0; ks < 12; ks++) {
            int k0 = ks * 8;
            uu af[4];
            lda64(af, AOu + (mh * 16) * 104 + k0, 104, lq, lr);
            #pragma unroll
            for (int nt = 0; nt < 3; nt++) {
                uu b0, b1;
                ldb64(b0, b1, Wu + (nq * 24 + nt * 8 + lq) * 104 + k0 + 2 * lr);
                mma8(acc[nt], af, b0, b1);
            }
        }
        #pragma unroll
        for (int nt = 0; nt < 3; nt++) {
            int j0 = nq * 24 + nt * 8;
            float bl = __ldg(proj_b + j0 + 2 * lr);
            float bh = __ldg(proj_b + j0 + 2 * lr + 1);
            #pragma unroll
            for (int e = 0; e < 4; e++) {
                int n = mh * 16 + lq + ((e >> 1) << 3);
                int j = j0 + 2 * lr + (e & 1);
                float v = acc[nt][e] + ((e & 1) ? bh : bl)
                        + __ldg(&x[xbase + (j << 16) + pos[n]]);
                hout[n * 104 + j] = v;
            }
        }
    }
    __syncthreads();                                   // (7)

    // write h (NHWC), coalesced
    #pragma unroll
    for (int it = 0; it < 12; it++) {
        int e = tid + it * 512;
        int n = e / 96, c = e - (e / 96) * 96;
        g_h[(b * 65536 + pos[n]) * 96 + c] = hout[n * 104 + c];
    }
}

// ---------------- Kernel B smem (word indices) ----------------
#define B_YS   0        // ys [128][104] tf32 k-perm (later yb [128][97] fp32)
#define B_WST  13312    // w1 half [192][100] / w2 half [96][196]
#define B_HCT  32512    // hct [128][196] tf32
#define B_MU   57600    // 128
#define B_RS   57728    // 128
#define B_NW   57856    // 96
#define B_NB   57952    // 96
#define B_TOT  58048    // 232,192 bytes

__global__ void __launch_bounds__(512, 1) swin_mlp_kernel(
    const float* __restrict__ n2w, const float* __restrict__ n2b,
    const float* __restrict__ b1g,
    const float* __restrict__ b2g,
    float* __restrict__ out)
{
    extern __shared__ float sm[];
    float* yb   = sm + B_YS;
    float* mu_s = sm + B_MU;
    float* rs_s = sm + B_RS;
    float* nw_s = sm + B_NW;
    float* nb_s = sm + B_NB;
    uu* Ysu = (uu*)(sm + B_YS);
    uu* Wsu = (uu*)(sm + B_WST);
    uu* Hcu = (uu*)(sm + B_HCT);

    const int tid  = threadIdx.x;
    const int lane = tid & 31;
    const int wid  = tid >> 5;
    const int lq   = lane >> 2;
    const int lr   = lane & 3;
    const int mh   = wid >> 2;
    const int nq   = wid & 3;
    const int P0   = blockIdx.x * 128;
    const int b    = P0 >> 16;
    const int pix0 = P0 & 65535;

    if (tid < 96)      nw_s[tid] = __ldg(n2w + tid);
    else if (tid < 192) nb_s[tid - 96] = __ldg(n2b + tid - 96);

    // LN2 stats straight from g_h
    {
        int p = tid >> 2, part = tid & 3;
        const float4* g4 = (const float4*)(g_h + (size_t)(P0 + p) * 96 + part * 24);
        float s = 0.f, s2 = 0.f;
        #pragma unroll
        for (int i = 0; i < 6; i++) {
            float4 v = g4[i];
            s  += v.x + v.y + v.z + v.w;
            s2 += v.x * v.x + v.y * v.y + v.z * v.z + v.w * v.w;
        }
        #pragma unroll
        for (int o = 1; o < 4; o <<= 1) {
            s  += __shfl_xor_sync(0xffffffffu, s,  o);
            s2 += __shfl_xor_sync(0xffffffffu, s2, o);
        }
        if (part == 0) {
            float mu = s * (1.f / 96.f);
            float var = s2 * (1.f / 96.f) - mu * mu;
            mu_s[p] = mu;
            rs_s[p] = rsqrtf(var + 1e-6f);
        }
    }
    __syncthreads();                                   // (1)

    // normalize -> ys tf32 (k-permuted slots); stage w1 half0 (uint4 copy)
    #pragma unroll
    for (int it = 0; it < 6; it++) {
        int v4 = tid + it * 512;
        int p = v4 / 24, c4 = v4 - (v4 / 24) * 24;
        float4 g = *(const float4*)(g_h + (size_t)(P0 + p) * 96 + c4 * 4);
        float mu = mu_s[p], rs = rs_s[p];
        int c = c4 * 4;
        uu* dst = Ysu + p * 104;
        dst[kperm(c)]     = tf32c((g.x - mu) * rs * nw_s[c]     + nb_s[c]);
        dst[kperm(c + 1)] = tf32c((g.y - mu) * rs * nw_s[c + 1] + nb_s[c + 1]);
        dst[kperm(c + 2)] = tf32c((g.z - mu) * rs * nw_s[c + 2] + nb_s[c + 2]);
        dst[kperm(c + 3)] = tf32c((g.w - mu) * rs * nw_s[c + 3] + nb_s[c + 3]);
    }
    {
        uint4* dst = (uint4*)Wsu;
        const uint4* src = (const uint4*)g_w1;
        for (int i = tid; i < 4800; i += 512) dst[i] = src[i];
    }
    __syncthreads();                                   // (2)

    float acc2[3][2][4];
    #pragma unroll
    for (int nt = 0; nt < 3; nt++)
        #pragma unroll
        for (int mt = 0; mt < 2; mt++)
            #pragma unroll
            for (int e = 0; e < 4; e++) acc2[nt][mt][e] = 0.f;

    for (int half = 0; half < 2; half++) {
        // ---- fc1 half: m32 x n48, 12 ksteps (A lds64 perm, B lds32) ----
        {
            float acc[6][2][4];
            #pragma unroll
            for (int nt = 0; nt < 6; nt++)
                #pragma unroll
                for (int mt = 0; mt < 2; mt++)
                    #pragma unroll
                    for (int e = 0; e < 4; e++) acc[nt][mt][e] = 0.f;

            #pragma unroll 2
            for (int ks = 0; ks < 12; ks++) {
                int k0 = ks * 8;
                uu af[2][4];
                #pragma unroll
                for (int mt = 0; mt < 2; mt++)
                    lda64(af[mt], Ysu + (mh * 32 + mt * 16) * 104 + k0, 104, lq, lr);
                #pragma unroll
                for (int nt = 0; nt < 6; nt++) {
                    const uu* bb = Wsu + (nq * 48 + nt * 8) * 100 + k0;
                    uu b0 = bb[lq * 100 + lr], b1 = bb[lq * 100 + lr + 4];
                    mma8(acc[nt][0], af[0], b0, b1);
                    mma8(acc[nt][1], af[1], b0, b1);
                }
            }
            #pragma unroll
            for (int nt = 0; nt < 6; nt++) {
                int jl = nq * 48 + nt * 8;
                float bl = __ldg(b1g + half * 192 + jl + 2 * lr);
                float bh = __ldg(b1g + half * 192 + jl + 2 * lr + 1);
                #pragma unroll
                for (int mt = 0; mt < 2; mt++)
                    #pragma unroll
                    for (int e = 0; e < 4; e++) {
                        int p = mh * 32 + mt * 16 + lq + ((e >> 1) << 3);
                        int j = jl + 2 * lr + (e & 1);
                        float v = acc[nt][mt][e] + ((e & 1) ? bh : bl);
                        v = 0.5f * v * (1.f + erf_as(v * 0.7071067811865475f));
                        Hcu[p * 196 + j] = tf32c(v);
                    }
            }
        }
        __syncthreads();

        // stage w2 half (uint4 copy)
        {
            uint4* dst = (uint4*)Wsu;
            const uint4* src = (const uint4*)(g_w2 + half * 18816);
            for (int i = tid; i < 4704; i += 512) dst[i] = src[i];
        }
        __syncthreads();

        // ---- fc2 partial: m32 x n24, 24 ksteps ----
        #pragma unroll 2
        for (int ks = 0; ks < 24; ks++) {
            int k0 = ks * 8;
            uu af[2][4];
            #pragma unroll
            for (int mt = 0; mt < 2; mt++)
                lda(af[mt], Hcu + (mh * 32 + mt * 16) * 196 + k0, 196, lq, lr);
            #pragma unroll
            for (int nt = 0; nt < 3; nt++) {
                const uu* bb = Wsu + (nq * 24 + nt * 8) * 196 + k0;
                uu b0 = bb[lq * 196 + lr], b1 = bb[lq * 196 + lr + 4];
                mma8(acc2[nt][0], af[0], b0, b1);
                mma8(acc2[nt][1], af[1], b0, b1);
            }
        }
        __syncthreads();

        if (half == 0) {
            uint4* dst = (uint4*)Wsu;
            const uint4* src = (const uint4*)(g_w1 + 19200);
            for (int i = tid; i < 4800; i += 512) dst[i] = src[i];
            __syncthreads();
        }
    }

    // epilogue: bias + residual -> yb [128][97] (ys dead)
    #pragma unroll
    for (int nt = 0; nt < 3; nt++) {
        int c0 = nq * 24 + nt * 8;
        float bl = __ldg(b2g + c0 + 2 * lr);
        float bh = __ldg(b2g + c0 + 2 * lr + 1);
        #pragma unroll
        for (int mt = 0; mt < 2; mt++)
            #pragma unroll
            for (int e = 0; e < 4; e++) {
                int p = mh * 32 + mt * 16 + lq + ((e >> 1) << 3);
                int c = c0 + 2 * lr + (e & 1);
                float v = acc2[nt][mt][e] + ((e & 1) ? bh : bl)
                        + g_h[(size_t)(P0 + p) * 96 + c];
                yb[p * 97 + c] = v;
            }
    }
    __syncthreads();

    // coalesced NCHW store
    #pragma unroll
    for (int it = 0; it < 24; it++) {
        int e = tid + it * 512;
        int c = e >> 7, p = e & 127;
        out[((size_t)(b * 96 + c) << 16) + (size_t)pix0 + p] = yb[p * 97 + c];
    }
}

extern "C" void kernel_launch(void* const* d_in, const int* in_sizes, int n_in,
                              void* d_out, int out_size)
{
    const float* x      = (const float*)d_in[0];
    const float* norm_w = (const float*)d_in[1];
    const float* norm_b = (const float*)d_in[2];
    const float* qkv_w  = (const float*)d_in[3];
    const float* qkv_b  = (const float*)d_in[4];
    const float* proj_w = (const float*)d_in[5];
    const float* proj_b = (const float*)d_in[6];
    const float* rpb    = (const float*)d_in[7];
    const float* n2w    = (const float*)d_in[8];
    const float* n2b    = (const float*)d_in[9];
    const float* fc1_w  = (const float*)d_in[10];
    const float* fc1_b  = (const float*)d_in[11];
    const float* fc2_w  = (const float*)d_in[12];
    const float* fc2_b  = (const float*)d_in[13];
    float* out = (float*)d_out;

    cudaFuncSetAttribute(swin_attn_kernel, cudaFuncAttributeMaxDynamicSharedMemorySize,
                         A_TOT * 4);
    cudaFuncSetAttribute(swin_mlp_kernel, cudaFuncAttributeMaxDynamicSharedMemorySize,
                         B_TOT * 4);

    swin_prep_kernel<<<112, 256>>>(qkv_w, proj_w, fc1_w, fc2_w);
    swin_attn_kernel<<<4096, 512, A_TOT * 4>>>(
        x, norm_w, norm_b, qkv_b, proj_b, rpb);
    swin_mlp_kernel<<<2048, 512, B_TOT * 4>>>(
        n2w, n2b, fc1_b, fc2_b, out);
}

// round 8
// speedup vs baseline: 3.9623x; 1.0510x over previous
#include <cuda_runtime.h>
#include <math.h>

// ---------------------------------------------------------------------------
// Swin block, B=4 C=96 H=W=256 WS=8 NH=4 HD=24 SHIFT=4 N=64 MLP_H=384
// tf32 mma.sync m16n8k8. 256-thread CTAs, 2 CTAs/SM (launch_bounds(256,2)).
// Weights are NOT staged in smem: prep kernel emits k-permuted tf32 images and
// every mma B-fragment is a single LDG.64 from L2. Activations in smem with
// strides ≡ 8 (mod 32) so A-fragments are conflict-free LDS.64 pairs.
// Kernel A (4096 CTAs, 1 window): LN1 + QKV + scores(bias+mask) + in-register
//   softmax + in-register P->AV + proj + residual -> g_h (NHWC scratch)
// Kernel B (2048 CTAs, 128 px): LN2 + 4x(fc1-quarter+GELU -> fc2-partial)
//   + residual -> NCHW out
// ---------------------------------------------------------------------------

typedef unsigned uu;

__device__ __forceinline__ uu tf32c(float f) {
    uu u; asm("cvt.rna.tf32.f32 %0, %1;" : "=r"(u) : "f"(f)); return u;
}
__device__ __forceinline__ void mma8(float* d, const uu* a, uu b0, uu b1) {
    asm("mma.sync.aligned.m16n8k8.row.col.f32.tf32.tf32.f32 "
        "{%0,%1,%2,%3},{%4,%5,%6,%7},{%8,%9},{%0,%1,%2,%3};"
        : "+f"(d[0]), "+f"(d[1]), "+f"(d[2]), "+f"(d[3])
        : "r"(a[0]), "r"(a[1]), "r"(a[2]), "r"(a[3]), "r"(b0), "r"(b1));
}
__device__ __forceinline__ int kperm(int k) {
    return (k & ~7) | ((k & 3) << 1) | ((k >> 2) & 1);
}
// A fragment (m16k8) from k-permuted smem tile: 2x LDS.64
__device__ __forceinline__ void lda64(uu* a, const uu* base, int stride, int lq, int lr) {
    uint2 v0 = *(const uint2*)(base + lq * stride + 2 * lr);
    uint2 v1 = *(const uint2*)(base + (lq + 8) * stride + 2 * lr);
    a[0] = v0.x; a[2] = v0.y; a[1] = v1.x; a[3] = v1.y;
}
// B fragment (n8k8) from k-permuted global image: 1x LDG.64
__device__ __forceinline__ void ldbg(uu& b0, uu& b1, const uu* p) {
    uint2 v = __ldg((const uint2*)p); b0 = v.x; b1 = v.y;
}

// Abramowitz-Stegun 7.1.26 erf (|abs err| < 1.5e-7)
__device__ __forceinline__ float erf_as(float x) {
    float ax = fabsf(x);
    float t  = __frcp_rn(1.f + 0.3275911f * ax);
    float y  = t * (0.254829592f + t * (-0.284496736f + t * (1.421413741f
             + t * (-1.453152027f + t * 1.061405429f))));
    float r  = 1.f - y * __expf(-ax * ax);
    return copysignf(r, x);
}

// NHWC scratch for h = x + attn_out (100.7 MB)
__device__ float g_h[4 * 256 * 256 * 96];

// tf32 weight images, k-permuted within 8-groups (B-fragment = LDG.64)
__device__ uu g_wqkv[288 * 96];
__device__ uu g_wproj[96 * 96];
__device__ uu g_w1[384 * 96];     // [hidden j][kperm(c)]
__device__ uu g_w2[96 * 384];     // [out c][kperm(j)]

__global__ void swin_prep_kernel(const float* __restrict__ qkv_w,
                                 const float* __restrict__ proj_w,
                                 const float* __restrict__ fc1_w,
                                 const float* __restrict__ fc2_w)
{
    int t = blockIdx.x * blockDim.x + threadIdx.x;
    int T = gridDim.x * blockDim.x;
    for (int i = t; i < 27648; i += T) {
        int r = i / 96, k = i - r * 96;
        g_wqkv[r * 96 + kperm(k)] = tf32c(__ldg(qkv_w + i));
    }
    for (int i = t; i < 9216; i += T) {
        int r = i / 96, k = i - r * 96;
        g_wproj[r * 96 + kperm(k)] = tf32c(__ldg(proj_w + i));
    }
    for (int i = t; i < 36864; i += T) {
        int r = i / 96, k = i - r * 96;
        g_w1[r * 96 + kperm(k)] = tf32c(__ldg(fc1_w + i));
    }
    for (int i = t; i < 36864; i += T) {
        int c = i / 384, j = i - c * 384;
        g_w2[c * 384 + kperm(j)] = tf32c(__ldg(fc2_w + i));
    }
}

// ---------------- Kernel A smem (word indices) ----------------
#define A_XT   0        // X_ln [64][104] tf32 k-perm (later AO)
#define A_Q    6656     // Q    [64][104] tf32 k-perm (later hout fp32)
#define A_K    13312    // K    [64][104] tf32 k-perm
#define A_VT   19968    // V^T  [96][72]  tf32 token-perm
#define A_RPB  26880    // 900
#define A_POS  27780    // 64 int
#define A_CLS  27844    // 64 int
#define A_MU   27908    // 64
#define A_RS   27972    // 64
#define A_TOT  28036    // 112,144 bytes

__global__ void __launch_bounds__(256, 2) swin_attn_kernel(
    const float* __restrict__ x,
    const float* __restrict__ norm_w, const float* __restrict__ norm_b,
    const float* __restrict__ qkv_b,
    const float* __restrict__ proj_b,
    const float* __restrict__ rpb)
{
    extern __shared__ float sm[];
    float* xt    = sm + A_XT;
    float* rpb_s = sm + A_RPB;
    float* mu_s  = sm + A_MU;
    float* rs_s  = sm + A_RS;
    int*   pos   = (int*)(sm + A_POS);
    int*   cls_s = (int*)(sm + A_CLS);

    uu* Xu  = (uu*)(sm + A_XT);
    uu* Qu  = (uu*)(sm + A_Q);
    uu* Ku  = (uu*)(sm + A_K);
    uu* Vtu = (uu*)(sm + A_VT);
    uu* AOu = (uu*)(sm + A_XT);   // AO overlays xt
    float* hout = sm + A_Q;       // hout overlays Q

    const int tid  = threadIdx.x;
    const int lane = tid & 31;
    const int wid  = tid >> 5;            // 0..7
    const int lq   = lane >> 2;
    const int lr   = lane & 3;
    const int mh   = wid >> 2;            // 0..1 (QKV/proj m32 group)
    const int nq   = wid & 3;             // 0..3
    const int hh   = wid & 3;             // scores/AV head
    const int mq   = wid >> 2;            // scores/AV 32-row slice
    const int blk  = blockIdx.x;
    const int b    = blk >> 10;
    const int wh   = (blk >> 5) & 31;
    const int ww   = blk & 31;

    if (tid < 64) {
        int i = tid >> 3, j = tid & 7;
        int hs = wh * 8 + i;
        int wsp = ww * 8 + j;
        int r = (hs + 4) & 255;
        int c = (wsp + 4) & 255;
        pos[tid] = r * 256 + c;
        int rr = (hs  < 248) ? 0 : ((hs  < 252) ? 1 : 2);
        int cr = (wsp < 248) ? 0 : ((wsp < 252) ? 1 : 2);
        cls_s[tid] = rr * 3 + cr;
    }
    for (int idx = tid; idx < 900; idx += 256) rpb_s[idx] = __ldg(rpb + idx);
    __syncthreads();                                   // (1)

    const int xbase = b * 96 * 65536;

    // load tokens -> xt[n][perm(c)] fp32
    #pragma unroll
    for (int it = 0; it < 24; it++) {
        int e = tid + it * 256;
        int c = e >> 6, n = e & 63;
        xt[n * 104 + kperm(c)] = __ldg(&x[xbase + (c << 16) + pos[n]]);
    }
    __syncthreads();                                   // (2)

    // LN1 stats: 4 lanes per token, 24 slots each (order-invariant sums)
    {
        int p = tid >> 2, part = tid & 3;
        const float4* x4 = (const float4*)(xt + p * 104 + part * 24);
        float s = 0.f, s2 = 0.f;
        #pragma unroll
        for (int i = 0; i < 6; i++) {
            float4 v = x4[i];
            s  += v.x + v.y + v.z + v.w;
            s2 += v.x * v.x + v.y * v.y + v.z * v.z + v.w * v.w;
        }
        #pragma unroll
        for (int o = 1; o < 4; o <<= 1) {
            s  += __shfl_xor_sync(0xffffffffu, s,  o);
            s2 += __shfl_xor_sync(0xffffffffu, s2, o);
        }
        if (part == 0) {
            float mu = s * (1.f / 96.f);
            float var = s2 * (1.f / 96.f) - mu * mu;
            mu_s[p] = mu;
            rs_s[p] = rsqrtf(var + 1e-6f);
        }
    }
    __syncthreads();                                   // (3)

    // normalize in place -> tf32 (slot -> channel via inverse perm)
    #pragma unroll
    for (int it = 0; it < 24; it++) {
        int e = tid + it * 256;
        int s = e >> 6, n = e & 63;
        int sl = s & 7;
        int chan = (s & ~7) | ((sl & 1) << 2) | (sl >> 1);
        float v = (xt[n * 104 + s] - mu_s[n]) * rs_s[n] * __ldg(norm_w + chan)
                  + __ldg(norm_b + chan);
        Xu[n * 104 + s] = tf32c(v);
    }
    __syncthreads();                                   // (4)

    // ---------------- QKV: warp tile m32 x n72, 12 k-steps, B from L2 ----
    {
        float acc[9][2][4];
        #pragma unroll
        for (int nt = 0; nt < 9; nt++)
            #pragma unroll
            for (int mt = 0; mt < 2; mt++)
                #pragma unroll
                for (int e = 0; e < 4; e++) acc[nt][mt][e] = 0.f;

        const uu* wb = g_wqkv + (nq * 72 + lq) * 96 + 2 * lr;
        #pragma unroll
        for (int ks = 0; ks < 12; ks++) {
            int k0 = ks * 8;
            uu af[2][4];
            lda64(af[0], Xu + (mh * 32) * 104 + k0, 104, lq, lr);
            lda64(af[1], Xu + (mh * 32 + 16) * 104 + k0, 104, lq, lr);
            #pragma unroll
            for (int nt = 0; nt < 9; nt++) {
                uu b0, b1;
                ldbg(b0, b1, wb + nt * 8 * 96 + k0);
                mma8(acc[nt][0], af[0], b0, b1);
                mma8(acc[nt][1], af[1], b0, b1);
            }
        }
        const float scale = 0.2041241452319315f;  // 24^-0.5
        #pragma unroll
        for (int nt = 0; nt < 9; nt++) {
            int j0 = nq * 72 + nt * 8;
            float bl = __ldg(qkv_b + j0 + 2 * lr);
            float bh = __ldg(qkv_b + j0 + 2 * lr + 1);
            #pragma unroll
            for (int mt = 0; mt < 2; mt++)
                #pragma unroll
                for (int e = 0; e < 4; e++) {
                    int row = mh * 32 + mt * 16 + lq + ((e >> 1) << 3);
                    int col = j0 + 2 * lr + (e & 1);
                    float v = acc[nt][mt][e] + ((e & 1) ? bh : bl);
                    if (col < 96)       Qu[row * 104 + kperm(col)] = tf32c(v * scale);
                    else if (col < 192) Ku[row * 104 + kperm(col - 96)] = tf32c(v);
                    else                Vtu[(col - 192) * 72 + kperm(row)] = tf32c(v);
                }
        }
    }
    __syncthreads();                                   // (5)

    // ---- Scores (m32 x 64) + bias + mask + softmax + AV, in registers ----
    {
        float acc[8][2][4];
        #pragma unroll
        for (int nt = 0; nt < 8; nt++)
            #pragma unroll
            for (int mt = 0; mt < 2; mt++)
                #pragma unroll
                for (int e = 0; e < 4; e++) acc[nt][mt][e] = 0.f;

        #pragma unroll
        for (int ks = 0; ks < 3; ks++) {
            int k0 = hh * 24 + ks * 8;
            uu af[2][4];
            lda64(af[0], Qu + (mq * 32) * 104 + k0, 104, lq, lr);
            lda64(af[1], Qu + (mq * 32 + 16) * 104 + k0, 104, lq, lr);
            #pragma unroll
            for (int nt = 0; nt < 8; nt++) {
                uint2 v = *(const uint2*)(Ku + (nt * 8 + lq) * 104 + k0 + 2 * lr);
                mma8(acc[nt][0], af[0], v.x, v.y);
                mma8(acc[nt][1], af[1], v.x, v.y);
            }
        }
        // bias + mask
        #pragma unroll
        for (int mt = 0; mt < 2; mt++) {
            int nlo = mq * 32 + mt * 16 + lq, nhi = nlo + 8;
            int ilo = nlo >> 3, jlo = nlo & 7, clo = cls_s[nlo];
            int ihi = nhi >> 3, jhi = nhi & 7, chi = cls_s[nhi];
            #pragma unroll
            for (int nt = 0; nt < 8; nt++) {
                #pragma unroll
                for (int e = 0; e < 4; e++) {
                    int m = nt * 8 + 2 * lr + (e & 1);
                    int mi = m >> 3, mj = m & 7;
                    int cm = cls_s[m];
                    if (e < 2) {
                        int ridx = (ilo - mi + 7) * 15 + (jlo - mj + 7);
                        acc[nt][mt][e] += rpb_s[ridx * 4 + hh];
                        if (cm != clo) acc[nt][mt][e] -= 100.f;
                    } else {
                        int ridx = (ihi - mi + 7) * 15 + (jhi - mj + 7);
                        acc[nt][mt][e] += rpb_s[ridx * 4 + hh];
                        if (cm != chi) acc[nt][mt][e] -= 100.f;
                    }
                }
            }
        }
        // softmax per row (reduce over lr lanes) and AV per mt
        float fav[3][2][4];
        #pragma unroll
        for (int nt = 0; nt < 3; nt++)
            #pragma unroll
            for (int mt = 0; mt < 2; mt++)
                #pragma unroll
                for (int e = 0; e < 4; e++) fav[nt][mt][e] = 0.f;

        #pragma unroll
        for (int mt = 0; mt < 2; mt++) {
            float mx0 = -1e30f, mx1 = -1e30f;
            #pragma unroll
            for (int nt = 0; nt < 8; nt++) {
                mx0 = fmaxf(mx0, fmaxf(acc[nt][mt][0], acc[nt][mt][1]));
                mx1 = fmaxf(mx1, fmaxf(acc[nt][mt][2], acc[nt][mt][3]));
            }
            #pragma unroll
            for (int o = 1; o < 4; o <<= 1) {
                mx0 = fmaxf(mx0, __shfl_xor_sync(0xffffffffu, mx0, o));
                mx1 = fmaxf(mx1, __shfl_xor_sync(0xffffffffu, mx1, o));
            }
            float sm0 = 0.f, sm1 = 0.f;
            #pragma unroll
            for (int nt = 0; nt < 8; nt++) {
                acc[nt][mt][0] = __expf(acc[nt][mt][0] - mx0);
                acc[nt][mt][1] = __expf(acc[nt][mt][1] - mx0);
                acc[nt][mt][2] = __expf(acc[nt][mt][2] - mx1);
                acc[nt][mt][3] = __expf(acc[nt][mt][3] - mx1);
                sm0 += acc[nt][mt][0] + acc[nt][mt][1];
                sm1 += acc[nt][mt][2] + acc[nt][mt][3];
            }
            #pragma unroll
            for (int o = 1; o < 4; o <<= 1) {
                sm0 += __shfl_xor_sync(0xffffffffu, sm0, o);
                sm1 += __shfl_xor_sync(0xffffffffu, sm1, o);
            }
            float inv0 = __fdividef(1.f, sm0);
            float inv1 = __fdividef(1.f, sm1);
            #pragma unroll
            for (int nt = 0; nt < 8; nt++) {
                acc[nt][mt][0] *= inv0; acc[nt][mt][1] *= inv0;
                acc[nt][mt][2] *= inv1; acc[nt][mt][3] *= inv1;
            }
            // P -> A-frags via quad shuffles, mma against Vtu
            #pragma unroll
            for (int ks = 0; ks < 8; ks++) {
                int srcA = (lane & ~3) | (lr >> 1);
                int srcB = srcA + 2;
                float sA0 = __shfl_sync(0xffffffffu, acc[ks][mt][0], srcA);
                float sA1 = __shfl_sync(0xffffffffu, acc[ks][mt][1], srcA);
                float sA2 = __shfl_sync(0xffffffffu, acc[ks][mt][2], srcA);
                float sA3 = __shfl_sync(0xffffffffu, acc[ks][mt][3], srcA);
                float sB0 = __shfl_sync(0xffffffffu, acc[ks][mt][0], srcB);
                float sB1 = __shfl_sync(0xffffffffu, acc[ks][mt][1], srcB);
                float sB2 = __shfl_sync(0xffffffffu, acc[ks][mt][2], srcB);
                float sB3 = __shfl_sync(0xffffffffu, acc[ks][mt][3], srcB);
                bool oddc = (lr & 1);
                uu a[4];
                a[0] = tf32c(oddc ? sA1 : sA0);
                a[1] = tf32c(oddc ? sA3 : sA2);
                a[2] = tf32c(oddc ? sB1 : sB0);
                a[3] = tf32c(oddc ? sB3 : sB2);
                #pragma unroll
                for (int nt = 0; nt < 3; nt++) {
                    uint2 v = *(const uint2*)(Vtu + (hh * 24 + nt * 8 + lq) * 72
                                              + ks * 8 + 2 * lr);
                    mma8(fav[nt][mt], a, v.x, v.y);
                }
            }
        }
        __syncthreads();                               // (6) before AO overlays xt
        #pragma unroll
        for (int nt = 0; nt < 3; nt++)
            #pragma unroll
            for (int mt = 0; mt < 2; mt++)
                #pragma unroll
                for (int e = 0; e < 4; e++) {
                    int n = mq * 32 + mt * 16 + lq + ((e >> 1) << 3);
                    int c = hh * 24 + nt * 8 + 2 * lr + (e & 1);
                    AOu[n * 104 + kperm(c)] = tf32c(fav[nt][mt][e]);
                }
    }
    __syncthreads();                                   // (7)

    // ---------------- Proj (m32 x n24) + residual -> hout ----------------
    {
        float acc[3][2][4];
        #pragma unroll
        for (int nt = 0; nt < 3; nt++)
            #pragma unroll
            for (int mt = 0; mt < 2; mt++)
                #pragma unroll
                for (int e = 0; e < 4; e++) acc[nt][mt][e] = 0.f;

        const uu* wb = g_wproj + (nq * 24 + lq) * 96 + 2 * lr;
        #pragma unroll
        for (int ks = 0; ks < 12; ks++) {
            int k0 = ks * 8;
            uu af[2][4];
            lda64(af[0], AOu + (mh * 32) * 104 + k0, 104, lq, lr);
            lda64(af[1], AOu + (mh * 32 + 16) * 104 + k0, 104, lq, lr);
            #pragma unroll
            for (int nt = 0; nt < 3; nt++) {
                uu b0, b1;
                ldbg(b0, b1, wb + nt * 8 * 96 + k0);
                mma8(acc[nt][0], af[0], b0, b1);
                mma8(acc[nt][1], af[1], b0, b1);
            }
        }
        #pragma unroll
        for (int nt = 0; nt < 3; nt++) {
            int j0 = nq * 24 + nt * 8;
            float bl = __ldg(proj_b + j0 + 2 * lr);
            float bh = __ldg(proj_b + j0 + 2 * lr + 1);
            #pragma unroll
            for (int mt = 0; mt < 2; mt++)
                #pragma unroll
                for (int e = 0; e < 4; e++) {
                    int n = mh * 32 + mt * 16 + lq + ((e >> 1) << 3);
                    int j = j0 + 2 * lr + (e & 1);
                    float v = acc[nt][mt][e] + ((e & 1) ? bh : bl)
                            + __ldg(&x[xbase + (j << 16) + pos[n]]);
                    hout[n * 104 + j] = v;
                }
        }
    }
    __syncthreads();                                   // (8)

    // write h (NHWC), coalesced
    #pragma unroll
    for (int it = 0; it < 24; it++) {
        int e = tid + it * 256;
        int n = e / 96, c = e - (e / 96) * 96;
        g_h[(b * 65536 + pos[n]) * 96 + c] = hout[n * 104 + c];
    }
}

// ---------------- Kernel B smem (word indices) ----------------
#define B_YS   0        // ys [128][104] tf32 k-perm (later yb [128][97] fp32)
#define B_HCT  13312    // hct [128][104] tf32 k-perm (one hidden quarter)
#define B_MU   26624    // 128
#define B_RS   26752    // 128
#define B_NW   26880    // 96
#define B_NB   26976    // 96
#define B_TOT  27072    // 108,288 bytes

__global__ void __launch_bounds__(256, 2) swin_mlp_kernel(
    const float* __restrict__ n2w, const float* __restrict__ n2b,
    const float* __restrict__ b1g,
    const float* __restrict__ b2g,
    float* __restrict__ out)
{
    extern __shared__ float sm[];
    float* yb   = sm + B_YS;
    float* mu_s = sm + B_MU;
    float* rs_s = sm + B_RS;
    float* nw_s = sm + B_NW;
    float* nb_s = sm + B_NB;
    uu* Ysu = (uu*)(sm + B_YS);
    uu* Hcu = (uu*)(sm + B_HCT);

    const int tid  = threadIdx.x;
    const int lane = tid & 31;
    const int wid  = tid >> 5;          // 0..7
    const int lq   = lane >> 2;
    const int lr   = lane & 3;
    const int mh   = wid & 3;           // m32 block 0..3 (128 rows)
    const int nqh  = wid >> 2;          // 0..1 (n-half)
    const int P0   = blockIdx.x * 128;
    const int b    = P0 >> 16;
    const int pix0 = P0 & 65535;

    if (tid < 96)       nw_s[tid] = __ldg(n2w + tid);
    else if (tid < 192) nb_s[tid - 96] = __ldg(n2b + tid - 96);

    // LN2 stats from g_h: 2 lanes per token, 48 ch each
    {
        int p = tid >> 1, part = tid & 1;
        const float4* g4 = (const float4*)(g_h + (size_t)(P0 + p) * 96 + part * 48);
        float s = 0.f, s2 = 0.f;
        #pragma unroll
        for (int i = 0; i < 12; i++) {
            float4 v = g4[i];
            s  += v.x + v.y + v.z + v.w;
            s2 += v.x * v.x + v.y * v.y + v.z * v.z + v.w * v.w;
        }
        s  += __shfl_xor_sync(0xffffffffu, s,  1);
        s2 += __shfl_xor_sync(0xffffffffu, s2, 1);
        if (part == 0) {
            float mu = s * (1.f / 96.f);
            float var = s2 * (1.f / 96.f) - mu * mu;
            mu_s[p] = mu;
            rs_s[p] = rsqrtf(var + 1e-6f);
        }
    }
    __syncthreads();                                   // (1)

    // normalize -> ys tf32 (k-permuted slots)
    #pragma unroll
    for (int it = 0; it < 12; it++) {
        int v4 = tid + it * 256;
        int p = v4 / 24, c4 = v4 - (v4 / 24) * 24;
        float4 g = *(const float4*)(g_h + (size_t)(P0 + p) * 96 + c4 * 4);
        float mu = mu_s[p], rs = rs_s[p];
        int c = c4 * 4;
        uu* dst = Ysu + p * 104;
        dst[kperm(c)]     = tf32c((g.x - mu) * rs * nw_s[c]     + nb_s[c]);
        dst[kperm(c + 1)] = tf32c((g.y - mu) * rs * nw_s[c + 1] + nb_s[c + 1]);
        dst[kperm(c + 2)] = tf32c((g.z - mu) * rs * nw_s[c + 2] + nb_s[c + 2]);
        dst[kperm(c + 3)] = tf32c((g.w - mu) * rs * nw_s[c + 3] + nb_s[c + 3]);
    }
    __syncthreads();                                   // (2)

    float acc2[6][2][4];
    #pragma unroll
    for (int nt = 0; nt < 6; nt++)
        #pragma unroll
        for (int mt = 0; mt < 2; mt++)
            #pragma unroll
            for (int e = 0; e < 4; e++) acc2[nt][mt][e] = 0.f;

    for (int ng = 0; ng < 4; ng++) {                   // hidden quarter = 96
        // ---- fc1 quarter: two n24 chunks per warp (m32 x n24 each) ----
        #pragma unroll
        for (int nc = 0; nc < 2; nc++) {
            float acc1[3][2][4];
            #pragma unroll
            for (int nt = 0; nt < 3; nt++)
                #pragma unroll
                for (int mt = 0; mt < 2; mt++)
                    #pragma unroll
                    for (int e = 0; e < 4; e++) acc1[nt][mt][e] = 0.f;

            const int jb = nqh * 48 + nc * 24;             // local hidden base
            const uu* wb = g_w1 + (ng * 96 + jb + lq) * 96 + 2 * lr;
            #pragma unroll
            for (int ks = 0; ks < 12; ks++) {
                int k0 = ks * 8;
                uu af[2][4];
                lda64(af[0], Ysu + (mh * 32) * 104 + k0, 104, lq, lr);
                lda64(af[1], Ysu + (mh * 32 + 16) * 104 + k0, 104, lq, lr);
                #pragma unroll
                for (int nt = 0; nt < 3; nt++) {
                    uu b0, b1;
                    ldbg(b0, b1, wb + nt * 8 * 96 + k0);
                    mma8(acc1[nt][0], af[0], b0, b1);
                    mma8(acc1[nt][1], af[1], b0, b1);
                }
            }
            #pragma unroll
            for (int nt = 0; nt < 3; nt++) {
                int jl = jb + nt * 8;
                float bl = __ldg(b1g + ng * 96 + jl + 2 * lr);
                float bh = __ldg(b1g + ng * 96 + jl + 2 * lr + 1);
                #pragma unroll
                for (int mt = 0; mt < 2; mt++)
                    #pragma unroll
                    for (int e = 0; e < 4; e++) {
                        int p = mh * 32 + mt * 16 + lq + ((e >> 1) << 3);
                        int j = jl + 2 * lr + (e & 1);
                        float v = acc1[nt][mt][e] + ((e & 1) ? bh : bl);
                        v = 0.5f * v * (1.f + erf_as(v * 0.7071067811865475f));
                        Hcu[p * 104 + kperm(j)] = tf32c(v);
                    }
            }
        }
        __syncthreads();                               // hct quarter ready

        // ---- fc2 partial over this quarter: m32 x n48, 12 ksteps ----
        const uu* wb2 = g_w2 + (nqh * 48 + lq) * 384 + ng * 96 + 2 * lr;
        #pragma unroll
        for (int ks = 0; ks < 12; ks++) {
            int k0 = ks * 8;
            uu af[2][4];
            lda64(af[0], Hcu + (mh * 32) * 104 + k0, 104, lq, lr);
            lda64(af[1], Hcu + (mh * 32 + 16) * 104 + k0, 104, lq, lr);
            #pragma unroll
            for (int nt = 0; nt < 6; nt++) {
                uu b0, b1;
                ldbg(b0, b1, wb2 + nt * 8 * 384 + k0);
                mma8(acc2[nt][0], af[0], b0, b1);
                mma8(acc2[nt][1], af[1], b0, b1);
            }
        }
        __syncthreads();                               // before next fc1 overwrite
    }

    // epilogue: bias + residual -> yb [128][97] (ys dead)
    #pragma unroll
    for (int nt = 0; nt < 6; nt++) {
        int c0 = nqh * 48 + nt * 8;
        float bl = __ldg(b2g + c0 + 2 * lr);
        float bh = __ldg(b2g + c0 + 2 * lr + 1);
        #pragma unroll
        for (int mt = 0; mt < 2; mt++)
            #pragma unroll
            for (int e = 0; e < 4; e++) {
                int p = mh * 32 + mt * 16 + lq + ((e >> 1) << 3);
                int c = c0 + 2 * lr + (e & 1);
                float v = acc2[nt][mt][e] + ((e & 1) ? bh : bl)
                        + g_h[(size_t)(P0 + p) * 96 + c];
                yb[p * 97 + c] = v;
            }
    }
    __syncthreads();

    // coalesced NCHW store
    #pragma unroll
    for (int it = 0; it < 48; it++) {
        int e = tid + it * 256;
        int c = e >> 7, p = e & 127;
        out[((size_t)(b * 96 + c) << 16) + (size_t)pix0 + p] = yb[p * 97 + c];
    }
}

extern "C" void kernel_launch(void* const* d_in, const int* in_sizes, int n_in,
                              void* d_out, int out_size)
{
    const float* x      = (const float*)d_in[0];
    const float* norm_w = (const float*)d_in[1];
    const float* norm_b = (const float*)d_in[2];
    const float* qkv_w  = (const float*)d_in[3];
    const float* qkv_b  = (const float*)d_in[4];
    const float* proj_w = (const float*)d_in[5];
    const float* proj_b = (const float*)d_in[6];
    const float* rpb    = (const float*)d_in[7];
    const float* n2w    = (const float*)d_in[8];
    const float* n2b    = (const float*)d_in[9];
    const float* fc1_w  = (const float*)d_in[10];
    const float* fc1_b  = (const float*)d_in[11];
    const float* fc2_w  = (const float*)d_in[12];
    const float* fc2_b  = (const float*)d_in[13];
    float* out = (float*)d_out;

    cudaFuncSetAttribute(swin_attn_kernel, cudaFuncAttributeMaxDynamicSharedMemorySize,
                         A_TOT * 4);
    cudaFuncSetAttribute(swin_mlp_kernel, cudaFuncAttributeMaxDynamicSharedMemorySize,
                         B_TOT * 4);

    swin_prep_kernel<<<112, 256>>>(qkv_w, proj_w, fc1_w, fc2_w);
    swin_attn_kernel<<<4096, 256, A_TOT * 4>>>(
        x, norm_w, norm_b, qkv_b, proj_b, rpb);
    swin_mlp_kernel<<<2048, 256, B_TOT * 4>>>(
        n2w, n2b, fc1_b, fc2_b, out);
}

// round 9
// speedup vs baseline: 5.6127x; 1.4165x over previous
#include <cuda_runtime.h>
#include <cuda_fp16.h>
#include <math.h>

// ---------------------------------------------------------------------------
// Swin block, B=4 C=96 H=W=256 WS=8 NH=4 HD=24 SHIFT=4 N=64 MLP_H=384
// fp16 mma.sync m16n8k16 (fp32 accum) — same 10-bit mantissa as tf32, half
// the mma instructions. 256-thread CTAs, 2 CTAs/SM. Weights pre-converted to
// pair-permuted half images; B-fragments = 1 LDG.64 from L2, A-fragments =
// 2 LDS.64 from conflict-free smem (row strides ≡ 8 or 24 mod 32).
// Attention P->AV needs NO shuffles: score C-fragments pack directly into
// f16 A-fragments.
// ---------------------------------------------------------------------------

typedef unsigned uu;

__device__ __forceinline__ uu packh2(float lo, float hi) {
    __half2 h = __floats2half2_rn(lo, hi);
    return *reinterpret_cast<uu*>(&h);
}
__device__ __forceinline__ void mmaf16(float* d, const uu* a, uu b0, uu b1) {
    asm("mma.sync.aligned.m16n8k16.row.col.f32.f16.f16.f32 "
        "{%0,%1,%2,%3},{%4,%5,%6,%7},{%8,%9},{%0,%1,%2,%3};"
        : "+f"(d[0]), "+f"(d[1]), "+f"(d[2]), "+f"(d[3])
        : "r"(a[0]), "r"(a[1]), "r"(a[2]), "r"(a[3]), "r"(b0), "r"(b1));
}
// pair permutation within 8-groups: pairs (lr, lr+4) become adjacent words
__device__ __forceinline__ int pperm(int p) {
    return (p & ~7) | ((p & 3) << 1) | ((p >> 2) & 1);
}
// A fragment (m16k16 f16) from pair-permuted smem: 2x LDS.64
__device__ __forceinline__ void lda64(uu* a, const uu* base, int stride, int lq, int lr) {
    uint2 v0 = *(const uint2*)(base + lq * stride + 2 * lr);
    uint2 v1 = *(const uint2*)(base + (lq + 8) * stride + 2 * lr);
    a[0] = v0.x; a[2] = v0.y; a[1] = v1.x; a[3] = v1.y;
}
// B fragment (n8k16) from pair-permuted global image: 1x LDG.64
__device__ __forceinline__ void ldbg(uu& b0, uu& b1, const uu* p) {
    uint2 v = __ldg((const uint2*)p); b0 = v.x; b1 = v.y;
}

// Abramowitz-Stegun 7.1.26 erf (|abs err| < 1.5e-7)
__device__ __forceinline__ float erf_as(float x) {
    float ax = fabsf(x);
    float t  = __frcp_rn(1.f + 0.3275911f * ax);
    float y  = t * (0.254829592f + t * (-0.284496736f + t * (1.421413741f
             + t * (-1.453152027f + t * 1.061405429f))));
    float r  = 1.f - y * __expf(-ax * ax);
    return copysignf(r, x);
}

// NHWC scratch for h = x + attn_out (100.7 MB)
__device__ float g_h[4 * 256 * 256 * 96];

// half weight images, channel-pair-permuted (each uu = half2 = 2 channels)
__device__ uu g_wqkv[288 * 48];
__device__ uu g_wproj[96 * 48];
__device__ uu g_w1[384 * 48];     // [hidden j][c-pair perm]
__device__ uu g_w2[96 * 192];     // [out c][j-pair perm]

__global__ void swin_prep_kernel(const float* __restrict__ qkv_w,
                                 const float* __restrict__ proj_w,
                                 const float* __restrict__ fc1_w,
                                 const float* __restrict__ fc2_w)
{
    int t = blockIdx.x * blockDim.x + threadIdx.x;
    int T = gridDim.x * blockDim.x;
    for (int i = t; i < 288 * 48; i += T) {
        int r = i / 48, p = i - r * 48;
        g_wqkv[r * 48 + pperm(p)] =
            packh2(__ldg(qkv_w + r * 96 + 2 * p), __ldg(qkv_w + r * 96 + 2 * p + 1));
    }
    for (int i = t; i < 96 * 48; i += T) {
        int r = i / 48, p = i - r * 48;
        g_wproj[r * 48 + pperm(p)] =
            packh2(__ldg(proj_w + r * 96 + 2 * p), __ldg(proj_w + r * 96 + 2 * p + 1));
    }
    for (int i = t; i < 384 * 48; i += T) {
        int r = i / 48, p = i - r * 48;
        g_w1[r * 48 + pperm(p)] =
            packh2(__ldg(fc1_w + r * 96 + 2 * p), __ldg(fc1_w + r * 96 + 2 * p + 1));
    }
    for (int i = t; i < 96 * 192; i += T) {
        int c = i / 192, p = i - c * 192;
        g_w2[c * 192 + pperm(p)] =
            packh2(__ldg(fc2_w + c * 384 + 2 * p), __ldg(fc2_w + c * 384 + 2 * p + 1));
    }
}

// ---------------- Kernel A smem (word indices) ----------------
#define A_XT   0        // raw x fp32 [64][104] (later AO f16 [64][56])
#define A_XH   6656     // X_ln f16 [64][56]
#define A_Q    10240    // Q f16 [64][72]  (head dim padded 24->32)
#define A_K    14848    // K f16 [64][72]
#define A_VT   19456    // V^T f16 [96][40] (token pairs, permuted)
#define A_HOUT 6656     // hout fp32 [64][104], overlays XH+Q after scores
#define A_RPB  23296    // 900
#define A_POS  24196    // 64 int
#define A_CLS  24260    // 64 int
#define A_MU   24324    // 64
#define A_RS   24388    // 64
#define A_TOT  24452    // 97,808 bytes

__global__ void __launch_bounds__(256, 2) swin_attn_kernel(
    const float* __restrict__ x,
    const float* __restrict__ norm_w, const float* __restrict__ norm_b,
    const float* __restrict__ qkv_b,
    const float* __restrict__ proj_b,
    const float* __restrict__ rpb)
{
    extern __shared__ float sm[];
    float* xt    = sm + A_XT;
    float* rpb_s = sm + A_RPB;
    float* mu_s  = sm + A_MU;
    float* rs_s  = sm + A_RS;
    int*   pos   = (int*)(sm + A_POS);
    int*   cls_s = (int*)(sm + A_CLS);

    uu* Xhu = (uu*)(sm + A_XH);
    uu* Qu  = (uu*)(sm + A_Q);
    uu* Ku  = (uu*)(sm + A_K);
    uu* Vtu = (uu*)(sm + A_VT);
    uu* AOu = (uu*)(sm + A_XT);     // AO overlays raw xt
    float* hout = sm + A_HOUT;      // overlays XH + Q

    const int tid  = threadIdx.x;
    const int lane = tid & 31;
    const int wid  = tid >> 5;            // 0..7
    const int lq   = lane >> 2;
    const int lr   = lane & 3;
    const int mh   = wid >> 2;            // 0..1 (QKV/proj m32 group)
    const int nq   = wid & 3;             // 0..3
    const int hh   = wid & 3;             // scores/AV head
    const int mq   = wid >> 2;            // scores/AV 32-row slice
    const int blk  = blockIdx.x;
    const int b    = blk >> 10;
    const int wh   = (blk >> 5) & 31;
    const int ww   = blk & 31;

    if (tid < 64) {
        int i = tid >> 3, j = tid & 7;
        int hs = wh * 8 + i;
        int wsp = ww * 8 + j;
        int r = (hs + 4) & 255;
        int c = (wsp + 4) & 255;
        pos[tid] = r * 256 + c;
        int rr = (hs  < 248) ? 0 : ((hs  < 252) ? 1 : 2);
        int cr = (wsp < 248) ? 0 : ((wsp < 252) ? 1 : 2);
        cls_s[tid] = rr * 3 + cr;
    }
    for (int idx = tid; idx < 900; idx += 256) rpb_s[idx] = __ldg(rpb + idx);
    // zero Q/K pad slots (head-dim pairs 12..15 -> slots 9,11,13,15 per head)
    for (int i = tid; i < 2048; i += 256) {
        int sl = 9 + 2 * (i & 3);
        int hd = (i >> 2) & 3;
        int r  = (i >> 4) & 63;
        uu* dst = (i & 1024) ? Ku : Qu;
        dst[r * 72 + hd * 16 + sl] = 0;
    }
    __syncthreads();                                   // (1)

    const int xbase = b * 96 * 65536;

    // load tokens -> xt[n][c] fp32 (natural order)
    #pragma unroll
    for (int it = 0; it < 24; it++) {
        int e = tid + it * 256;
        int c = e >> 6, n = e & 63;
        xt[n * 104 + c] = __ldg(&x[xbase + (c << 16) + pos[n]]);
    }
    __syncthreads();                                   // (2)

    // LN1 stats: 4 lanes per token
    {
        int p = tid >> 2, part = tid & 3;
        const float4* x4 = (const float4*)(xt + p * 104 + part * 24);
        float s = 0.f, s2 = 0.f;
        #pragma unroll
        for (int i = 0; i < 6; i++) {
            float4 v = x4[i];
            s  += v.x + v.y + v.z + v.w;
            s2 += v.x * v.x + v.y * v.y + v.z * v.z + v.w * v.w;
        }
        #pragma unroll
        for (int o = 1; o < 4; o <<= 1) {
            s  += __shfl_xor_sync(0xffffffffu, s,  o);
            s2 += __shfl_xor_sync(0xffffffffu, s2, o);
        }
        if (part == 0) {
            float mu = s * (1.f / 96.f);
            float var = s2 * (1.f / 96.f) - mu * mu;
            mu_s[p] = mu;
            rs_s[p] = rsqrtf(var + 1e-6f);
        }
    }
    __syncthreads();                                   // (3)

    // normalize -> Xh f16 pairs (permuted slots)
    #pragma unroll
    for (int it = 0; it < 12; it++) {
        int w = tid + it * 256;                        // 64*48 words
        int n = w / 48, p = w - (w / 48) * 48;
        float2 xv = *(const float2*)(xt + n * 104 + 2 * p);
        float2 nw = __ldg((const float2*)(norm_w) + p);
        float2 nb = __ldg((const float2*)(norm_b) + p);
        float mu = mu_s[n], rs = rs_s[n];
        Xhu[n * 56 + pperm(p)] = packh2((xv.x - mu) * rs * nw.x + nb.x,
                                        (xv.y - mu) * rs * nw.y + nb.y);
    }
    __syncthreads();                                   // (4)

    // ---------------- QKV: warp tile m32 x n72, 6 k16-steps ----------------
    {
        float acc[9][2][4];
        #pragma unroll
        for (int nt = 0; nt < 9; nt++)
            #pragma unroll
            for (int mt = 0; mt < 2; mt++)
                #pragma unroll
                for (int e = 0; e < 4; e++) acc[nt][mt][e] = 0.f;

        const uu* wb = g_wqkv + (nq * 72 + lq) * 48 + 2 * lr;
        #pragma unroll
        for (int ks = 0; ks < 6; ks++) {
            int k0 = ks * 8;
            uu af[2][4];
            lda64(af[0], Xhu + (mh * 32) * 56 + k0, 56, lq, lr);
            lda64(af[1], Xhu + (mh * 32 + 16) * 56 + k0, 56, lq, lr);
            #pragma unroll
            for (int nt = 0; nt < 9; nt++) {
                uu b0, b1;
                ldbg(b0, b1, wb + nt * 8 * 48 + k0);
                mmaf16(acc[nt][0], af[0], b0, b1);
                mmaf16(acc[nt][1], af[1], b0, b1);
            }
        }
        const float scale = 0.2041241452319315f;  // 24^-0.5
        #pragma unroll
        for (int nt = 0; nt < 9; nt++) {
            int j0 = nq * 72 + nt * 8;
            float bl = __ldg(qkv_b + j0 + 2 * lr);
            float bh = __ldg(qkv_b + j0 + 2 * lr + 1);
            #pragma unroll
            for (int mt = 0; mt < 2; mt++) {
                int row = mh * 32 + mt * 16 + lq;
                int col = j0 + 2 * lr;
                float v0 = acc[nt][mt][0] + bl;
                float v1 = acc[nt][mt][1] + bh;
                float v2 = acc[nt][mt][2] + bl;
                float v3 = acc[nt][mt][3] + bh;
                if (col < 96) {
                    int head = col / 24;
                    int chp  = (col - head * 24) >> 1;
                    int ps   = head * 16 + pperm(chp);
                    Qu[row * 72 + ps]       = packh2(v0 * scale, v1 * scale);
                    Qu[(row + 8) * 72 + ps] = packh2(v2 * scale, v3 * scale);
                } else if (col < 192) {
                    int kc   = col - 96;
                    int head = kc / 24;
                    int chp  = (kc - head * 24) >> 1;
                    int ps   = head * 16 + pperm(chp);
                    Ku[row * 72 + ps]       = packh2(v0, v1);
                    Ku[(row + 8) * 72 + ps] = packh2(v2, v3);
                } else {
                    int cc = col - 192;
                    #pragma unroll
                    for (int e = 0; e < 4; e++) {
                        float v = (e == 0) ? v0 : (e == 1) ? v1 : (e == 2) ? v2 : v3;
                        int n = row + ((e >> 1) << 3);
                        int c2 = cc + (e & 1);
                        int tp = n >> 1;
                        int sl = pperm(tp & 7) | (tp & ~7);
                        ((__half*)(Vtu + c2 * 40 + sl))[n & 1] = __float2half_rn(v);
                    }
                }
            }
        }
    }
    __syncthreads();                                   // (5)

    // ---- Scores (m32 x 64, head-dim padded 32) + bias + mask + softmax + AV ----
    {
        float acc[8][2][4];
        #pragma unroll
        for (int nt = 0; nt < 8; nt++)
            #pragma unroll
            for (int mt = 0; mt < 2; mt++)
                #pragma unroll
                for (int e = 0; e < 4; e++) acc[nt][mt][e] = 0.f;

        #pragma unroll
        for (int ks = 0; ks < 2; ks++) {
            int k0 = hh * 16 + ks * 8;
            uu af[2][4];
            lda64(af[0], Qu + (mq * 32) * 72 + k0, 72, lq, lr);
            lda64(af[1], Qu + (mq * 32 + 16) * 72 + k0, 72, lq, lr);
            #pragma unroll
            for (int nt = 0; nt < 8; nt++) {
                uint2 v = *(const uint2*)(Ku + (nt * 8 + lq) * 72 + k0 + 2 * lr);
                mmaf16(acc[nt][0], af[0], v.x, v.y);
                mmaf16(acc[nt][1], af[1], v.x, v.y);
            }
        }
        // bias + mask
        #pragma unroll
        for (int mt = 0; mt < 2; mt++) {
            int nlo = mq * 32 + mt * 16 + lq, nhi = nlo + 8;
            int ilo = nlo >> 3, jlo = nlo & 7, clo = cls_s[nlo];
            int ihi = nhi >> 3, jhi = nhi & 7, chi = cls_s[nhi];
            #pragma unroll
            for (int nt = 0; nt < 8; nt++) {
                #pragma unroll
                for (int e = 0; e < 4; e++) {
                    int m = nt * 8 + 2 * lr + (e & 1);
                    int mi = m >> 3, mj = m & 7;
                    int cm = cls_s[m];
                    if (e < 2) {
                        int ridx = (ilo - mi + 7) * 15 + (jlo - mj + 7);
                        acc[nt][mt][e] += rpb_s[ridx * 4 + hh];
                        if (cm != clo) acc[nt][mt][e] -= 100.f;
                    } else {
                        int ridx = (ihi - mi + 7) * 15 + (jhi - mj + 7);
                        acc[nt][mt][e] += rpb_s[ridx * 4 + hh];
                        if (cm != chi) acc[nt][mt][e] -= 100.f;
                    }
                }
            }
        }
        // NOTE: f16 C layout: e0,e1 = row lq cols 2lr,2lr+1; e2,e3 = row lq+8
        float fav[3][2][4];
        #pragma unroll
        for (int nt = 0; nt < 3; nt++)
            #pragma unroll
            for (int mt = 0; mt < 2; mt++)
                #pragma unroll
                for (int e = 0; e < 4; e++) fav[nt][mt][e] = 0.f;

        #pragma unroll
        for (int mt = 0; mt < 2; mt++) {
            float mx0 = -1e30f, mx1 = -1e30f;
            #pragma unroll
            for (int nt = 0; nt < 8; nt++) {
                mx0 = fmaxf(mx0, fmaxf(acc[nt][mt][0], acc[nt][mt][1]));
                mx1 = fmaxf(mx1, fmaxf(acc[nt][mt][2], acc[nt][mt][3]));
            }
            #pragma unroll
            for (int o = 1; o < 4; o <<= 1) {
                mx0 = fmaxf(mx0, __shfl_xor_sync(0xffffffffu, mx0, o));
                mx1 = fmaxf(mx1, __shfl_xor_sync(0xffffffffu, mx1, o));
            }
            float sm0 = 0.f, sm1 = 0.f;
            #pragma unroll
            for (int nt = 0; nt < 8; nt++) {
                acc[nt][mt][0] = __expf(acc[nt][mt][0] - mx0);
                acc[nt][mt][1] = __expf(acc[nt][mt][1] - mx0);
                acc[nt][mt][2] = __expf(acc[nt][mt][2] - mx1);
                acc[nt][mt][3] = __expf(acc[nt][mt][3] - mx1);
                sm0 += acc[nt][mt][0] + acc[nt][mt][1];
                sm1 += acc[nt][mt][2] + acc[nt][mt][3];
            }
            #pragma unroll
            for (int o = 1; o < 4; o <<= 1) {
                sm0 += __shfl_xor_sync(0xffffffffu, sm0, o);
                sm1 += __shfl_xor_sync(0xffffffffu, sm1, o);
            }
            float inv0 = __fdividef(1.f, sm0);
            float inv1 = __fdividef(1.f, sm1);
            // AV: pack P directly into A-fragments (no shuffles!)
            #pragma unroll
            for (int ks = 0; ks < 4; ks++) {
                uu a[4];
                a[0] = packh2(acc[2 * ks][mt][0] * inv0,     acc[2 * ks][mt][1] * inv0);
                a[1] = packh2(acc[2 * ks][mt][2] * inv1,     acc[2 * ks][mt][3] * inv1);
                a[2] = packh2(acc[2 * ks + 1][mt][0] * inv0, acc[2 * ks + 1][mt][1] * inv0);
                a[3] = packh2(acc[2 * ks + 1][mt][2] * inv1, acc[2 * ks + 1][mt][3] * inv1);
                #pragma unroll
                for (int nt = 0; nt < 3; nt++) {
                    uint2 v = *(const uint2*)(Vtu + (hh * 24 + nt * 8 + lq) * 40
                                              + ks * 8 + 2 * lr);
                    mmaf16(fav[nt][mt], a, v.x, v.y);
                }
            }
        }
        // AO -> smem f16 (overlays raw xt; raw xt dead since normalize)
        #pragma unroll
        for (int nt = 0; nt < 3; nt++)
            #pragma unroll
            for (int mt = 0; mt < 2; mt++) {
                int n0 = mq * 32 + mt * 16 + lq;
                int cp = hh * 12 + nt * 4 + lr;     // channel pair index
                AOu[n0 * 56 + pperm(cp)]       = packh2(fav[nt][mt][0], fav[nt][mt][1]);
                AOu[(n0 + 8) * 56 + pperm(cp)] = packh2(fav[nt][mt][2], fav[nt][mt][3]);
            }
    }
    __syncthreads();                                   // (6)

    // ---------------- Proj (m32 x n24, 6 k-steps) + residual -> hout ------
    {
        float acc[3][2][4];
        #pragma unroll
        for (int nt = 0; nt < 3; nt++)
            #pragma unroll
            for (int mt = 0; mt < 2; mt++)
                #pragma unroll
                for (int e = 0; e < 4; e++) acc[nt][mt][e] = 0.f;

        const uu* wb = g_wproj + (nq * 24 + lq) * 48 + 2 * lr;
        #pragma unroll
        for (int ks = 0; ks < 6; ks++) {
            int k0 = ks * 8;
            uu af[2][4];
            lda64(af[0], AOu + (mh * 32) * 56 + k0, 56, lq, lr);
            lda64(af[1], AOu + (mh * 32 + 16) * 56 + k0, 56, lq, lr);
            #pragma unroll
            for (int nt = 0; nt < 3; nt++) {
                uu b0, b1;
                ldbg(b0, b1, wb + nt * 8 * 48 + k0);
                mmaf16(acc[nt][0], af[0], b0, b1);
                mmaf16(acc[nt][1], af[1], b0, b1);
            }
        }
        #pragma unroll
        for (int nt = 0; nt < 3; nt++) {
            int j0 = nq * 24 + nt * 8;
            float bl = __ldg(proj_b + j0 + 2 * lr);
            float bh = __ldg(proj_b + j0 + 2 * lr + 1);
            #pragma unroll
            for (int mt = 0; mt < 2; mt++)
                #pragma unroll
                for (int e = 0; e < 4; e++) {
                    int n = mh * 32 + mt * 16 + lq + ((e >> 1) << 3);
                    int j = j0 + 2 * lr + (e & 1);
                    float v = acc[nt][mt][e] + ((e & 1) ? bh : bl)
                            + __ldg(&x[xbase + (j << 16) + pos[n]]);
                    hout[n * 104 + j] = v;
                }
        }
    }
    __syncthreads();                                   // (7)

    // write h (NHWC), coalesced
    #pragma unroll
    for (int it = 0; it < 24; it++) {
        int e = tid + it * 256;
        int n = e / 96, c = e - (e / 96) * 96;
        g_h[(b * 65536 + pos[n]) * 96 + c] = hout[n * 104 + c];
    }
}

// ---------------- Kernel B smem (word indices) ----------------
#define B_YS   0        // ys f16 [128][56] (later yb fp32 [128][97])
#define B_HCT  7168     // hct f16 [128][56] (one hidden quarter)
#define B_MU   14336    // 128
#define B_RS   14464    // 128
#define B_NW   14592    // 96
#define B_NB   14688    // 96
#define B_TOT  14784    // 59,136 bytes

__global__ void __launch_bounds__(256, 2) swin_mlp_kernel(
    const float* __restrict__ n2w, const float* __restrict__ n2b,
    const float* __restrict__ b1g,
    const float* __restrict__ b2g,
    float* __restrict__ out)
{
    extern __shared__ float sm[];
    float* yb   = sm + B_YS;
    float* mu_s = sm + B_MU;
    float* rs_s = sm + B_RS;
    float* nw_s = sm + B_NW;
    float* nb_s = sm + B_NB;
    uu* Ysu = (uu*)(sm + B_YS);
    uu* Hcu = (uu*)(sm + B_HCT);

    const int tid  = threadIdx.x;
    const int lane = tid & 31;
    const int wid  = tid >> 5;          // 0..7
    const int lq   = lane >> 2;
    const int lr   = lane & 3;
    const int mh   = wid & 3;           // m32 block 0..3 (128 rows)
    const int nqh  = wid >> 2;          // 0..1 (n-half)
    const int P0   = blockIdx.x * 128;
    const int b    = P0 >> 16;
    const int pix0 = P0 & 65535;

    if (tid < 96)       nw_s[tid] = __ldg(n2w + tid);
    else if (tid < 192) nb_s[tid - 96] = __ldg(n2b + tid - 96);

    // LN2 stats from g_h: 2 lanes per token, 48 ch each
    {
        int p = tid >> 1, part = tid & 1;
        const float4* g4 = (const float4*)(g_h + (size_t)(P0 + p) * 96 + part * 48);
        float s = 0.f, s2 = 0.f;
        #pragma unroll
        for (int i = 0; i < 12; i++) {
            float4 v = g4[i];
            s  += v.x + v.y + v.z + v.w;
            s2 += v.x * v.x + v.y * v.y + v.z * v.z + v.w * v.w;
        }
        s  += __shfl_xor_sync(0xffffffffu, s,  1);
        s2 += __shfl_xor_sync(0xffffffffu, s2, 1);
        if (part == 0) {
            float mu = s * (1.f / 96.f);
            float var = s2 * (1.f / 96.f) - mu * mu;
            mu_s[p] = mu;
            rs_s[p] = rsqrtf(var + 1e-6f);
        }
    }
    __syncthreads();                                   // (1)

    // normalize -> ys f16 pairs (permuted slots)
    #pragma unroll
    for (int it = 0; it < 24; it++) {
        int w = tid + it * 256;                        // 128*48 words
        int p = w / 48, pl = w - (w / 48) * 48;
        float2 g = *(const float2*)(g_h + (size_t)(P0 + p) * 96 + 2 * pl);
        float mu = mu_s[p], rs = rs_s[p];
        float2 nw = *(const float2*)(nw_s + 2 * pl);
        float2 nb = *(const float2*)(nb_s + 2 * pl);
        Ysu[p * 56 + pperm(pl)] = packh2((g.x - mu) * rs * nw.x + nb.x,
                                         (g.y - mu) * rs * nw.y + nb.y);
    }
    __syncthreads();                                   // (2)

    float acc2[6][2][4];
    #pragma unroll
    for (int nt = 0; nt < 6; nt++)
        #pragma unroll
        for (int mt = 0; mt < 2; mt++)
            #pragma unroll
            for (int e = 0; e < 4; e++) acc2[nt][mt][e] = 0.f;

    for (int ng = 0; ng < 4; ng++) {                   // hidden quarter = 96
        // ---- fc1 quarter: two n24 chunks per warp, 6 k-steps ----
        #pragma unroll
        for (int nc = 0; nc < 2; nc++) {
            float acc1[3][2][4];
            #pragma unroll
            for (int nt = 0; nt < 3; nt++)
                #pragma unroll
                for (int mt = 0; mt < 2; mt++)
                    #pragma unroll
                    for (int e = 0; e < 4; e++) acc1[nt][mt][e] = 0.f;

            const int jb = nqh * 48 + nc * 24;
            const uu* wb = g_w1 + (ng * 96 + jb + lq) * 48 + 2 * lr;
            #pragma unroll
            for (int ks = 0; ks < 6; ks++) {
                int k0 = ks * 8;
                uu af[2][4];
                lda64(af[0], Ysu + (mh * 32) * 56 + k0, 56, lq, lr);
                lda64(af[1], Ysu + (mh * 32 + 16) * 56 + k0, 56, lq, lr);
                #pragma unroll
                for (int nt = 0; nt < 3; nt++) {
                    uu b0, b1;
                    ldbg(b0, b1, wb + nt * 8 * 48 + k0);
                    mmaf16(acc1[nt][0], af[0], b0, b1);
                    mmaf16(acc1[nt][1], af[1], b0, b1);
                }
            }
            #pragma unroll
            for (int nt = 0; nt < 3; nt++) {
                int jl = jb + nt * 8;
                float bl = __ldg(b1g + ng * 96 + jl + 2 * lr);
                float bh = __ldg(b1g + ng * 96 + jl + 2 * lr + 1);
                int pl = (jl >> 1) + lr;               // hidden pair index
                #pragma unroll
                for (int mt = 0; mt < 2; mt++) {
                    int p0r = mh * 32 + mt * 16 + lq;
                    float v0 = acc1[nt][mt][0] + bl;
                    float v1 = acc1[nt][mt][1] + bh;
                    float v2 = acc1[nt][mt][2] + bl;
                    float v3 = acc1[nt][mt][3] + bh;
                    v0 = 0.5f * v0 * (1.f + erf_as(v0 * 0.7071067811865475f));
                    v1 = 0.5f * v1 * (1.f + erf_as(v1 * 0.7071067811865475f));
                    v2 = 0.5f * v2 * (1.f + erf_as(v2 * 0.7071067811865475f));
                    v3 = 0.5f * v3 * (1.f + erf_as(v3 * 0.7071067811865475f));
                    Hcu[p0r * 56 + pperm(pl)]       = packh2(v0, v1);
                    Hcu[(p0r + 8) * 56 + pperm(pl)] = packh2(v2, v3);
                }
            }
        }
        __syncthreads();                               // hct quarter ready

        // ---- fc2 partial over this quarter: m32 x n48, 6 k-steps ----
        const uu* wb2 = g_w2 + (nqh * 48 + lq) * 192 + ng * 48 + 2 * lr;
        #pragma unroll
        for (int ks = 0; ks < 6; ks++) {
            int k0 = ks * 8;
            uu af[2][4];
            lda64(af[0], Hcu + (mh * 32) * 56 + k0, 56, lq, lr);
            lda64(af[1], Hcu + (mh * 32 + 16) * 56 + k0, 56, lq, lr);
            #pragma unroll
            for (int nt = 0; nt < 6; nt++) {
                uu b0, b1;
                ldbg(b0, b1, wb2 + nt * 8 * 192 + k0);
                mmaf16(acc2[nt][0], af[0], b0, b1);
                mmaf16(acc2[nt][1], af[1], b0, b1);
            }
        }
        __syncthreads();                               // before next quarter
    }

    // epilogue: bias + residual -> yb [128][97] (ys/hct dead)
    #pragma unroll
    for (int nt = 0; nt < 6; nt++) {
        int c0 = nqh * 48 + nt * 8;
        float bl = __ldg(b2g + c0 + 2 * lr);
        float bh = __ldg(b2g + c0 + 2 * lr + 1);
        #pragma unroll
        for (int mt = 0; mt < 2; mt++)
            #pragma unroll
            for (int e = 0; e < 4; e++) {
                int p = mh * 32 + mt * 16 + lq + ((e >> 1) << 3);
                int c = c0 + 2 * lr + (e & 1);
                float v = acc2[nt][mt][e] + ((e & 1) ? bh : bl)
                        + g_h[(size_t)(P0 + p) * 96 + c];
                yb[p * 97 + c] = v;
            }
    }
    __syncthreads();

    // coalesced NCHW store
    #pragma unroll
    for (int it = 0; it < 48; it++) {
        int e = tid + it * 256;
        int c = e >> 7, p = e & 127;
        out[((size_t)(b * 96 + c) << 16) + (size_t)pix0 + p] = yb[p * 97 + c];
    }
}

extern "C" void kernel_launch(void* const* d_in, const int* in_sizes, int n_in,
                              void* d_out, int out_size)
{
    const float* x      = (const float*)d_in[0];
    const float* norm_w = (const float*)d_in[1];
    const float* norm_b = (const float*)d_in[2];
    const float* qkv_w  = (const float*)d_in[3];
    const float* qkv_b  = (const float*)d_in[4];
    const float* proj_w = (const float*)d_in[5];
    const float* proj_b = (const float*)d_in[6];
    const float* rpb    = (const float*)d_in[7];
    const float* n2w    = (const float*)d_in[8];
    const float* n2b    = (const float*)d_in[9];
    const float* fc1_w  = (const float*)d_in[10];
    const float* fc1_b  = (const float*)d_in[11];
    const float* fc2_w  = (const float*)d_in[12];
    const float* fc2_b  = (const float*)d_in[13];
    float* out = (float*)d_out;

    cudaFuncSetAttribute(swin_attn_kernel, cudaFuncAttributeMaxDynamicSharedMemorySize,
                         A_TOT * 4);
    cudaFuncSetAttribute(swin_mlp_kernel, cudaFuncAttributeMaxDynamicSharedMemorySize,
                         B_TOT * 4);

    swin_prep_kernel<<<112, 256>>>(qkv_w, proj_w, fc1_w, fc2_w);
    swin_attn_kernel<<<4096, 256, A_TOT * 4>>>(
        x, norm_w, norm_b, qkv_b, proj_b, rpb);
    swin_mlp_kernel<<<2048, 256, B_TOT * 4>>>(
        n2w, n2b, fc1_b, fc2_b, out);
}

// round 10
// speedup vs baseline: 5.7979x; 1.0330x over previous
#include <cuda_runtime.h>
#include <cuda_fp16.h>
#include <math.h>

// ---------------------------------------------------------------------------
// Swin block, B=4 C=96 H=W=256 WS=8 NH=4 HD=24 SHIFT=4 N=64 MLP_H=384
// fp16 mma.sync m16n8k16 (fp32 accum), 256-thread CTAs, 2 CTAs/SM.
// Prep kernel emits: pair-permuted half weight images (B-frag = 1 LDG.64),
// scale-folded qkv bias, and a precomputed bias+mask table
// g_sbias[variant][head][n][m] (4 edge-class variants) so the attention
// scores need ZERO mask/bias ALU — accumulators are initialized from it.
// ---------------------------------------------------------------------------

typedef unsigned uu;

__device__ __forceinline__ uu packh2(float lo, float hi) {
    __half2 h = __floats2half2_rn(lo, hi);
    return *reinterpret_cast<uu*>(&h);
}
__device__ __forceinline__ void mmaf16(float* d, const uu* a, uu b0, uu b1) {
    asm("mma.sync.aligned.m16n8k16.row.col.f32.f16.f16.f32 "
        "{%0,%1,%2,%3},{%4,%5,%6,%7},{%8,%9},{%0,%1,%2,%3};"
        : "+f"(d[0]), "+f"(d[1]), "+f"(d[2]), "+f"(d[3])
        : "r"(a[0]), "r"(a[1]), "r"(a[2]), "r"(a[3]), "r"(b0), "r"(b1));
}
// pair permutation within 8-groups: pairs (lr, lr+4) become adjacent words
__device__ __forceinline__ int pperm(int p) {
    return (p & ~7) | ((p & 3) << 1) | ((p >> 2) & 1);
}
// A fragment (m16k16 f16) from pair-permuted smem: 2x LDS.64
__device__ __forceinline__ void lda64(uu* a, const uu* base, int stride, int lq, int lr) {
    uint2 v0 = *(const uint2*)(base + lq * stride + 2 * lr);
    uint2 v1 = *(const uint2*)(base + (lq + 8) * stride + 2 * lr);
    a[0] = v0.x; a[2] = v0.y; a[1] = v1.x; a[3] = v1.y;
}
// B fragment (n8k16) from pair-permuted global image: 1x LDG.64
__device__ __forceinline__ void ldbg(uu& b0, uu& b1, const uu* p) {
    uint2 v = __ldg((const uint2*)p); b0 = v.x; b1 = v.y;
}

// Abramowitz-Stegun 7.1.26 erf (|abs err| < 1.5e-7)
__device__ __forceinline__ float erf_as(float x) {
    float ax = fabsf(x);
    float t  = __frcp_rn(1.f + 0.3275911f * ax);
    float y  = t * (0.254829592f + t * (-0.284496736f + t * (1.421413741f
             + t * (-1.453152027f + t * 1.061405429f))));
    float r  = 1.f - y * __expf(-ax * ax);
    return copysignf(r, x);
}

// NHWC scratch for h = x + attn_out (100.7 MB)
__device__ float g_h[4 * 256 * 256 * 96];

// half weight images, channel-pair-permuted (each uu = half2 = 2 channels)
__device__ uu g_wqkv[288 * 48];   // q-rows (0..95) pre-scaled by 24^-0.5
__device__ uu g_wproj[96 * 48];
__device__ uu g_w1[384 * 48];     // [hidden j][c-pair perm]
__device__ uu g_w2[96 * 192];     // [out c][j-pair perm]
__device__ float g_bqkv[288];     // qkv bias, q part pre-scaled
// bias+mask table: [variant][head][n][m], variant = (wh==31)*2 + (ww==31)
__device__ float g_sbias[4 * 4 * 64 * 64];

__global__ void swin_prep_kernel(const float* __restrict__ qkv_w,
                                 const float* __restrict__ proj_w,
                                 const float* __restrict__ fc1_w,
                                 const float* __restrict__ fc2_w,
                                 const float* __restrict__ qkv_b,
                                 const float* __restrict__ rpb)
{
    const float scale = 0.2041241452319315f;  // 24^-0.5
    int t = blockIdx.x * blockDim.x + threadIdx.x;
    int T = gridDim.x * blockDim.x;
    for (int i = t; i < 288 * 48; i += T) {
        int r = i / 48, p = i - r * 48;
        float s = (r < 96) ? scale : 1.f;
        g_wqkv[r * 48 + pperm(p)] =
            packh2(__ldg(qkv_w + r * 96 + 2 * p) * s,
                   __ldg(qkv_w + r * 96 + 2 * p + 1) * s);
    }
    for (int i = t; i < 288; i += T)
        g_bqkv[i] = __ldg(qkv_b + i) * ((i < 96) ? scale : 1.f);
    for (int i = t; i < 96 * 48; i += T) {
        int r = i / 48, p = i - r * 48;
        g_wproj[r * 48 + pperm(p)] =
            packh2(__ldg(proj_w + r * 96 + 2 * p), __ldg(proj_w + r * 96 + 2 * p + 1));
    }
    for (int i = t; i < 384 * 48; i += T) {
        int r = i / 48, p = i - r * 48;
        g_w1[r * 48 + pperm(p)] =
            packh2(__ldg(fc1_w + r * 96 + 2 * p), __ldg(fc1_w + r * 96 + 2 * p + 1));
    }
    for (int i = t; i < 96 * 192; i += T) {
        int c = i / 192, p = i - c * 192;
        g_w2[c * 192 + pperm(p)] =
            packh2(__ldg(fc2_w + c * 384 + 2 * p), __ldg(fc2_w + c * 384 + 2 * p + 1));
    }
    // bias+mask table
    for (int i = t; i < 4 * 4 * 64 * 64; i += T) {
        int m  = i & 63;
        int n  = (i >> 6) & 63;
        int h  = (i >> 12) & 3;
        int v  = (i >> 14) & 3;
        int i1 = n >> 3, j1 = n & 7;
        int i2 = m >> 3, j2 = m & 7;
        int ridx = (i1 - i2 + 7) * 15 + (j1 - j2 + 7);
        float bias = __ldg(rpb + ridx * 4 + h);
        int rn = (v & 2) ? ((i1 < 4) ? 1 : 2) : 0;
        int cn = (v & 1) ? ((j1 < 4) ? 1 : 2) : 0;
        int rm = (v & 2) ? ((i2 < 4) ? 1 : 2) : 0;
        int cm = (v & 1) ? ((j2 < 4) ? 1 : 2) : 0;
        if ((rn * 3 + cn) != (rm * 3 + cm)) bias -= 100.f;
        g_sbias[i] = bias;
    }
}

// ---------------- Kernel A smem (word indices) ----------------
#define A_XT   0        // raw x fp32 [64][104]   (alive until proj residual)
#define A_XH   6656     // X_ln f16 [64][56]      (dead after QKV -> AO overlays)
#define A_Q    10240    // Q f16 [64][72]  (head dim padded 24->32)
#define A_K    14848    // K f16 [64][72]
#define A_VT   19456    // V^T f16 [96][40] (token pairs, permuted)
#define A_HOUT 10240    // hout fp32 [64][104], overlays Q..K after scores
#define A_POS  23296    // 64 int
#define A_MU   23360    // 64
#define A_RS   23424    // 64
#define A_TOT  23488    // 93,952 bytes

__global__ void __launch_bounds__(256, 2) swin_attn_kernel(
    const float* __restrict__ x,
    const float* __restrict__ norm_w, const float* __restrict__ norm_b,
    const float* __restrict__ proj_b)
{
    extern __shared__ float sm[];
    float* xt    = sm + A_XT;
    float* mu_s  = sm + A_MU;
    float* rs_s  = sm + A_RS;
    int*   pos   = (int*)(sm + A_POS);

    uu* Xhu = (uu*)(sm + A_XH);
    uu* Qu  = (uu*)(sm + A_Q);
    uu* Ku  = (uu*)(sm + A_K);
    uu* Vtu = (uu*)(sm + A_VT);
    uu* AOu = (uu*)(sm + A_XH);     // AO overlays Xh (both f16 [64][56])
    float* hout = sm + A_HOUT;      // overlays Q+K

    const int tid  = threadIdx.x;
    const int lane = tid & 31;
    const int wid  = tid >> 5;            // 0..7
    const int lq   = lane >> 2;
    const int lr   = lane & 3;
    const int mh   = wid >> 2;            // 0..1 (QKV/proj m32 group)
    const int nq   = wid & 3;             // 0..3
    const int hh   = wid & 3;             // scores/AV head
    const int mq   = wid >> 2;            // scores/AV 32-row slice
    const int blk  = blockIdx.x;
    const int b    = blk >> 10;
    const int wh   = (blk >> 5) & 31;
    const int ww   = blk & 31;
    const int variant = ((wh == 31) ? 2 : 0) | ((ww == 31) ? 1 : 0);

    if (tid < 64) {
        int i = tid >> 3, j = tid & 7;
        int hs = wh * 8 + i;
        int wsp = ww * 8 + j;
        int r = (hs + 4) & 255;
        int c = (wsp + 4) & 255;
        pos[tid] = r * 256 + c;
    }
    // zero Q/K pad slots (head-dim pairs 12..15 -> slots 9,11,13,15 per head)
    for (int i = tid; i < 2048; i += 256) {
        int sl = 9 + 2 * (i & 3);
        int hd = (i >> 2) & 3;
        int r  = (i >> 4) & 63;
        uu* dst = (i & 1024) ? Ku : Qu;
        dst[r * 72 + hd * 16 + sl] = 0;
    }
    __syncthreads();                                   // (1)

    const int xbase = b * 96 * 65536;

    // load tokens -> xt[n][c] fp32 (natural order; kept for residual)
    #pragma unroll
    for (int it = 0; it < 24; it++) {
        int e = tid + it * 256;
        int c = e >> 6, n = e & 63;
        xt[n * 104 + c] = __ldg(&x[xbase + (c << 16) + pos[n]]);
    }
    __syncthreads();                                   // (2)

    // LN1 stats: 4 lanes per token
    {
        int p = tid >> 2, part = tid & 3;
        const float4* x4 = (const float4*)(xt + p * 104 + part * 24);
        float s = 0.f, s2 = 0.f;
        #pragma unroll
        for (int i = 0; i < 6; i++) {
            float4 v = x4[i];
            s  += v.x + v.y + v.z + v.w;
            s2 += v.x * v.x + v.y * v.y + v.z * v.z + v.w * v.w;
        }
        #pragma unroll
        for (int o = 1; o < 4; o <<= 1) {
            s  += __shfl_xor_sync(0xffffffffu, s,  o);
            s2 += __shfl_xor_sync(0xffffffffu, s2, o);
        }
        if (part == 0) {
            float mu = s * (1.f / 96.f);
            float var = s2 * (1.f / 96.f) - mu * mu;
            mu_s[p] = mu;
            rs_s[p] = rsqrtf(var + 1e-6f);
        }
    }
    __syncthreads();                                   // (3)

    // normalize -> Xh f16 pairs (permuted slots)
    #pragma unroll
    for (int it = 0; it < 12; it++) {
        int w = tid + it * 256;                        // 64*48 words
        int n = w / 48, p = w - (w / 48) * 48;
        float2 xv = *(const float2*)(xt + n * 104 + 2 * p);
        float2 nw = __ldg((const float2*)(norm_w) + p);
        float2 nb = __ldg((const float2*)(norm_b) + p);
        float mu = mu_s[n], rs = rs_s[n];
        Xhu[n * 56 + pperm(p)] = packh2((xv.x - mu) * rs * nw.x + nb.x,
                                        (xv.y - mu) * rs * nw.y + nb.y);
    }
    __syncthreads();                                   // (4)

    // ---------------- QKV: warp tile m32 x n72, 6 k16-steps ----------------
    {
        float acc[9][2][4];
        #pragma unroll
        for (int nt = 0; nt < 9; nt++)
            #pragma unroll
            for (int mt = 0; mt < 2; mt++)
                #pragma unroll
                for (int e = 0; e < 4; e++) acc[nt][mt][e] = 0.f;

        const uu* wb = g_wqkv + (nq * 72 + lq) * 48 + 2 * lr;
        #pragma unroll
        for (int ks = 0; ks < 6; ks++) {
            int k0 = ks * 8;
            uu af[2][4];
            lda64(af[0], Xhu + (mh * 32) * 56 + k0, 56, lq, lr);
            lda64(af[1], Xhu + (mh * 32 + 16) * 56 + k0, 56, lq, lr);
            #pragma unroll
            for (int nt = 0; nt < 9; nt++) {
                uu b0, b1;
                ldbg(b0, b1, wb + nt * 8 * 48 + k0);
                mmaf16(acc[nt][0], af[0], b0, b1);
                mmaf16(acc[nt][1], af[1], b0, b1);
            }
        }
        #pragma unroll
        for (int nt = 0; nt < 9; nt++) {
            int j0 = nq * 72 + nt * 8;
            float bl = __ldg(g_bqkv + j0 + 2 * lr);
            float bh = __ldg(g_bqkv + j0 + 2 * lr + 1);
            #pragma unroll
            for (int mt = 0; mt < 2; mt++) {
                int row = mh * 32 + mt * 16 + lq;
                int col = j0 + 2 * lr;
                float v0 = acc[nt][mt][0] + bl;
                float v1 = acc[nt][mt][1] + bh;
                float v2 = acc[nt][mt][2] + bl;
                float v3 = acc[nt][mt][3] + bh;
                if (col < 96) {
                    int head = col / 24;
                    int chp  = (col - head * 24) >> 1;
                    int ps   = head * 16 + pperm(chp);
                    Qu[row * 72 + ps]       = packh2(v0, v1);
                    Qu[(row + 8) * 72 + ps] = packh2(v2, v3);
                } else if (col < 192) {
                    int kc   = col - 96;
                    int head = kc / 24;
                    int chp  = (kc - head * 24) >> 1;
                    int ps   = head * 16 + pperm(chp);
                    Ku[row * 72 + ps]       = packh2(v0, v1);
                    Ku[(row + 8) * 72 + ps] = packh2(v2, v3);
                } else {
                    int cc = col - 192;
                    #pragma unroll
                    for (int e = 0; e < 4; e++) {
                        float v = (e == 0) ? v0 : (e == 1) ? v1 : (e == 2) ? v2 : v3;
                        int n = row + ((e >> 1) << 3);
                        int c2 = cc + (e & 1);
                        int tp = n >> 1;
                        int sl = pperm(tp & 7) | (tp & ~7);
                        ((__half*)(Vtu + c2 * 40 + sl))[n & 1] = __float2half_rn(v);
                    }
                }
            }
        }
    }
    __syncthreads();                                   // (5)

    // ---- Scores (m32 x 64) with acc INITIALIZED from g_sbias, softmax, AV ----
    {
        float acc[8][2][4];
        const float* bb = g_sbias + (((variant * 4 + hh) * 64 + mq * 32 + lq) * 64)
                        + 2 * lr;
        #pragma unroll
        for (int nt = 0; nt < 8; nt++)
            #pragma unroll
            for (int mt = 0; mt < 2; mt++) {
                float2 lo = __ldg((const float2*)(bb + (mt * 16) * 64 + nt * 8));
                float2 hi = __ldg((const float2*)(bb + (mt * 16 + 8) * 64 + nt * 8));
                acc[nt][mt][0] = lo.x; acc[nt][mt][1] = lo.y;
                acc[nt][mt][2] = hi.x; acc[nt][mt][3] = hi.y;
            }

        #pragma unroll
        for (int ks = 0; ks < 2; ks++) {
            int k0 = hh * 16 + ks * 8;
            uu af[2][4];
            lda64(af[0], Qu + (mq * 32) * 72 + k0, 72, lq, lr);
            lda64(af[1], Qu + (mq * 32 + 16) * 72 + k0, 72, lq, lr);
            #pragma unroll
            for (int nt = 0; nt < 8; nt++) {
                uint2 v = *(const uint2*)(Ku + (nt * 8 + lq) * 72 + k0 + 2 * lr);
                mmaf16(acc[nt][0], af[0], v.x, v.y);
                mmaf16(acc[nt][1], af[1], v.x, v.y);
            }
        }
        // softmax + AV  (f16 C layout: e0,e1 = row lq; e2,e3 = row lq+8)
        float fav[3][2][4];
        #pragma unroll
        for (int nt = 0; nt < 3; nt++)
            #pragma unroll
            for (int mt = 0; mt < 2; mt++)
                #pragma unroll
                for (int e = 0; e < 4; e++) fav[nt][mt][e] = 0.f;

        #pragma unroll
        for (int mt = 0; mt < 2; mt++) {
            float mx0 = -1e30f, mx1 = -1e30f;
            #pragma unroll
            for (int nt = 0; nt < 8; nt++) {
                mx0 = fmaxf(mx0, fmaxf(acc[nt][mt][0], acc[nt][mt][1]));
                mx1 = fmaxf(mx1, fmaxf(acc[nt][mt][2], acc[nt][mt][3]));
            }
            #pragma unroll
            for (int o = 1; o < 4; o <<= 1) {
                mx0 = fmaxf(mx0, __shfl_xor_sync(0xffffffffu, mx0, o));
                mx1 = fmaxf(mx1, __shfl_xor_sync(0xffffffffu, mx1, o));
            }
            float sm0 = 0.f, sm1 = 0.f;
            #pragma unroll
            for (int nt = 0; nt < 8; nt++) {
                acc[nt][mt][0] = __expf(acc[nt][mt][0] - mx0);
                acc[nt][mt][1] = __expf(acc[nt][mt][1] - mx0);
                acc[nt][mt][2] = __expf(acc[nt][mt][2] - mx1);
                acc[nt][mt][3] = __expf(acc[nt][mt][3] - mx1);
                sm0 += acc[nt][mt][0] + acc[nt][mt][1];
                sm1 += acc[nt][mt][2] + acc[nt][mt][3];
            }
            #pragma unroll
            for (int o = 1; o < 4; o <<= 1) {
                sm0 += __shfl_xor_sync(0xffffffffu, sm0, o);
                sm1 += __shfl_xor_sync(0xffffffffu, sm1, o);
            }
            float inv0 = __fdividef(1.f, sm0);
            float inv1 = __fdividef(1.f, sm1);
            // AV: pack P directly into A-fragments (no shuffles)
            #pragma unroll
            for (int ks = 0; ks < 4; ks++) {
                uu a[4];
                a[0] = packh2(acc[2 * ks][mt][0] * inv0,     acc[2 * ks][mt][1] * inv0);
                a[1] = packh2(acc[2 * ks][mt][2] * inv1,     acc[2 * ks][mt][3] * inv1);
                a[2] = packh2(acc[2 * ks + 1][mt][0] * inv0, acc[2 * ks + 1][mt][1] * inv0);
                a[3] = packh2(acc[2 * ks + 1][mt][2] * inv1, acc[2 * ks + 1][mt][3] * inv1);
                #pragma unroll
                for (int nt = 0; nt < 3; nt++) {
                    uint2 v = *(const uint2*)(Vtu + (hh * 24 + nt * 8 + lq) * 40
                                              + ks * 8 + 2 * lr);
                    mmaf16(fav[nt][mt], a, v.x, v.y);
                }
            }
        }
        __syncthreads();                               // (6) Xh dead -> AO overlay
        #pragma unroll
        for (int nt = 0; nt < 3; nt++)
            #pragma unroll
            for (int mt = 0; mt < 2; mt++) {
                int n0 = mq * 32 + mt * 16 + lq;
                int cp = hh * 12 + nt * 4 + lr;     // channel pair index
                AOu[n0 * 56 + pperm(cp)]       = packh2(fav[nt][mt][0], fav[nt][mt][1]);
                AOu[(n0 + 8) * 56 + pperm(cp)] = packh2(fav[nt][mt][2], fav[nt][mt][3]);
            }
    }
    __syncthreads();                                   // (7)

    // ---------------- Proj (m32 x n24, 6 k-steps) + residual -> hout ------
    {
        float acc[3][2][4];
        #pragma unroll
        for (int nt = 0; nt < 3; nt++)
            #pragma unroll
            for (int mt = 0; mt < 2; mt++)
                #pragma unroll
                for (int e = 0; e < 4; e++) acc[nt][mt][e] = 0.f;

        const uu* wb = g_wproj + (nq * 24 + lq) * 48 + 2 * lr;
        #pragma unroll
        for (int ks = 0; ks < 6; ks++) {
            int k0 = ks * 8;
            uu af[2][4];
            lda64(af[0], AOu + (mh * 32) * 56 + k0, 56, lq, lr);
            lda64(af[1], AOu + (mh * 32 + 16) * 56 + k0, 56, lq, lr);
            #pragma unroll
            for (int nt = 0; nt < 3; nt++) {
                uu b0, b1;
                ldbg(b0, b1, wb + nt * 8 * 48 + k0);
                mmaf16(acc[nt][0], af[0], b0, b1);
                mmaf16(acc[nt][1], af[1], b0, b1);
            }
        }
        #pragma unroll
        for (int nt = 0; nt < 3; nt++) {
            int j0 = nq * 24 + nt * 8;
            float bl = __ldg(proj_b + j0 + 2 * lr);
            float bh = __ldg(proj_b + j0 + 2 * lr + 1);
            #pragma unroll
            for (int mt = 0; mt < 2; mt++)
                #pragma unroll
                for (int e = 0; e < 4; e++) {
                    int n = mh * 32 + mt * 16 + lq + ((e >> 1) << 3);
                    int j = j0 + 2 * lr + (e & 1);
                    float v = acc[nt][mt][e] + ((e & 1) ? bh : bl)
                            + xt[n * 104 + j];       // residual from smem
                    hout[n * 104 + j] = v;
                }
        }
    }
    __syncthreads();                                   // (8)

    // write h (NHWC), coalesced
    #pragma unroll
    for (int it = 0; it < 24; it++) {
        int e = tid + it * 256;
        int n = e / 96, c = e - (e / 96) * 96;
        g_h[(b * 65536 + pos[n]) * 96 + c] = hout[n * 104 + c];
    }
}

// ---------------- Kernel B smem (word indices) ----------------
#define B_YS   0        // ys f16 [128][56]
#define B_HCT  7168     // hct f16 [128][56] (one hidden quarter)
#define B_XS   14336    // raw h fp32 [128][100] (residual)
#define B_NW   27136    // 96
#define B_NB   27232    // 96
#define B_TOT  27328    // 109,312 bytes  (yb fp32 [128][97] overlays ys+hct)

__global__ void __launch_bounds__(256, 2) swin_mlp_kernel(
    const float* __restrict__ n2w, const float* __restrict__ n2b,
    const float* __restrict__ b1g,
    const float* __restrict__ b2g,
    float* __restrict__ out)
{
    extern __shared__ float sm[];
    float* yb   = sm + B_YS;     // epilogue bounce, overlays ys+hct
    float* xs   = sm + B_XS;
    float* nw_s = sm + B_NW;
    float* nb_s = sm + B_NB;
    uu* Ysu = (uu*)(sm + B_YS);
    uu* Hcu = (uu*)(sm + B_HCT);

    const int tid  = threadIdx.x;
    const int lane = tid & 31;
    const int wid  = tid >> 5;          // 0..7
    const int lq   = lane >> 2;
    const int lr   = lane & 3;
    const int mh   = wid & 3;           // m32 block 0..3 (128 rows)
    const int nqh  = wid >> 2;          // 0..1 (n-half)
    const int P0   = blockIdx.x * 128;
    const int b    = P0 >> 16;
    const int pix0 = P0 & 65535;

    if (tid < 96)       nw_s[tid] = __ldg(n2w + tid);
    else if (tid < 192) nb_s[tid - 96] = __ldg(n2b + tid - 96);
    __syncthreads();                                   // (1)

    // Single-pass LN2: each lane owns 48 channels of one token in registers
    {
        int p = tid >> 1, part = tid & 1;
        const float4* g4 = (const float4*)(g_h + (size_t)(P0 + p) * 96 + part * 48);
        float4 g[12];
        float s = 0.f, s2 = 0.f;
        #pragma unroll
        for (int i = 0; i < 12; i++) {
            g[i] = g4[i];
            s  += g[i].x + g[i].y + g[i].z + g[i].w;
            s2 += g[i].x * g[i].x + g[i].y * g[i].y + g[i].z * g[i].z + g[i].w * g[i].w;
        }
        s  += __shfl_xor_sync(0xffffffffu, s,  1);
        s2 += __shfl_xor_sync(0xffffffffu, s2, 1);
        float mu = s * (1.f / 96.f);
        float var = s2 * (1.f / 96.f) - mu * mu;
        float rs = rsqrtf(var + 1e-6f);
        // raw -> xs (for residual)
        float* xr = xs + p * 100 + part * 48;
        #pragma unroll
        for (int i = 0; i < 12; i++) *(float4*)(xr + 4 * i) = g[i];
        // normalized -> ys f16 pairs
        #pragma unroll
        for (int i = 0; i < 12; i++) {
            int c = part * 48 + 4 * i;
            int pl = c >> 1;
            Ysu[p * 56 + pperm(pl)]     = packh2((g[i].x - mu) * rs * nw_s[c]     + nb_s[c],
                                                 (g[i].y - mu) * rs * nw_s[c + 1] + nb_s[c + 1]);
            Ysu[p * 56 + pperm(pl + 1)] = packh2((g[i].z - mu) * rs * nw_s[c + 2] + nb_s[c + 2],
                                                 (g[i].w - mu) * rs * nw_s[c + 3] + nb_s[c + 3]);
        }
    }
    __syncthreads();                                   // (2)

    float acc2[6][2][4];
    #pragma unroll
    for (int nt = 0; nt < 6; nt++)
        #pragma unroll
        for (int mt = 0; mt < 2; mt++)
            #pragma unroll
            for (int e = 0; e < 4; e++) acc2[nt][mt][e] = 0.f;

    for (int ng = 0; ng < 4; ng++) {                   // hidden quarter = 96
        // ---- fc1 quarter: two n24 chunks per warp, 6 k-steps ----
        #pragma unroll
        for (int nc = 0; nc < 2; nc++) {
            float acc1[3][2][4];
            #pragma unroll
            for (int nt = 0; nt < 3; nt++)
                #pragma unroll
                for (int mt = 0; mt < 2; mt++)
                    #pragma unroll
                    for (int e = 0; e < 4; e++) acc1[nt][mt][e] = 0.f;

            const int jb = nqh * 48 + nc * 24;
            const uu* wb = g_w1 + (ng * 96 + jb + lq) * 48 + 2 * lr;
            #pragma unroll
            for (int ks = 0; ks < 6; ks++) {
                int k0 = ks * 8;
                uu af[2][4];
                lda64(af[0], Ysu + (mh * 32) * 56 + k0, 56, lq, lr);
                lda64(af[1], Ysu + (mh * 32 + 16) * 56 + k0, 56, lq, lr);
                #pragma unroll
                for (int nt = 0; nt < 3; nt++) {
                    uu b0, b1;
                    ldbg(b0, b1, wb + nt * 8 * 48 + k0);
                    mmaf16(acc1[nt][0], af[0], b0, b1);
                    mmaf16(acc1[nt][1], af[1], b0, b1);
                }
            }
            #pragma unroll
            for (int nt = 0; nt < 3; nt++) {
                int jl = jb + nt * 8;
                float bl = __ldg(b1g + ng * 96 + jl + 2 * lr);
                float bh = __ldg(b1g + ng * 96 + jl + 2 * lr + 1);
                int pl = (jl >> 1) + lr;               // hidden pair index
                #pragma unroll
                for (int mt = 0; mt < 2; mt++) {
                    int p0r = mh * 32 + mt * 16 + lq;
                    float v0 = acc1[nt][mt][0] + bl;
                    float v1 = acc1[nt][mt][1] + bh;
                    float v2 = acc1[nt][mt][2] + bl;
                    float v3 = acc1[nt][mt][3] + bh;
                    v0 = 0.5f * v0 * (1.f + erf_as(v0 * 0.7071067811865475f));
                    v1 = 0.5f * v1 * (1.f + erf_as(v1 * 0.7071067811865475f));
                    v2 = 0.5f * v2 * (1.f + erf_as(v2 * 0.7071067811865475f));
                    v3 = 0.5f * v3 * (1.f + erf_as(v3 * 0.7071067811865475f));
                    Hcu[p0r * 56 + pperm(pl)]       = packh2(v0, v1);
                    Hcu[(p0r + 8) * 56 + pperm(pl)] = packh2(v2, v3);
                }
            }
        }
        __syncthreads();                               // hct quarter ready

        // ---- fc2 partial over this quarter: m32 x n48, 6 k-steps ----
        const uu* wb2 = g_w2 + (nqh * 48 + lq) * 192 + ng * 48 + 2 * lr;
        #pragma unroll
        for (int ks = 0; ks < 6; ks++) {
            int k0 = ks * 8;
            uu af[2][4];
            lda64(af[0], Hcu + (mh * 32) * 56 + k0, 56, lq, lr);
            lda64(af[1], Hcu + (mh * 32 + 16) * 56 + k0, 56, lq, lr);
            #pragma unroll
            for (int nt = 0; nt < 6; nt++) {
                uu b0, b1;
                ldbg(b0, b1, wb2 + nt * 8 * 192 + k0);
                mmaf16(acc2[nt][0], af[0], b0, b1);
                mmaf16(acc2[nt][1], af[1], b0, b1);
            }
        }
        __syncthreads();                               // before next quarter
    }

    // epilogue: bias + residual (from xs, LDS) -> yb [128][97]
    #pragma unroll
    for (int nt = 0; nt < 6; nt++) {
        int c0 = nqh * 48 + nt * 8;
        float bl = __ldg(b2g + c0 + 2 * lr);
        float bh = __ldg(b2g + c0 + 2 * lr + 1);
        #pragma unroll
        for (int mt = 0; mt < 2; mt++)
            #pragma unroll
            for (int e = 0; e < 4; e++) {
                int p = mh * 32 + mt * 16 + lq + ((e >> 1) << 3);
                int c = c0 + 2 * lr + (e & 1);
                float v = acc2[nt][mt][e] + ((e & 1) ? bh : bl)
                        + xs[p * 100 + c];
                yb[p * 97 + c] = v;
            }
    }
    __syncthreads();

    // coalesced NCHW store
    #pragma unroll
    for (int it = 0; it < 48; it++) {
        int e = tid + it * 256;
        int c = e >> 7, p = e & 127;
        out[((size_t)(b * 96 + c) << 16) + (size_t)pix0 + p] = yb[p * 97 + c];
    }
}

extern "C" void kernel_launch(void* const* d_in, const int* in_sizes, int n_in,
                              void* d_out, int out_size)
{
    const float* x      = (const float*)d_in[0];
    const float* norm_w = (const float*)d_in[1];
    const float* norm_b = (const float*)d_in[2];
    const float* qkv_w  = (const float*)d_in[3];
    const float* qkv_b  = (const float*)d_in[4];
    const float* proj_w = (const float*)d_in[5];
    const float* proj_b = (const float*)d_in[6];
    const float* rpb    = (const float*)d_in[7];
    const float* n2w    = (const float*)d_in[8];
    const float* n2b    = (const float*)d_in[9];
    const float* fc1_w  = (const float*)d_in[10];
    const float* fc1_b  = (const float*)d_in[11];
    const float* fc2_w  = (const float*)d_in[12];
    const float* fc2_b  = (const float*)d_in[13];
    float* out = (float*)d_out;

    cudaFuncSetAttribute(swin_attn_kernel, cudaFuncAttributeMaxDynamicSharedMemorySize,
                         A_TOT * 4);
    cudaFuncSetAttribute(swin_mlp_kernel, cudaFuncAttributeMaxDynamicSharedMemorySize,
                         B_TOT * 4);

    swin_prep_kernel<<<112, 256>>>(qkv_w, proj_w, fc1_w, fc2_w, qkv_b, rpb);
    swin_attn_kernel<<<4096, 256, A_TOT * 4>>>(x, norm_w, norm_b, proj_b);
    swin_mlp_kernel<<<2048, 256, B_TOT * 4>>>(n2w, n2b, fc1_b, fc2_b, out);
}

// round 11
// speedup vs baseline: 8.2827x; 1.4286x over previous
#include <cuda_runtime.h>
#include <cuda_fp16.h>
#include <math.h>

// ---------------------------------------------------------------------------
// Swin block, B=4 C=96 H=W=256 WS=8 NH=4 HD=24 SHIFT=4 N=64 MLP_H=384
// SINGLE fused kernel per window: LN1 + QKV + scores(bias-table) + softmax
// + AV + proj + residual + LN2 + fc1/GELU + fc2 + residual -> out (NCHW).
// fp16 mma.sync m16n8k16 (fp32 accum), 256-thread CTAs, 2 CTAs/SM.
// No global scratch: h lives in smem. Weights are pair-permuted half images
// (B-frag = 1 LDG.64 from L2); activations in conflict-free smem (A-frag =
// 2 LDS.64). Bias+mask folded into a 4-variant precomputed score-init table.
// ---------------------------------------------------------------------------

typedef unsigned uu;

__device__ __forceinline__ uu packh2(float lo, float hi) {
    __half2 h = __floats2half2_rn(lo, hi);
    return *reinterpret_cast<uu*>(&h);
}
__device__ __forceinline__ void mmaf16(float* d, const uu* a, uu b0, uu b1) {
    asm("mma.sync.aligned.m16n8k16.row.col.f32.f16.f16.f32 "
        "{%0,%1,%2,%3},{%4,%5,%6,%7},{%8,%9},{%0,%1,%2,%3};"
        : "+f"(d[0]), "+f"(d[1]), "+f"(d[2]), "+f"(d[3])
        : "r"(a[0]), "r"(a[1]), "r"(a[2]), "r"(a[3]), "r"(b0), "r"(b1));
}
// pair permutation within 8-groups: pairs (lr, lr+4) become adjacent words
__device__ __forceinline__ int pperm(int p) {
    return (p & ~7) | ((p & 3) << 1) | ((p >> 2) & 1);
}
// A fragment (m16k16 f16) from pair-permuted smem: 2x LDS.64
__device__ __forceinline__ void lda64(uu* a, const uu* base, int stride, int lq, int lr) {
    uint2 v0 = *(const uint2*)(base + lq * stride + 2 * lr);
    uint2 v1 = *(const uint2*)(base + (lq + 8) * stride + 2 * lr);
    a[0] = v0.x; a[2] = v0.y; a[1] = v1.x; a[3] = v1.y;
}
// B fragment (n8k16) from pair-permuted global image: 1x LDG.64
__device__ __forceinline__ void ldbg(uu& b0, uu& b1, const uu* p) {
    uint2 v = __ldg((const uint2*)p); b0 = v.x; b1 = v.y;
}

// Abramowitz-Stegun 7.1.26 erf (|abs err| < 1.5e-7)
__device__ __forceinline__ float erf_as(float x) {
    float ax = fabsf(x);
    float t  = __frcp_rn(1.f + 0.3275911f * ax);
    float y  = t * (0.254829592f + t * (-0.284496736f + t * (1.421413741f
             + t * (-1.453152027f + t * 1.061405429f))));
    float r  = 1.f - y * __expf(-ax * ax);
    return copysignf(r, x);
}

// half weight images, channel-pair-permuted (each uu = half2 = 2 channels)
__device__ uu g_wqkv[288 * 48];   // q-rows (0..95) pre-scaled by 24^-0.5
__device__ uu g_wproj[96 * 48];
__device__ uu g_w1[384 * 48];     // [hidden j][c-pair perm]
__device__ uu g_w2[96 * 192];     // [out c][j-pair perm]
__device__ float g_bqkv[288];     // qkv bias, q part pre-scaled
// bias+mask table: [variant][head][n][m], variant = (wh==31)*2 + (ww==31)
__device__ float g_sbias[4 * 4 * 64 * 64];

__global__ void swin_prep_kernel(const float* __restrict__ qkv_w,
                                 const float* __restrict__ proj_w,
                                 const float* __restrict__ fc1_w,
                                 const float* __restrict__ fc2_w,
                                 const float* __restrict__ qkv_b,
                                 const float* __restrict__ rpb)
{
    const float scale = 0.2041241452319315f;  // 24^-0.5
    int t = blockIdx.x * blockDim.x + threadIdx.x;
    int T = gridDim.x * blockDim.x;
    for (int i = t; i < 288 * 48; i += T) {
        int r = i / 48, p = i - r * 48;
        float s = (r < 96) ? scale : 1.f;
        g_wqkv[r * 48 + pperm(p)] =
            packh2(__ldg(qkv_w + r * 96 + 2 * p) * s,
                   __ldg(qkv_w + r * 96 + 2 * p + 1) * s);
    }
    for (int i = t; i < 288; i += T)
        g_bqkv[i] = __ldg(qkv_b + i) * ((i < 96) ? scale : 1.f);
    for (int i = t; i < 96 * 48; i += T) {
        int r = i / 48, p = i - r * 48;
        g_wproj[r * 48 + pperm(p)] =
            packh2(__ldg(proj_w + r * 96 + 2 * p), __ldg(proj_w + r * 96 + 2 * p + 1));
    }
    for (int i = t; i < 384 * 48; i += T) {
        int r = i / 48, p = i - r * 48;
        g_w1[r * 48 + pperm(p)] =
            packh2(__ldg(fc1_w + r * 96 + 2 * p), __ldg(fc1_w + r * 96 + 2 * p + 1));
    }
    for (int i = t; i < 96 * 192; i += T) {
        int c = i / 192, p = i - c * 192;
        g_w2[c * 192 + pperm(p)] =
            packh2(__ldg(fc2_w + c * 384 + 2 * p), __ldg(fc2_w + c * 384 + 2 * p + 1));
    }
    for (int i = t; i < 4 * 4 * 64 * 64; i += T) {
        int m  = i & 63;
        int n  = (i >> 6) & 63;
        int h  = (i >> 12) & 3;
        int v  = (i >> 14) & 3;
        int i1 = n >> 3, j1 = n & 7;
        int i2 = m >> 3, j2 = m & 7;
        int ridx = (i1 - i2 + 7) * 15 + (j1 - j2 + 7);
        float bias = __ldg(rpb + ridx * 4 + h);
        int rn = (v & 2) ? ((i1 < 4) ? 1 : 2) : 0;
        int cn = (v & 1) ? ((j1 < 4) ? 1 : 2) : 0;
        int rm = (v & 2) ? ((i2 < 4) ? 1 : 2) : 0;
        int cm = (v & 1) ? ((j2 < 4) ? 1 : 2) : 0;
        if ((rn * 3 + cn) != (rm * 3 + cm)) bias -= 100.f;
        g_sbias[i] = bias;
    }
}

// ---------------- fused kernel smem (word indices) ----------------
#define F_XT   0        // raw x fp32 [64][104] -> ys f16 [64][56] -> yb fp32 [64][97]
#define F_XH   6656     // Xh f16 [64][56] -> AO f16 -> hct f16 [64][56]
#define F_Q    10240    // Q f16 [64][72] -> hout fp32 [64][104] (spans into K)
#define F_K    14848    // K f16 [64][72]
#define F_VT   19456    // V^T f16 [96][40] (token pairs, permuted)
#define F_POS  23296    // 64 int
#define F_TOT  23360    // 93,440 bytes

__global__ void __launch_bounds__(256, 2) swin_fused_kernel(
    const float* __restrict__ x,
    const float* __restrict__ norm_w, const float* __restrict__ norm_b,
    const float* __restrict__ proj_b,
    const float* __restrict__ n2w, const float* __restrict__ n2b,
    const float* __restrict__ b1g, const float* __restrict__ b2g,
    float* __restrict__ out)
{
    extern __shared__ float sm[];
    float* xt   = sm + F_XT;
    float* yb   = sm + F_XT;            // epilogue bounce (after ys dead)
    float* hout = sm + F_Q;             // h = x + attn (after Q/K dead)
    int*   pos  = (int*)(sm + F_POS);

    uu* Xhu = (uu*)(sm + F_XH);
    uu* AOu = (uu*)(sm + F_XH);
    uu* Hcu = (uu*)(sm + F_XH);
    uu* Ysu = (uu*)(sm + F_XT);
    uu* Qu  = (uu*)(sm + F_Q);
    uu* Ku  = (uu*)(sm + F_K);
    uu* Vtu = (uu*)(sm + F_VT);

    const int tid  = threadIdx.x;
    const int lane = tid & 31;
    const int wid  = tid >> 5;            // 0..7
    const int lq   = lane >> 2;
    const int lr   = lane & 3;
    const int mh   = wid >> 2;            // 0..1 (QKV/proj/MLP m32 group)
    const int nq   = wid & 3;             // 0..3
    const int hh   = wid & 3;             // scores/AV head
    const int mq   = wid >> 2;            // scores/AV 32-row slice
    const int blk  = blockIdx.x;
    const int b    = blk >> 10;
    const int wh   = (blk >> 5) & 31;
    const int ww   = blk & 31;
    const int variant = ((wh == 31) ? 2 : 0) | ((ww == 31) ? 1 : 0);

    if (tid < 64) {
        int i = tid >> 3, j = tid & 7;
        int hs = wh * 8 + i;
        int wsp = ww * 8 + j;
        int r = (hs + 4) & 255;
        int c = (wsp + 4) & 255;
        pos[tid] = r * 256 + c;
    }
    // zero Q/K pad slots (head-dim pairs 12..15 -> slots 9,11,13,15 per head)
    for (int i = tid; i < 2048; i += 256) {
        int sl = 9 + 2 * (i & 3);
        int hd = (i >> 2) & 3;
        int r  = (i >> 4) & 63;
        uu* dst = (i & 1024) ? Ku : Qu;
        dst[r * 72 + hd * 16 + sl] = 0;
    }
    __syncthreads();                                   // (1)

    const int xbase = b * 96 * 65536;

    // ---- gather + LN1 entirely in registers (4 lanes per token) ----
    {
        int p = tid >> 2, part = tid & 3;
        const float* xp = x + xbase + pos[p];
        float g[24];
        #pragma unroll
        for (int i = 0; i < 24; i++) g[i] = __ldg(xp + ((part * 24 + i) << 16));
        float s = 0.f, s2 = 0.f;
        #pragma unroll
        for (int i = 0; i < 24; i++) { s += g[i]; s2 += g[i] * g[i]; }
        #pragma unroll
        for (int o = 1; o < 4; o <<= 1) {
            s  += __shfl_xor_sync(0xffffffffu, s,  o);
            s2 += __shfl_xor_sync(0xffffffffu, s2, o);
        }
        float mu = s * (1.f / 96.f);
        float var = s2 * (1.f / 96.f) - mu * mu;
        float rs = rsqrtf(var + 1e-6f);
        // raw -> xt (residual for proj)
        float* xr = xt + p * 104 + part * 24;
        #pragma unroll
        for (int i = 0; i < 6; i++)
            *(float4*)(xr + 4 * i) = make_float4(g[4 * i], g[4 * i + 1],
                                                 g[4 * i + 2], g[4 * i + 3]);
        // normalized -> Xh f16 pairs (permuted slots)
        #pragma unroll
        for (int i = 0; i < 12; i++) {
            int c = part * 24 + 2 * i;
            float2 nw = __ldg((const float2*)norm_w + (c >> 1));
            float2 nb = __ldg((const float2*)norm_b + (c >> 1));
            Xhu[p * 56 + pperm(part * 12 + i)] =
                packh2((g[2 * i] - mu) * rs * nw.x + nb.x,
                       (g[2 * i + 1] - mu) * rs * nw.y + nb.y);
        }
    }
    __syncthreads();                                   // (2)

    // ---------------- QKV: warp tile m32 x n72, 6 k16-steps ----------------
    {
        float acc[9][2][4];
        #pragma unroll
        for (int nt = 0; nt < 9; nt++)
            #pragma unroll
            for (int mt = 0; mt < 2; mt++)
                #pragma unroll
                for (int e = 0; e < 4; e++) acc[nt][mt][e] = 0.f;

        const uu* wb = g_wqkv + (nq * 72 + lq) * 48 + 2 * lr;
        #pragma unroll
        for (int ks = 0; ks < 6; ks++) {
            int k0 = ks * 8;
            uu af[2][4];
            lda64(af[0], Xhu + (mh * 32) * 56 + k0, 56, lq, lr);
            lda64(af[1], Xhu + (mh * 32 + 16) * 56 + k0, 56, lq, lr);
            #pragma unroll
            for (int nt = 0; nt < 9; nt++) {
                uu b0, b1;
                ldbg(b0, b1, wb + nt * 8 * 48 + k0);
                mmaf16(acc[nt][0], af[0], b0, b1);
                mmaf16(acc[nt][1], af[1], b0, b1);
            }
        }
        #pragma unroll
        for (int nt = 0; nt < 9; nt++) {
            int j0 = nq * 72 + nt * 8;
            float bl = __ldg(g_bqkv + j0 + 2 * lr);
            float bh = __ldg(g_bqkv + j0 + 2 * lr + 1);
            #pragma unroll
            for (int mt = 0; mt < 2; mt++) {
                int row = mh * 32 + mt * 16 + lq;
                int col = j0 + 2 * lr;
                float v0 = acc[nt][mt][0] + bl;
                float v1 = acc[nt][mt][1] + bh;
                float v2 = acc[nt][mt][2] + bl;
                float v3 = acc[nt][mt][3] + bh;
                if (col < 96) {
                    int head = col / 24;
                    int chp  = (col - head * 24) >> 1;
                    int ps   = head * 16 + pperm(chp);
                    Qu[row * 72 + ps]       = packh2(v0, v1);
                    Qu[(row + 8) * 72 + ps] = packh2(v2, v3);
                } else if (col < 192) {
                    int kc   = col - 96;
                    int head = kc / 24;
                    int chp  = (kc - head * 24) >> 1;
                    int ps   = head * 16 + pperm(chp);
                    Ku[row * 72 + ps]       = packh2(v0, v1);
                    Ku[(row + 8) * 72 + ps] = packh2(v2, v3);
                } else {
                    int cc = col - 192;
                    #pragma unroll
                    for (int e = 0; e < 4; e++) {
                        float v = (e == 0) ? v0 : (e == 1) ? v1 : (e == 2) ? v2 : v3;
                        int n = row + ((e >> 1) << 3);
                        int c2 = cc + (e & 1);
                        int tp = n >> 1;
                        int sl = pperm(tp & 7) | (tp & ~7);
                        ((__half*)(Vtu + c2 * 40 + sl))[n & 1] = __float2half_rn(v);
                    }
                }
            }
        }
    }
    __syncthreads();                                   // (3)

    // ---- Scores (m32 x 64), acc initialized from g_sbias; softmax; AV ----
    {
        float acc[8][2][4];
        const float* bb = g_sbias + (((variant * 4 + hh) * 64 + mq * 32 + lq) * 64)
                        + 2 * lr;
        #pragma unroll
        for (int nt = 0; nt < 8; nt++)
            #pragma unroll
            for (int mt = 0; mt < 2; mt++) {
                float2 lo = __ldg((const float2*)(bb + (mt * 16) * 64 + nt * 8));
                float2 hi = __ldg((const float2*)(bb + (mt * 16 + 8) * 64 + nt * 8));
                acc[nt][mt][0] = lo.x; acc[nt][mt][1] = lo.y;
                acc[nt][mt][2] = hi.x; acc[nt][mt][3] = hi.y;
            }

        #pragma unroll
        for (int ks = 0; ks < 2; ks++) {
            int k0 = hh * 16 + ks * 8;
            uu af[2][4];
            lda64(af[0], Qu + (mq * 32) * 72 + k0, 72, lq, lr);
            lda64(af[1], Qu + (mq * 32 + 16) * 72 + k0, 72, lq, lr);
            #pragma unroll
            for (int nt = 0; nt < 8; nt++) {
                uint2 v = *(const uint2*)(Ku + (nt * 8 + lq) * 72 + k0 + 2 * lr);
                mmaf16(acc[nt][0], af[0], v.x, v.y);
                mmaf16(acc[nt][1], af[1], v.x, v.y);
            }
        }
        // softmax + AV
        float fav[3][2][4];
        #pragma unroll
        for (int nt = 0; nt < 3; nt++)
            #pragma unroll
            for (int mt = 0; mt < 2; mt++)
                #pragma unroll
                for (int e = 0; e < 4; e++) fav[nt][mt][e] = 0.f;

        #pragma unroll
        for (int mt = 0; mt < 2; mt++) {
            float mx0 = -1e30f, mx1 = -1e30f;
            #pragma unroll
            for (int nt = 0; nt < 8; nt++) {
                mx0 = fmaxf(mx0, fmaxf(acc[nt][mt][0], acc[nt][mt][1]));
                mx1 = fmaxf(mx1, fmaxf(acc[nt][mt][2], acc[nt][mt][3]));
            }
            #pragma unroll
            for (int o = 1; o < 4; o <<= 1) {
                mx0 = fmaxf(mx0, __shfl_xor_sync(0xffffffffu, mx0, o));
                mx1 = fmaxf(mx1, __shfl_xor_sync(0xffffffffu, mx1, o));
            }
            float sm0 = 0.f, sm1 = 0.f;
            #pragma unroll
            for (int nt = 0; nt < 8; nt++) {
                acc[nt][mt][0] = __expf(acc[nt][mt][0] - mx0);
                acc[nt][mt][1] = __expf(acc[nt][mt][1] - mx0);
                acc[nt][mt][2] = __expf(acc[nt][mt][2] - mx1);
                acc[nt][mt][3] = __expf(acc[nt][mt][3] - mx1);
                sm0 += acc[nt][mt][0] + acc[nt][mt][1];
                sm1 += acc[nt][mt][2] + acc[nt][mt][3];
            }
            #pragma unroll
            for (int o = 1; o < 4; o <<= 1) {
                sm0 += __shfl_xor_sync(0xffffffffu, sm0, o);
                sm1 += __shfl_xor_sync(0xffffffffu, sm1, o);
            }
            float inv0 = __fdividef(1.f, sm0);
            float inv1 = __fdividef(1.f, sm1);
            // AV: pack P directly into A-fragments
            #pragma unroll
            for (int ks = 0; ks < 4; ks++) {
                uu a[4];
                a[0] = packh2(acc[2 * ks][mt][0] * inv0,     acc[2 * ks][mt][1] * inv0);
                a[1] = packh2(acc[2 * ks][mt][2] * inv1,     acc[2 * ks][mt][3] * inv1);
                a[2] = packh2(acc[2 * ks + 1][mt][0] * inv0, acc[2 * ks + 1][mt][1] * inv0);
                a[3] = packh2(acc[2 * ks + 1][mt][2] * inv1, acc[2 * ks + 1][mt][3] * inv1);
                #pragma unroll
                for (int nt = 0; nt < 3; nt++) {
                    uint2 v = *(const uint2*)(Vtu + (hh * 24 + nt * 8 + lq) * 40
                                              + ks * 8 + 2 * lr);
                    mmaf16(fav[nt][mt], a, v.x, v.y);
                }
            }
        }
        __syncthreads();                               // (4) Xh dead -> AO overlay
        #pragma unroll
        for (int nt = 0; nt < 3; nt++)
            #pragma unroll
            for (int mt = 0; mt < 2; mt++) {
                int n0 = mq * 32 + mt * 16 + lq;
                int cp = hh * 12 + nt * 4 + lr;
                AOu[n0 * 56 + pperm(cp)]       = packh2(fav[nt][mt][0], fav[nt][mt][1]);
                AOu[(n0 + 8) * 56 + pperm(cp)] = packh2(fav[nt][mt][2], fav[nt][mt][3]);
            }
    }
    __syncthreads();                                   // (5)

    // ------- Proj (m32 x n24, 6 k-steps) + residual(xt) -> hout (smem) ----
    {
        float acc[3][2][4];
        #pragma unroll
        for (int nt = 0; nt < 3; nt++)
            #pragma unroll
            for (int mt = 0; mt < 2; mt++)
                #pragma unroll
                for (int e = 0; e < 4; e++) acc[nt][mt][e] = 0.f;

        const uu* wb = g_wproj + (nq * 24 + lq) * 48 + 2 * lr;
        #pragma unroll
        for (int ks = 0; ks < 6; ks++) {
            int k0 = ks * 8;
            uu af[2][4];
            lda64(af[0], AOu + (mh * 32) * 56 + k0, 56, lq, lr);
            lda64(af[1], AOu + (mh * 32 + 16) * 56 + k0, 56, lq, lr);
            #pragma unroll
            for (int nt = 0; nt < 3; nt++) {
                uu b0, b1;
                ldbg(b0, b1, wb + nt * 8 * 48 + k0);
                mmaf16(acc[nt][0], af[0], b0, b1);
                mmaf16(acc[nt][1], af[1], b0, b1);
            }
        }
        #pragma unroll
        for (int nt = 0; nt < 3; nt++) {
            int j0 = nq * 24 + nt * 8;
            float bl = __ldg(proj_b + j0 + 2 * lr);
            float bh = __ldg(proj_b + j0 + 2 * lr + 1);
            #pragma unroll
            for (int mt = 0; mt < 2; mt++)
                #pragma unroll
                for (int e = 0; e < 4; e++) {
                    int n = mh * 32 + mt * 16 + lq + ((e >> 1) << 3);
                    int j = j0 + 2 * lr + (e & 1);
                    hout[n * 104 + j] = acc[nt][mt][e] + ((e & 1) ? bh : bl)
                                      + xt[n * 104 + j];
                }
        }
    }
    __syncthreads();                                   // (6)

    // ---- LN2 from hout (smem), 4 lanes/token -> ys f16 (overlays xt) ----
    {
        int p = tid >> 2, part = tid & 3;
        float g[24];
        const float* hp = hout + p * 104 + part * 24;
        #pragma unroll
        for (int i = 0; i < 6; i++) {
            float4 v = *(const float4*)(hp + 4 * i);
            g[4 * i] = v.x; g[4 * i + 1] = v.y; g[4 * i + 2] = v.z; g[4 * i + 3] = v.w;
        }
        float s = 0.f, s2 = 0.f;
        #pragma unroll
        for (int i = 0; i < 24; i++) { s += g[i]; s2 += g[i] * g[i]; }
        #pragma unroll
        for (int o = 1; o < 4; o <<= 1) {
            s  += __shfl_xor_sync(0xffffffffu, s,  o);
            s2 += __shfl_xor_sync(0xffffffffu, s2, o);
        }
        float mu = s * (1.f / 96.f);
        float var = s2 * (1.f / 96.f) - mu * mu;
        float rs = rsqrtf(var + 1e-6f);
        #pragma unroll
        for (int i = 0; i < 12; i++) {
            int c = part * 24 + 2 * i;
            float2 nw = __ldg((const float2*)n2w + (c >> 1));
            float2 nb = __ldg((const float2*)n2b + (c >> 1));
            Ysu[p * 56 + pperm(part * 12 + i)] =
                packh2((g[2 * i] - mu) * rs * nw.x + nb.x,
                       (g[2 * i + 1] - mu) * rs * nw.y + nb.y);
        }
    }
    __syncthreads();                                   // (7)

    // ---- MLP: 4 hidden quarters; fc1 (m32 x n24) -> fc2 partial (m32 x n24) ----
    float acc2[3][2][4];
    #pragma unroll
    for (int nt = 0; nt < 3; nt++)
        #pragma unroll
        for (int mt = 0; mt < 2; mt++)
            #pragma unroll
            for (int e = 0; e < 4; e++) acc2[nt][mt][e] = 0.f;

    for (int ng = 0; ng < 4; ng++) {
        // fc1 quarter (96 hidden): warp tile m32 x n24
        {
            float acc1[3][2][4];
            #pragma unroll
            for (int nt = 0; nt < 3; nt++)
                #pragma unroll
                for (int mt = 0; mt < 2; mt++)
                    #pragma unroll
                    for (int e = 0; e < 4; e++) acc1[nt][mt][e] = 0.f;

            const int jb = nq * 24;
            const uu* wb = g_w1 + (ng * 96 + jb + lq) * 48 + 2 * lr;
            #pragma unroll
            for (int ks = 0; ks < 6; ks++) {
                int k0 = ks * 8;
                uu af[2][4];
                lda64(af[0], Ysu + (mh * 32) * 56 + k0, 56, lq, lr);
                lda64(af[1], Ysu + (mh * 32 + 16) * 56 + k0, 56, lq, lr);
                #pragma unroll
                for (int nt = 0; nt < 3; nt++) {
                    uu b0, b1;
                    ldbg(b0, b1, wb + nt * 8 * 48 + k0);
                    mmaf16(acc1[nt][0], af[0], b0, b1);
                    mmaf16(acc1[nt][1], af[1], b0, b1);
                }
            }
            #pragma unroll
            for (int nt = 0; nt < 3; nt++) {
                int jl = jb + nt * 8;
                float bl = __ldg(b1g + ng * 96 + jl + 2 * lr);
                float bh = __ldg(b1g + ng * 96 + jl + 2 * lr + 1);
                int pl = (jl >> 1) + lr;               // local hidden pair idx
                #pragma unroll
                for (int mt = 0; mt < 2; mt++) {
                    int p0r = mh * 32 + mt * 16 + lq;
                    float v0 = acc1[nt][mt][0] + bl;
                    float v1 = acc1[nt][mt][1] + bh;
                    float v2 = acc1[nt][mt][2] + bl;
                    float v3 = acc1[nt][mt][3] + bh;
                    v0 = 0.5f * v0 * (1.f + erf_as(v0 * 0.7071067811865475f));
                    v1 = 0.5f * v1 * (1.f + erf_as(v1 * 0.7071067811865475f));
                    v2 = 0.5f * v2 * (1.f + erf_as(v2 * 0.7071067811865475f));
                    v3 = 0.5f * v3 * (1.f + erf_as(v3 * 0.7071067811865475f));
                    Hcu[p0r * 56 + pperm(pl)]       = packh2(v0, v1);
                    Hcu[(p0r + 8) * 56 + pperm(pl)] = packh2(v2, v3);
                }
            }
        }
        __syncthreads();                               // hct quarter ready

        // fc2 partial: warp tile m32 x n24 over out channels
        const uu* wb2 = g_w2 + (nq * 24 + lq) * 192 + ng * 48 + 2 * lr;
        #pragma unroll
        for (int ks = 0; ks < 6; ks++) {
            int k0 = ks * 8;
            uu af[2][4];
            lda64(af[0], Hcu + (mh * 32) * 56 + k0, 56, lq, lr);
            lda64(af[1], Hcu + (mh * 32 + 16) * 56 + k0, 56, lq, lr);
            #pragma unroll
            for (int nt = 0; nt < 3; nt++) {
                uu b0, b1;
                ldbg(b0, b1, wb2 + nt * 8 * 192 + k0);
                mmaf16(acc2[nt][0], af[0], b0, b1);
                mmaf16(acc2[nt][1], af[1], b0, b1);
            }
        }
        __syncthreads();                               // before next quarter
    }

    // epilogue: bias + residual (hout, smem) -> yb [64][97] (overlays ys)
    #pragma unroll
    for (int nt = 0; nt < 3; nt++) {
        int c0 = nq * 24 + nt * 8;
        float bl = __ldg(b2g + c0 + 2 * lr);
        float bh = __ldg(b2g + c0 + 2 * lr + 1);
        #pragma unroll
        for (int mt = 0; mt < 2; mt++)
            #pragma unroll
            for (int e = 0; e < 4; e++) {
                int p = mh * 32 + mt * 16 + lq + ((e >> 1) << 3);
                int c = c0 + 2 * lr + (e & 1);
                yb[p * 97 + c] = acc2[nt][mt][e] + ((e & 1) ? bh : bl)
                               + hout[p * 104 + c];
            }
    }
    __syncthreads();

    // store out (NCHW): per channel, 8-pixel row segments (32B coalesced)
    #pragma unroll
    for (int it = 0; it < 24; it++) {
        int e = tid + it * 256;
        int c = e >> 6, n = e & 63;
        out[((size_t)(b * 96 + c) << 16) + pos[n]] = yb[n * 97 + c];
    }
}

extern "C" void kernel_launch(void* const* d_in, const int* in_sizes, int n_in,
                              void* d_out, int out_size)
{
    const float* x      = (const float*)d_in[0];
    const float* norm_w = (const float*)d_in[1];
    const float* norm_b = (const float*)d_in[2];
    const float* qkv_w  = (const float*)d_in[3];
    const float* qkv_b  = (const float*)d_in[4];
    const float* proj_w = (const float*)d_in[5];
    const float* proj_b = (const float*)d_in[6];
    const float* rpb    = (const float*)d_in[7];
    const float* n2w    = (const float*)d_in[8];
    const float* n2b    = (const float*)d_in[9];
    const float* fc1_w  = (const float*)d_in[10];
    const float* fc1_b  = (const float*)d_in[11];
    const float* fc2_w  = (const float*)d_in[12];
    const float* fc2_b  = (const float*)d_in[13];
    float* out = (float*)d_out;

    cudaFuncSetAttribute(swin_fused_kernel, cudaFuncAttributeMaxDynamicSharedMemorySize,
                         F_TOT * 4);

    swin_prep_kernel<<<112, 256>>>(qkv_w, proj_w, fc1_w, fc2_w, qkv_b, rpb);
    swin_fused_kernel<<<4096, 256, F_TOT * 4>>>(
        x, norm_w, norm_b, proj_b, n2w, n2b, fc1_b, fc2_b, out);
}

// round 12
// speedup vs baseline: 8.9370x; 1.0790x over previous
#include <cuda_runtime.h>
#include <cuda_fp16.h>
#include <math.h>

// ---------------------------------------------------------------------------
// Swin block, B=4 C=96 H=W=256 WS=8 NH=4 HD=24 SHIFT=4 N=64 MLP_H=384
// Fully fused per-window kernel (LN1+QKV+attn+proj+res+LN2+MLP+res -> NCHW).
// fp16 mma m16n8k16, fp32 accum, 256-thr CTAs, 2 CTAs/SM.
// ALL operands use 2-k-step 128-bit loads:
//   A-frag = 2x LDS.128 per TWO k-steps, B-frag = 1x LDG.128 per TWO k-steps.
// pperm2 groups each lane's 4 words (2 k-steps x 2 pairs) contiguously;
// strides ≡ 16 (mod 32) -> conflict-free 128-bit smem access.
// ---------------------------------------------------------------------------

typedef unsigned uu;

__device__ __forceinline__ uu packh2(float lo, float hi) {
    __half2 h = __floats2half2_rn(lo, hi);
    return *reinterpret_cast<uu*>(&h);
}
__device__ __forceinline__ void mmaf16(float* d, const uu* a, uu b0, uu b1) {
    asm("mma.sync.aligned.m16n8k16.row.col.f32.f16.f16.f32 "
        "{%0,%1,%2,%3},{%4,%5,%6,%7},{%8,%9},{%0,%1,%2,%3};"
        : "+f"(d[0]), "+f"(d[1]), "+f"(d[2]), "+f"(d[3])
        : "r"(a[0]), "r"(a[1]), "r"(a[2]), "r"(a[3]), "r"(b0), "r"(b1));
}
// 2-kstep permutation: pair p -> slot; lane (lq,lr) reads uint4 at group*16+lr*4
// covering pairs {lr, lr+4, lr+8, lr+12} of the 16-pair (2 k-step) group.
__device__ __forceinline__ int pperm2(int p) {
    return (p & ~15) | ((p & 3) << 2) | (((p >> 3) & 1) << 1) | ((p >> 2) & 1);
}

// Abramowitz-Stegun 7.1.26 erf (|abs err| < 1.5e-7)
__device__ __forceinline__ float erf_as(float x) {
    float ax = fabsf(x);
    float t  = __frcp_rn(1.f + 0.3275911f * ax);
    float y  = t * (0.254829592f + t * (-0.284496736f + t * (1.421413741f
             + t * (-1.453152027f + t * 1.061405429f))));
    float r  = 1.f - y * __expf(-ax * ax);
    return copysignf(r, x);
}

// half weight images, pperm2-permuted pairs (uint4 = 2 k-steps per lane)
__device__ uu g_wqkv[288 * 48];   // q-rows (0..95) pre-scaled by 24^-0.5
__device__ uu g_wproj[96 * 48];
__device__ uu g_w1[384 * 48];
__device__ uu g_w2[96 * 192];
__device__ float g_bqkv[288];
// bias+mask table, lane-contiguous: [v][h][n][lr*16 + nt*2 + par]
__device__ float g_sbias[4 * 4 * 64 * 64];

__global__ void swin_prep_kernel(const float* __restrict__ qkv_w,
                                 const float* __restrict__ proj_w,
                                 const float* __restrict__ fc1_w,
                                 const float* __restrict__ fc2_w,
                                 const float* __restrict__ qkv_b,
                                 const float* __restrict__ rpb)
{
    const float scale = 0.2041241452319315f;  // 24^-0.5
    int t = blockIdx.x * blockDim.x + threadIdx.x;
    int T = gridDim.x * blockDim.x;
    for (int i = t; i < 288 * 48; i += T) {
        int r = i / 48, p = i - r * 48;
        float s = (r < 96) ? scale : 1.f;
        g_wqkv[r * 48 + pperm2(p)] =
            packh2(__ldg(qkv_w + r * 96 + 2 * p) * s,
                   __ldg(qkv_w + r * 96 + 2 * p + 1) * s);
    }
    for (int i = t; i < 288; i += T)
        g_bqkv[i] = __ldg(qkv_b + i) * ((i < 96) ? scale : 1.f);
    for (int i = t; i < 96 * 48; i += T) {
        int r = i / 48, p = i - r * 48;
        g_wproj[r * 48 + pperm2(p)] =
            packh2(__ldg(proj_w + r * 96 + 2 * p), __ldg(proj_w + r * 96 + 2 * p + 1));
    }
    for (int i = t; i < 384 * 48; i += T) {
        int r = i / 48, p = i - r * 48;
        g_w1[r * 48 + pperm2(p)] =
            packh2(__ldg(fc1_w + r * 96 + 2 * p), __ldg(fc1_w + r * 96 + 2 * p + 1));
    }
    for (int i = t; i < 96 * 192; i += T) {
        int c = i / 192, p = i - c * 192;
        g_w2[c * 192 + pperm2(p)] =
            packh2(__ldg(fc2_w + c * 384 + 2 * p), __ldg(fc2_w + c * 384 + 2 * p + 1));
    }
    // bias+mask, lane-contiguous slot: j = lr*16 + nt*2 + par  (m = nt*8+2lr+par)
    for (int i = t; i < 4 * 4 * 64 * 64; i += T) {
        int j  = i & 63;
        int lr = j >> 4, rem = j & 15;
        int nt = rem >> 1, par = rem & 1;
        int m  = nt * 8 + 2 * lr + par;
        int n  = (i >> 6) & 63;
        int h  = (i >> 12) & 3;
        int v  = (i >> 14) & 3;
        int i1 = n >> 3, j1 = n & 7;
        int i2 = m >> 3, j2 = m & 7;
        int ridx = (i1 - i2 + 7) * 15 + (j1 - j2 + 7);
        float bias = __ldg(rpb + ridx * 4 + h);
        int rn = (v & 2) ? ((i1 < 4) ? 1 : 2) : 0;
        int cn = (v & 1) ? ((j1 < 4) ? 1 : 2) : 0;
        int rm = (v & 2) ? ((i2 < 4) ? 1 : 2) : 0;
        int cm = (v & 1) ? ((j2 < 4) ? 1 : 2) : 0;
        if ((rn * 3 + cn) != (rm * 3 + cm)) bias -= 100.f;
        g_sbias[i] = bias;
    }
}

// ---------------- fused kernel smem (word indices) ----------------
#define F_XT   0        // raw x fp32 [64][104] -> ys f16 [64][48] -> yb fp32 [64][97]
#define F_XH   6656     // Xh f16 [64][48] -> AO -> hct (3072 words)
#define F_Q    9728     // Q f16 [4 heads][64][16] (4096) -> hout fp32 [64][104]
#define F_K    13824    // K f16 [4][64][16] (4096)
#define F_VT   17920    // V^T f16 [2 kgrp][96][16] (3072)
#define F_POS  20992    // 64 int
#define F_TOT  21056    // 84,224 bytes

__global__ void __launch_bounds__(256, 2) swin_fused_kernel(
    const float* __restrict__ x,
    const float* __restrict__ norm_w, const float* __restrict__ norm_b,
    const float* __restrict__ proj_b,
    const float* __restrict__ n2w, const float* __restrict__ n2b,
    const float* __restrict__ b1g, const float* __restrict__ b2g,
    float* __restrict__ out)
{
    extern __shared__ float sm[];
    float* xt   = sm + F_XT;
    float* yb   = sm + F_XT;            // epilogue bounce
    float* hout = sm + F_Q;             // h = x + attn (overlays Q..K)
    int*   pos  = (int*)(sm + F_POS);

    uu* Xhu = (uu*)(sm + F_XH);
    uu* AOu = (uu*)(sm + F_XH);
    uu* Hcu = (uu*)(sm + F_XH);
    uu* Ysu = (uu*)(sm + F_XT);
    uu* Qu  = (uu*)(sm + F_Q);
    uu* Ku  = (uu*)(sm + F_K);
    uu* Vtu = (uu*)(sm + F_VT);

    const int tid  = threadIdx.x;
    const int lane = tid & 31;
    const int wid  = tid >> 5;            // 0..7
    const int lq   = lane >> 2;
    const int lr   = lane & 3;
    const int mh   = wid >> 2;            // 0..1 (m32 group)
    const int nq   = wid & 3;             // 0..3
    const int hh   = wid & 3;             // scores/AV head
    const int mq   = wid >> 2;            // scores/AV 32-row slice
    const int blk  = blockIdx.x;
    const int b    = blk >> 10;
    const int wh   = (blk >> 5) & 31;
    const int ww   = blk & 31;
    const int variant = ((wh == 31) ? 2 : 0) | ((ww == 31) ? 1 : 0);

    if (tid < 64) {
        int i = tid >> 3, j = tid & 7;
        int hs = wh * 8 + i;
        int wsp = ww * 8 + j;
        int r = (hs + 4) & 255;
        int c = (wsp + 4) & 255;
        pos[tid] = r * 256 + c;
    }
    // zero Q/K pad slots (per head: within-head pairs 12..15 -> slots 3,7,11,15)
    for (int i = tid; i < 2048; i += 256) {
        int sl = 3 + 4 * (i & 3);
        int hd = (i >> 2) & 3;
        int r  = (i >> 4) & 63;
        uu* dst = (i & 1024) ? Ku : Qu;
        dst[hd * 1024 + r * 16 + sl] = 0;
    }
    __syncthreads();                                   // (1)

    const int xbase = b * 96 * 65536;

    // ---- gather + LN1 in registers (4 lanes per token) ----
    {
        int p = tid >> 2, part = tid & 3;
        const float* xp = x + xbase + pos[p];
        float g[24];
        #pragma unroll
        for (int i = 0; i < 24; i++) g[i] = __ldg(xp + ((part * 24 + i) << 16));
        float s = 0.f, s2 = 0.f;
        #pragma unroll
        for (int i = 0; i < 24; i++) { s += g[i]; s2 += g[i] * g[i]; }
        #pragma unroll
        for (int o = 1; o < 4; o <<= 1) {
            s  += __shfl_xor_sync(0xffffffffu, s,  o);
            s2 += __shfl_xor_sync(0xffffffffu, s2, o);
        }
        float mu = s * (1.f / 96.f);
        float var = s2 * (1.f / 96.f) - mu * mu;
        float rs = rsqrtf(var + 1e-6f);
        float* xr = xt + p * 104 + part * 24;
        #pragma unroll
        for (int i = 0; i < 6; i++)
            *(float4*)(xr + 4 * i) = make_float4(g[4 * i], g[4 * i + 1],
                                                 g[4 * i + 2], g[4 * i + 3]);
        #pragma unroll
        for (int i = 0; i < 12; i++) {
            int c = part * 24 + 2 * i;
            float2 nw = __ldg((const float2*)norm_w + (c >> 1));
            float2 nb = __ldg((const float2*)norm_b + (c >> 1));
            Xhu[p * 48 + pperm2(part * 12 + i)] =
                packh2((g[2 * i] - mu) * rs * nw.x + nb.x,
                       (g[2 * i + 1] - mu) * rs * nw.y + nb.y);
        }
    }
    __syncthreads();                                   // (2)

    // -------- QKV: m32 x n72, 3 ks2 groups (2 k-steps each) --------
    {
        float acc[9][2][4];
        #pragma unroll
        for (int nt = 0; nt < 9; nt++)
            #pragma unroll
            for (int mt = 0; mt < 2; mt++)
                #pragma unroll
                for (int e = 0; e < 4; e++) acc[nt][mt][e] = 0.f;

        const uu* wb = g_wqkv + (nq * 72 + lq) * 48 + lr * 4;
        #pragma unroll
        for (int ks2 = 0; ks2 < 3; ks2++) {
            uu ae[2][4], ao[2][4];
            #pragma unroll
            for (int mt = 0; mt < 2; mt++) {
                uint4 lo = *(const uint4*)(Xhu + (mh * 32 + mt * 16 + lq) * 48
                                           + ks2 * 16 + lr * 4);
                uint4 hi = *(const uint4*)(Xhu + (mh * 32 + mt * 16 + lq + 8) * 48
                                           + ks2 * 16 + lr * 4);
                ae[mt][0] = lo.x; ae[mt][1] = hi.x; ae[mt][2] = lo.y; ae[mt][3] = hi.y;
                ao[mt][0] = lo.z; ao[mt][1] = hi.z; ao[mt][2] = lo.w; ao[mt][3] = hi.w;
            }
            #pragma unroll
            for (int nt = 0; nt < 9; nt++) {
                uint4 bw = __ldg((const uint4*)(wb + nt * 8 * 48 + ks2 * 16));
                #pragma unroll
                for (int mt = 0; mt < 2; mt++) {
                    mmaf16(acc[nt][mt], ae[mt], bw.x, bw.y);
                    mmaf16(acc[nt][mt], ao[mt], bw.z, bw.w);
                }
            }
        }
        #pragma unroll
        for (int nt = 0; nt < 9; nt++) {
            int j0 = nq * 72 + nt * 8;
            float bl = __ldg(g_bqkv + j0 + 2 * lr);
            float bh = __ldg(g_bqkv + j0 + 2 * lr + 1);
            #pragma unroll
            for (int mt = 0; mt < 2; mt++) {
                int row = mh * 32 + mt * 16 + lq;
                int col = j0 + 2 * lr;
                float v0 = acc[nt][mt][0] + bl;
                float v1 = acc[nt][mt][1] + bh;
                float v2 = acc[nt][mt][2] + bl;
                float v3 = acc[nt][mt][3] + bh;
                if (col < 192) {
                    uu* dst;
                    int cl = col;
                    if (col < 96) { dst = Qu; } else { dst = Ku; cl = col - 96; }
                    int head = cl / 24;
                    int q    = (cl - head * 24) >> 1;      // within-head pair 0..11
                    int sl   = ((q & 3) << 2) | (((q >> 3) & 1) << 1) | ((q >> 2) & 1);
                    dst[head * 1024 + row * 16 + sl]       = packh2(v0, v1);
                    dst[head * 1024 + (row + 8) * 16 + sl] = packh2(v2, v3);
                } else {
                    int cc = col - 192;
                    #pragma unroll
                    for (int e = 0; e < 4; e++) {
                        float v = (e == 0) ? v0 : (e == 1) ? v1 : (e == 2) ? v2 : v3;
                        int n = row + ((e >> 1) << 3);
                        int c2 = cc + (e & 1);
                        int tp = n >> 1;                    // token pair 0..31
                        int g  = tp >> 4;                   // k-group
                        int q  = tp & 15;
                        int sl = ((q & 3) << 2) | (((q >> 3) & 1) << 1) | ((q >> 2) & 1);
                        ((__half*)(Vtu + g * 1536 + c2 * 16 + sl))[n & 1] =
                            __float2half_rn(v);
                    }
                }
            }
        }
    }
    __syncthreads();                                   // (3)

    // ---- Scores (m32 x 64): acc init from g_sbias (LDG.128), 1 ks2/head ----
    {
        float acc[8][2][4];
        const float* sb = g_sbias + (((variant * 4 + hh) * 64 + mq * 32 + lq) * 64)
                        + lr * 16;
        #pragma unroll
        for (int mt = 0; mt < 2; mt++) {
            const float4* lo4 = (const float4*)(sb + (mt * 16) * 64);
            const float4* hi4 = (const float4*)(sb + (mt * 16 + 8) * 64);
            #pragma unroll
            for (int q = 0; q < 4; q++) {
                float4 L = __ldg(lo4 + q);
                float4 H = __ldg(hi4 + q);
                acc[2 * q][mt][0] = L.x;     acc[2 * q][mt][1] = L.y;
                acc[2 * q + 1][mt][0] = L.z; acc[2 * q + 1][mt][1] = L.w;
                acc[2 * q][mt][2] = H.x;     acc[2 * q][mt][3] = H.y;
                acc[2 * q + 1][mt][2] = H.z; acc[2 * q + 1][mt][3] = H.w;
            }
        }
        {
            uu ae[2][4], ao[2][4];
            #pragma unroll
            for (int mt = 0; mt < 2; mt++) {
                uint4 lo = *(const uint4*)(Qu + hh * 1024
                                           + (mq * 32 + mt * 16 + lq) * 16 + lr * 4);
                uint4 hi = *(const uint4*)(Qu + hh * 1024
                                           + (mq * 32 + mt * 16 + lq + 8) * 16 + lr * 4);
                ae[mt][0] = lo.x; ae[mt][1] = hi.x; ae[mt][2] = lo.y; ae[mt][3] = hi.y;
                ao[mt][0] = lo.z; ao[mt][1] = hi.z; ao[mt][2] = lo.w; ao[mt][3] = hi.w;
            }
            #pragma unroll
            for (int nt = 0; nt < 8; nt++) {
                uint4 kf = *(const uint4*)(Ku + hh * 1024 + (nt * 8 + lq) * 16 + lr * 4);
                #pragma unroll
                for (int mt = 0; mt < 2; mt++) {
                    mmaf16(acc[nt][mt], ae[mt], kf.x, kf.y);
                    mmaf16(acc[nt][mt], ao[mt], kf.z, kf.w);
                }
            }
        }
        // softmax + AV
        float fav[3][2][4];
        #pragma unroll
        for (int nt = 0; nt < 3; nt++)
            #pragma unroll
            for (int mt = 0; mt < 2; mt++)
                #pragma unroll
                for (int e = 0; e < 4; e++) fav[nt][mt][e] = 0.f;

        #pragma unroll
        for (int mt = 0; mt < 2; mt++) {
            float mx0 = -1e30f, mx1 = -1e30f;
            #pragma unroll
            for (int nt = 0; nt < 8; nt++) {
                mx0 = fmaxf(mx0, fmaxf(acc[nt][mt][0], acc[nt][mt][1]));
                mx1 = fmaxf(mx1, fmaxf(acc[nt][mt][2], acc[nt][mt][3]));
            }
            #pragma unroll
            for (int o = 1; o < 4; o <<= 1) {
                mx0 = fmaxf(mx0, __shfl_xor_sync(0xffffffffu, mx0, o));
                mx1 = fmaxf(mx1, __shfl_xor_sync(0xffffffffu, mx1, o));
            }
            float sm0 = 0.f, sm1 = 0.f;
            #pragma unroll
            for (int nt = 0; nt < 8; nt++) {
                acc[nt][mt][0] = __expf(acc[nt][mt][0] - mx0);
                acc[nt][mt][1] = __expf(acc[nt][mt][1] - mx0);
                acc[nt][mt][2] = __expf(acc[nt][mt][2] - mx1);
                acc[nt][mt][3] = __expf(acc[nt][mt][3] - mx1);
                sm0 += acc[nt][mt][0] + acc[nt][mt][1];
                sm1 += acc[nt][mt][2] + acc[nt][mt][3];
            }
            #pragma unroll
            for (int o = 1; o < 4; o <<= 1) {
                sm0 += __shfl_xor_sync(0xffffffffu, sm0, o);
                sm1 += __shfl_xor_sync(0xffffffffu, sm1, o);
            }
            float inv0 = __fdividef(1.f, sm0);
            float inv1 = __fdividef(1.f, sm1);
            // AV: pack P into A-frags; V fetched as uint4 (2 k-steps)
            #pragma unroll
            for (int g = 0; g < 2; g++) {
                uu a_e[4], a_o[4];
                a_e[0] = packh2(acc[4 * g][mt][0] * inv0,     acc[4 * g][mt][1] * inv0);
                a_e[1] = packh2(acc[4 * g][mt][2] * inv1,     acc[4 * g][mt][3] * inv1);
                a_e[2] = packh2(acc[4 * g + 1][mt][0] * inv0, acc[4 * g + 1][mt][1] * inv0);
                a_e[3] = packh2(acc[4 * g + 1][mt][2] * inv1, acc[4 * g + 1][mt][3] * inv1);
                a_o[0] = packh2(acc[4 * g + 2][mt][0] * inv0, acc[4 * g + 2][mt][1] * inv0);
                a_o[1] = packh2(acc[4 * g + 2][mt][2] * inv1, acc[4 * g + 2][mt][3] * inv1);
                a_o[2] = packh2(acc[4 * g + 3][mt][0] * inv0, acc[4 * g + 3][mt][1] * inv0);
                a_o[3] = packh2(acc[4 * g + 3][mt][2] * inv1, acc[4 * g + 3][mt][3] * inv1);
                #pragma unroll
                for (int nt = 0; nt < 3; nt++) {
                    uint4 vf = *(const uint4*)(Vtu + g * 1536
                                               + (hh * 24 + nt * 8 + lq) * 16 + lr * 4);
                    mmaf16(fav[nt][mt], a_e, vf.x, vf.y);
                    mmaf16(fav[nt][mt], a_o, vf.z, vf.w);
                }
            }
        }
        __syncthreads();                               // (4) Xh dead -> AO overlay
        #pragma unroll
        for (int nt = 0; nt < 3; nt++)
            #pragma unroll
            for (int mt = 0; mt < 2; mt++) {
                int n0 = mq * 32 + mt * 16 + lq;
                int cp = hh * 12 + nt * 4 + lr;
                AOu[n0 * 48 + pperm2(cp)]       = packh2(fav[nt][mt][0], fav[nt][mt][1]);
                AOu[(n0 + 8) * 48 + pperm2(cp)] = packh2(fav[nt][mt][2], fav[nt][mt][3]);
            }
    }
    __syncthreads();                                   // (5)

    // ------- Proj (m32 x n24, 3 ks2) + residual(xt) -> hout -------
    {
        float acc[3][2][4];
        #pragma unroll
        for (int nt = 0; nt < 3; nt++)
            #pragma unroll
            for (int mt = 0; mt < 2; mt++)
                #pragma unroll
                for (int e = 0; e < 4; e++) acc[nt][mt][e] = 0.f;

        const uu* wb = g_wproj + (nq * 24 + lq) * 48 + lr * 4;
        #pragma unroll
        for (int ks2 = 0; ks2 < 3; ks2++) {
            uu ae[2][4], ao[2][4];
            #pragma unroll
            for (int mt = 0; mt < 2; mt++) {
                uint4 lo = *(const uint4*)(AOu + (mh * 32 + mt * 16 + lq) * 48
                                           + ks2 * 16 + lr * 4);
                uint4 hi = *(const uint4*)(AOu + (mh * 32 + mt * 16 + lq + 8) * 48
                                           + ks2 * 16 + lr * 4);
                ae[mt][0] = lo.x; ae[mt][1] = hi.x; ae[mt][2] = lo.y; ae[mt][3] = hi.y;
                ao[mt][0] = lo.z; ao[mt][1] = hi.z; ao[mt][2] = lo.w; ao[mt][3] = hi.w;
            }
            #pragma unroll
            for (int nt = 0; nt < 3; nt++) {
                uint4 bw = __ldg((const uint4*)(wb + nt * 8 * 48 + ks2 * 16));
                #pragma unroll
                for (int mt = 0; mt < 2; mt++) {
                    mmaf16(acc[nt][mt], ae[mt], bw.x, bw.y);
                    mmaf16(acc[nt][mt], ao[mt], bw.z, bw.w);
                }
            }
        }
        #pragma unroll
        for (int nt = 0; nt < 3; nt++) {
            int j0 = nq * 24 + nt * 8;
            float bl = __ldg(proj_b + j0 + 2 * lr);
            float bh = __ldg(proj_b + j0 + 2 * lr + 1);
            #pragma unroll
            for (int mt = 0; mt < 2; mt++)
                #pragma unroll
                for (int e = 0; e < 4; e++) {
                    int n = mh * 32 + mt * 16 + lq + ((e >> 1) << 3);
                    int j = j0 + 2 * lr + (e & 1);
                    hout[n * 104 + j] = acc[nt][mt][e] + ((e & 1) ? bh : bl)
                                      + xt[n * 104 + j];
                }
        }
    }
    __syncthreads();                                   // (6)

    // ---- LN2 from hout -> ys f16 (overlays xt region) ----
    {
        int p = tid >> 2, part = tid & 3;
        float g[24];
        const float* hp = hout + p * 104 + part * 24;
        #pragma unroll
        for (int i = 0; i < 6; i++) {
            float4 v = *(const float4*)(hp + 4 * i);
            g[4 * i] = v.x; g[4 * i + 1] = v.y; g[4 * i + 2] = v.z; g[4 * i + 3] = v.w;
        }
        float s = 0.f, s2 = 0.f;
        #pragma unroll
        for (int i = 0; i < 24; i++) { s += g[i]; s2 += g[i] * g[i]; }
        #pragma unroll
        for (int o = 1; o < 4; o <<= 1) {
            s  += __shfl_xor_sync(0xffffffffu, s,  o);
            s2 += __shfl_xor_sync(0xffffffffu, s2, o);
        }
        float mu = s * (1.f / 96.f);
        float var = s2 * (1.f / 96.f) - mu * mu;
        float rs = rsqrtf(var + 1e-6f);
        #pragma unroll
        for (int i = 0; i < 12; i++) {
            int c = part * 24 + 2 * i;
            float2 nw = __ldg((const float2*)n2w + (c >> 1));
            float2 nb = __ldg((const float2*)n2b + (c >> 1));
            Ysu[p * 48 + pperm2(part * 12 + i)] =
                packh2((g[2 * i] - mu) * rs * nw.x + nb.x,
                       (g[2 * i + 1] - mu) * rs * nw.y + nb.y);
        }
    }
    __syncthreads();                                   // (7)

    // ---- MLP: 4 hidden quarters (fc1 m32xn24 -> fc2 partial m32xn24) ----
    float acc2[3][2][4];
    #pragma unroll
    for (int nt = 0; nt < 3; nt++)
        #pragma unroll
        for (int mt = 0; mt < 2; mt++)
            #pragma unroll
            for (int e = 0; e < 4; e++) acc2[nt][mt][e] = 0.f;

    for (int ng = 0; ng < 4; ng++) {
        {
            float acc1[3][2][4];
            #pragma unroll
            for (int nt = 0; nt < 3; nt++)
                #pragma unroll
                for (int mt = 0; mt < 2; mt++)
                    #pragma unroll
                    for (int e = 0; e < 4; e++) acc1[nt][mt][e] = 0.f;

            const uu* wb = g_w1 + (ng * 96 + nq * 24 + lq) * 48 + lr * 4;
            #pragma unroll
            for (int ks2 = 0; ks2 < 3; ks2++) {
                uu ae[2][4], ao[2][4];
                #pragma unroll
                for (int mt = 0; mt < 2; mt++) {
                    uint4 lo = *(const uint4*)(Ysu + (mh * 32 + mt * 16 + lq) * 48
                                               + ks2 * 16 + lr * 4);
                    uint4 hi = *(const uint4*)(Ysu + (mh * 32 + mt * 16 + lq + 8) * 48
                                               + ks2 * 16 + lr * 4);
                    ae[mt][0] = lo.x; ae[mt][1] = hi.x; ae[mt][2] = lo.y; ae[mt][3] = hi.y;
                    ao[mt][0] = lo.z; ao[mt][1] = hi.z; ao[mt][2] = lo.w; ao[mt][3] = hi.w;
                }
                #pragma unroll
                for (int nt = 0; nt < 3; nt++) {
                    uint4 bw = __ldg((const uint4*)(wb + nt * 8 * 48 + ks2 * 16));
                    #pragma unroll
                    for (int mt = 0; mt < 2; mt++) {
                        mmaf16(acc1[nt][mt], ae[mt], bw.x, bw.y);
                        mmaf16(acc1[nt][mt], ao[mt], bw.z, bw.w);
                    }
                }
            }
            #pragma unroll
            for (int nt = 0; nt < 3; nt++) {
                int jl = nq * 24 + nt * 8;
                float bl = __ldg(b1g + ng * 96 + jl + 2 * lr);
                float bh = __ldg(b1g + ng * 96 + jl + 2 * lr + 1);
                int pl = (jl >> 1) + lr;               // local hidden pair 0..47
                #pragma unroll
                for (int mt = 0; mt < 2; mt++) {
                    int p0r = mh * 32 + mt * 16 + lq;
                    float v0 = acc1[nt][mt][0] + bl;
                    float v1 = acc1[nt][mt][1] + bh;
                    float v2 = acc1[nt][mt][2] + bl;
                    float v3 = acc1[nt][mt][3] + bh;
                    v0 = 0.5f * v0 * (1.f + erf_as(v0 * 0.7071067811865475f));
                    v1 = 0.5f * v1 * (1.f + erf_as(v1 * 0.7071067811865475f));
                    v2 = 0.5f * v2 * (1.f + erf_as(v2 * 0.7071067811865475f));
                    v3 = 0.5f * v3 * (1.f + erf_as(v3 * 0.7071067811865475f));
                    Hcu[p0r * 48 + pperm2(pl)]       = packh2(v0, v1);
                    Hcu[(p0r + 8) * 48 + pperm2(pl)] = packh2(v2, v3);
                }
            }
        }
        __syncthreads();                               // hct quarter ready

        const uu* wb2 = g_w2 + (nq * 24 + lq) * 192 + ng * 48 + lr * 4;
        #pragma unroll
        for (int ks2 = 0; ks2 < 3; ks2++) {
            uu ae[2][4], ao[2][4];
            #pragma unroll
            for (int mt = 0; mt < 2; mt++) {
                uint4 lo = *(const uint4*)(Hcu + (mh * 32 + mt * 16 + lq) * 48
                                           + ks2 * 16 + lr * 4);
                uint4 hi = *(const uint4*)(Hcu + (mh * 32 + mt * 16 + lq + 8) * 48
                                           + ks2 * 16 + lr * 4);
                ae[mt][0] = lo.x; ae[mt][1] = hi.x; ae[mt][2] = lo.y; ae[mt][3] = hi.y;
                ao[mt][0] = lo.z; ao[mt][1] = hi.z; ao[mt][2] = lo.w; ao[mt][3] = hi.w;
            }
            #pragma unroll
            for (int nt = 0; nt < 3; nt++) {
                uint4 bw = __ldg((const uint4*)(wb2 + nt * 8 * 192 + ks2 * 16));
                #pragma unroll
                for (int mt = 0; mt < 2; mt++) {
                    mmaf16(acc2[nt][mt], ae[mt], bw.x, bw.y);
                    mmaf16(acc2[nt][mt], ao[mt], bw.z, bw.w);
                }
            }
        }
        __syncthreads();                               // before next quarter
    }

    // epilogue: bias + residual (hout) -> yb [64][97]
    #pragma unroll
    for (int nt = 0; nt < 3; nt++) {
        int c0 = nq * 24 + nt * 8;
        float bl = __ldg(b2g + c0 + 2 * lr);
        float bh = __ldg(b2g + c0 + 2 * lr + 1);
        #pragma unroll
        for (int mt = 0; mt < 2; mt++)
            #pragma unroll
            for (int e = 0; e < 4; e++) {
                int p = mh * 32 + mt * 16 + lq + ((e >> 1) << 3);
                int c = c0 + 2 * lr + (e & 1);
                yb[p * 97 + c] = acc2[nt][mt][e] + ((e & 1) ? bh : bl)
                               + hout[p * 104 + c];
            }
    }
    __syncthreads();

    // store out (NCHW): per channel, 8-pixel row segments (32B coalesced)
    #pragma unroll
    for (int it = 0; it < 24; it++) {
        int e = tid + it * 256;
        int c = e >> 6, n = e & 63;
        out[((size_t)(b * 96 + c) << 16) + pos[n]] = yb[n * 97 + c];
    }
}

extern "C" void kernel_launch(void* const* d_in, const int* in_sizes, int n_in,
                              void* d_out, int out_size)
{
    const float* x      = (const float*)d_in[0];
    const float* norm_w = (const float*)d_in[1];
    const float* norm_b = (const float*)d_in[2];
    const float* qkv_w  = (const float*)d_in[3];
    const float* qkv_b  = (const float*)d_in[4];
    const float* proj_w = (const float*)d_in[5];
    const float* proj_b = (const float*)d_in[6];
    const float* rpb    = (const float*)d_in[7];
    const float* n2w    = (const float*)d_in[8];
    const float* n2b    = (const float*)d_in[9];
    const float* fc1_w  = (const float*)d_in[10];
    const float* fc1_b  = (const float*)d_in[11];
    const float* fc2_w  = (const float*)d_in[12];
    const float* fc2_b  = (const float*)d_in[13];
    float* out = (float*)d_out;

    cudaFuncSetAttribute(swin_fused_kernel, cudaFuncAttributeMaxDynamicSharedMemorySize,
                         F_TOT * 4);

    swin_prep_kernel<<<112, 256>>>(qkv_w, proj_w, fc1_w, fc2_w, qkv_b, rpb);
    swin_fused_kernel<<<4096, 256, F_TOT * 4>>>(
        x, norm_w, norm_b, proj_b, n2w, n2b, fc1_b, fc2_b, out);
}